// round 2
// baseline (speedup 1.0000x reference)
#include <cuda_runtime.h>
#include <cuda_fp16.h>
#include <math.h>
#include <stdint.h>

#define NT 16384
#define NE 8

__device__ __half g_xh   [NT*1024];
__device__ __half g_W1h  [NE*1024*1024];
__device__ __half g_W2h  [NE*1024*1024];
__device__ __half g_Ws1h [1024*1024];
__device__ __half g_Ws2h [1024*1024];
__device__ __half g_Wqkvh[1024*384];
__device__ __half g_Wkuvh[256*256];
__device__ __half g_Waoh [128*1024];
__device__ __half g_Woh  [1024*1024];
__device__ __half g_hb   [NT*1024];
__device__ float  g_y    [NT*1024];
__device__ __half g_yh   [NT*1024];
__device__ float  g_qlat [NT*384];
__device__ __half g_lath [NT*256];
__device__ float  g_kv   [NT*256];
__device__ __half g_oh   [NT*128];
__device__ __half g_combh[NT*1024];
__device__ int    g_tokE [NT*2];
__device__ float  g_tokW [NT*2];
__device__ int    g_list [NE*NT];
__device__ float  g_wlist[NE*NT];
__device__ int    g_cnt  [NE];

__device__ __forceinline__ void cp16(void* s, const void* g, bool p){
  unsigned sa=(unsigned)__cvta_generic_to_shared(s); int n=p?16:0;
  asm volatile("cp.async.cg.shared.global [%0],[%1],16,%2;\n"::"r"(sa),"l"(g),"r"(n));
}
__device__ __forceinline__ void mma(float c[4], const uint32_t a[4], const uint32_t b[2]){
  asm volatile("mma.sync.aligned.m16n8k16.row.col.f32.f16.f16.f32 "
    "{%0,%1,%2,%3},{%4,%5,%6,%7},{%8,%9},{%0,%1,%2,%3};\n"
    :"+f"(c[0]),"+f"(c[1]),"+f"(c[2]),"+f"(c[3])
    :"r"(a[0]),"r"(a[1]),"r"(a[2]),"r"(a[3]),"r"(b[0]),"r"(b[1]));
}

// C[M,N]=A[M,K]*B[K,N], fp16 in / fp32 acc. MODE 0: outF=acc+bias. 1: outH=gelu(acc+bias).
// 2: ydst[gidx[r]] += gw[r]*(acc+bias). 3: outH=half(acc+addF).  GATHER: A row = gidx[r].
template<int MODE,bool GATHER>
__global__ void __launch_bounds__(256) gemm_k(
  const __half* __restrict__ A, const __half* __restrict__ B,
  int M, const int* __restrict__ Mp, int N, int K,
  const float* __restrict__ bias, float* __restrict__ outF, __half* __restrict__ outH,
  const float* __restrict__ addF, const int* __restrict__ gidx,
  const float* __restrict__ gw, float* __restrict__ ydst)
{
  if (Mp) M = *Mp;
  const int bM = blockIdx.y*128, bN = blockIdx.x*128;
  if (bM >= M) return;
  __shared__ __half As[2][128][48];
  __shared__ __half Bs[2][32][144];
  const int tid=threadIdx.x, lane=tid&31, warp=tid>>5;
  const int wM=warp>>2, wN=warp&3;

  const __half* ap[2]; bool av[2]; int ar[2],ac[2];
  #pragma unroll
  for(int s=0;s<2;s++){
    int c=tid+s*256; ar[s]=c>>2; ac[s]=(c&3)*8;
    int rg=bM+ar[s]; bool v=rg<M;
    long rowA = v ? (GATHER?(long)gidx[rg]:(long)rg) : 0;
    ap[s]=A+rowA*(long)K+ac[s]; av[s]=v;
  }
  const __half* bp[2]; int br[2],bc[2];
  #pragma unroll
  for(int s=0;s<2;s++){
    int c=tid+s*256; br[s]=c>>4; bc[s]=(c&15)*8;
    bp[s]=B+(long)br[s]*N+bN+bc[s];
  }
  float acc[4][4][4];
  #pragma unroll
  for(int i=0;i<4;i++)
    #pragma unroll
    for(int j=0;j<4;j++)
      #pragma unroll
      for(int q=0;q<4;q++) acc[i][j][q]=0.f;

  const int KT=K>>5;
  #pragma unroll
  for(int s=0;s<2;s++) cp16(&As[0][ar[s]][ac[s]],ap[s],av[s]);
  #pragma unroll
  for(int s=0;s<2;s++) cp16(&Bs[0][br[s]][bc[s]],bp[s],true);
  asm volatile("cp.async.commit_group;\n");

  for(int kt=0;kt<KT;kt++){
    if(kt+1<KT){
      int st=(kt+1)&1;
      #pragma unroll
      for(int s=0;s<2;s++) cp16(&As[st][ar[s]][ac[s]],ap[s]+(kt+1)*32,av[s]);
      #pragma unroll
      for(int s=0;s<2;s++) cp16(&Bs[st][br[s]][bc[s]],bp[s]+(long)(kt+1)*32*N,true);
      asm volatile("cp.async.commit_group;\ncp.async.wait_group 1;\n");
    } else asm volatile("cp.async.wait_group 0;\n");
    __syncthreads();
    const int st=kt&1, lr=lane>>2, lc=(lane&3)*2;
    #pragma unroll
    for(int kk=0;kk<2;kk++){
      uint32_t af[4][4], bf[4][2];
      #pragma unroll
      for(int mi=0;mi<4;mi++){
        int r=wM*64+mi*16+lr, cc=kk*16+lc;
        af[mi][0]=*(const uint32_t*)&As[st][r  ][cc  ];
        af[mi][1]=*(const uint32_t*)&As[st][r+8][cc  ];
        af[mi][2]=*(const uint32_t*)&As[st][r  ][cc+8];
        af[mi][3]=*(const uint32_t*)&As[st][r+8][cc+8];
      }
      #pragma unroll
      for(int ni=0;ni<4;ni++){
        int cc=wN*32+ni*8+(lane>>2), kr=kk*16+(lane&3)*2;
        __half2 p0=__halves2half2(Bs[st][kr  ][cc],Bs[st][kr+1][cc]);
        __half2 p1=__halves2half2(Bs[st][kr+8][cc],Bs[st][kr+9][cc]);
        bf[ni][0]=*(uint32_t*)&p0; bf[ni][1]=*(uint32_t*)&p1;
      }
      #pragma unroll
      for(int mi=0;mi<4;mi++)
        #pragma unroll
        for(int ni=0;ni<4;ni++) mma(acc[mi][ni],af[mi],bf[ni]);
    }
    __syncthreads();
  }
  const int lr=lane>>2, lc=(lane&3)*2;
  #pragma unroll
  for(int mi=0;mi<4;mi++)
    #pragma unroll
    for(int ni=0;ni<4;ni++){
      int r0=bM+wM*64+mi*16+lr, c0=bN+wN*32+ni*8+lc;
      #pragma unroll
      for(int q=0;q<4;q++){
        int r=r0+(q>>1)*8, c=c0+(q&1);
        if(r>=M) continue;
        float v=acc[mi][ni][q];
        if(MODE==0){ if(bias) v+=bias[c]; outF[(long)r*N+c]=v; }
        else if(MODE==1){ if(bias) v+=bias[c];
          v=0.5f*v*(1.0f+erff(v*0.70710678f)); outH[(long)r*N+c]=__float2half(v); }
        else if(MODE==2){ if(bias) v+=bias[c];
          ydst[(long)gidx[r]*N+c]+=gw[r]*v; }
        else { v+=addF[(long)r*N+c]; outH[(long)r*N+c]=__float2half(v); }
      }
    }
}

__global__ void f2h_k(const float* __restrict__ s, __half* __restrict__ d, int n){
  for(int i=blockIdx.x*blockDim.x+threadIdx.x;i<n;i+=gridDim.x*blockDim.x)
    d[i]=__float2half(s[i]);
}
__global__ void wqkv_k(const float* __restrict__ Wq,const float* __restrict__ Wkv,__half* __restrict__ d){
  for(int i=blockIdx.x*blockDim.x+threadIdx.x;i<1024*384;i+=gridDim.x*blockDim.x){
    int r=i/384,c=i%384;
    d[i]=__float2half(c<128?Wq[r*128+c]:Wkv[r*256+c-128]);
  }
}
__global__ void wkuv_k(const float* __restrict__ Wku,const float* __restrict__ Wvu,__half* __restrict__ d){
  for(int i=blockIdx.x*blockDim.x+threadIdx.x;i<256*256;i+=gridDim.x*blockDim.x){
    int r=i/256,c=i%256;
    d[i]=__float2half(c<128?Wku[r*128+c]:Wvu[r*128+c-128]);
  }
}
__global__ void lat_k(const float* __restrict__ qlat,__half* __restrict__ d){
  for(int i=blockIdx.x*blockDim.x+threadIdx.x;i<NT*256;i+=gridDim.x*blockDim.x)
    d[i]=__float2half(qlat[(long)(i/256)*384+128+(i&255)]);
}
__global__ void gate_k(const float* __restrict__ x,const float* __restrict__ Wg,
                       const float* __restrict__ rs,int* __restrict__ tokE,float* __restrict__ tokW){
  int t=blockIdx.x, tid=threadIdx.x;
  float a[8]={0,0,0,0,0,0,0,0};
  const float* xr=x+(long)t*1024;
  for(int i=tid;i<1024;i+=128){
    float xv=xr[i]; const float* wr=Wg+i*8;
    #pragma unroll
    for(int e=0;e<8;e++) a[e]+=xv*wr[e];
  }
  __shared__ float sm[128][8];
  #pragma unroll
  for(int e=0;e<8;e++) sm[tid][e]=a[e];
  __syncthreads();
  for(int off=64;off;off>>=1){
    if(tid<off){
      #pragma unroll
      for(int e=0;e<8;e++) sm[tid][e]+=sm[tid+off][e];
    }
    __syncthreads();
  }
  if(tid==0){
    float s[8], sc=rs[0];
    #pragma unroll
    for(int e=0;e<8;e++) s[e]=sc/(1.f+expf(-sm[0][e]));
    int i0=0;
    #pragma unroll
    for(int e=1;e<8;e++) if(s[e]>s[i0]) i0=e;
    int i1=-1;
    #pragma unroll
    for(int e=0;e<8;e++){ if(e==i0)continue; if(i1<0||s[e]>s[i1]) i1=e; }
    float sum=s[i0]+s[i1];
    tokE[2*t]=i0; tokE[2*t+1]=i1;
    tokW[2*t]=s[i0]/sum; tokW[2*t+1]=s[i1]/sum;
  }
}
__global__ void lists_k(const int* __restrict__ tokE,const float* __restrict__ tokW,
                        int* __restrict__ list,float* __restrict__ wlist,int* __restrict__ cnt){
  int e=blockIdx.x, tid=threadIdx.x;
  __shared__ int s[256]; __shared__ int base;
  if(tid==0) base=0;
  __syncthreads();
  for(int st=0;st<NT;st+=256){
    int t=st+tid, flag=0; float w=0.f;
    if(tokE[2*t]==e){flag=1;w=tokW[2*t];}
    else if(tokE[2*t+1]==e){flag=1;w=tokW[2*t+1];}
    s[tid]=flag; __syncthreads();
    for(int off=1;off<256;off<<=1){
      int v=(tid>=off)?s[tid-off]:0; __syncthreads();
      s[tid]+=v; __syncthreads();
    }
    int pos=base+s[tid]-flag;
    if(flag){ list[e*NT+pos]=t; wlist[e*NT+pos]=w; }
    __syncthreads();
    if(tid==0) base+=s[255];
    __syncthreads();
  }
  if(tid==0) cnt[e]=base;
}
// s=8 attention. freqs = pos*rope_freq is ELEMENTWISE (both len 8):
// angle[j] = j * 10000^(-j/8), identical for every position.
__global__ void attn_k(const float* __restrict__ qlat,const float* __restrict__ kv,
                       __half* __restrict__ oh){
  int b=blockIdx.x, h=threadIdx.x>>5, lane=threadIdx.x&31;
  __shared__ float q[4][8][32],k[4][8][32],v[4][8][32],p[4][8][8],sc[4][8][8];
  #pragma unroll
  for(int s=0;s<8;s++){
    long t=(long)b*8+s;
    q[h][s][lane]=qlat[t*384+h*32+lane];
    k[h][s][lane]=kv[t*256+h*32+lane];
    v[h][s][lane]=kv[t*256+128+h*32+lane];
  }
  __syncwarp();
  if(lane<8){
    float ang=(float)lane*powf(10000.f,-(float)lane/8.f);
    float c=cosf(ang), sn=sinf(ang);
    #pragma unroll
    for(int s=0;s<8;s++){
      float x1=q[h][s][lane], x2=q[h][s][lane+8];
      q[h][s][lane]=x1*c-x2*sn; q[h][s][lane+8]=x1*sn+x2*c;
    }
  }
  __syncwarp();
  #pragma unroll
  for(int e=0;e<2;e++){
    int id=lane+e*32, qi=id>>3, ki=id&7;
    float s0=0.f;
    #pragma unroll
    for(int d=0;d<32;d++) s0+=q[h][qi][d]*k[h][ki][d];
    sc[h][qi][ki]=s0*0.17677669529663687f;
  }
  __syncwarp();
  if(lane<8){
    float m=-1e30f;
    #pragma unroll
    for(int j=0;j<8;j++) m=fmaxf(m,sc[h][lane][j]);
    float ex[8], su=0.f;
    #pragma unroll
    for(int j=0;j<8;j++){ ex[j]=expf(sc[h][lane][j]-m); su+=ex[j]; }
    float inv=1.f/su;
    #pragma unroll
    for(int j=0;j<8;j++) p[h][lane][j]=ex[j]*inv;
  }
  __syncwarp();
  #pragma unroll
  for(int qi=0;qi<8;qi++){
    float o=0.f;
    #pragma unroll
    for(int j=0;j<8;j++) o+=p[h][qi][j]*v[h][j][lane];
    oh[((long)b*8+qi)*128+h*32+lane]=__float2half(o);
  }
}
__global__ void value_k(const __half* __restrict__ ch,const float* __restrict__ Wv,
                        const float* __restrict__ bv,float* __restrict__ o){
  int t=blockIdx.x, tid=threadIdx.x;
  float s=0.f;
  for(int i=tid;i<1024;i+=128) s+=__half2float(ch[(long)t*1024+i])*Wv[i];
  __shared__ float sm[128];
  sm[tid]=s; __syncthreads();
  for(int off=64;off;off>>=1){ if(tid<off) sm[tid]+=sm[tid+off]; __syncthreads(); }
  if(tid==0) o[t]=sm[0]+bv[0];
}

extern "C" void kernel_launch(void* const* d_in, const int* in_sizes, int n_in,
                              void* d_out, int out_size){
  const float *x=(const float*)d_in[0], *Wg=(const float*)d_in[1], *W1=(const float*)d_in[2],
    *b1=(const float*)d_in[3], *W2=(const float*)d_in[4], *b2=(const float*)d_in[5],
    *Ws1=(const float*)d_in[6], *bs1=(const float*)d_in[7], *Ws2=(const float*)d_in[8],
    *bs2=(const float*)d_in[9], *rs=(const float*)d_in[10], *Wq=(const float*)d_in[11],
    *Wkv=(const float*)d_in[12], *Wku=(const float*)d_in[13], *Wvu=(const float*)d_in[14],
    *Wao=(const float*)d_in[15], *Wo=(const float*)d_in[16], *bo=(const float*)d_in[17],
    *Wv=(const float*)d_in[18], *bv=(const float*)d_in[19];
  float* out=(float*)d_out;
  #define GS(T,p,s) T* p; cudaGetSymbolAddress((void**)&p,s)
  GS(__half,xh,g_xh); GS(__half,W1h,g_W1h); GS(__half,W2h,g_W2h);
  GS(__half,Ws1h,g_Ws1h); GS(__half,Ws2h,g_Ws2h); GS(__half,Wqkvh,g_Wqkvh);
  GS(__half,Wkuvh,g_Wkuvh); GS(__half,Waoh,g_Waoh); GS(__half,Woh,g_Woh);
  GS(__half,hb,g_hb); GS(float,y,g_y); GS(__half,yh,g_yh); GS(float,qlat,g_qlat);
  GS(__half,lath,g_lath); GS(float,kvb,g_kv); GS(__half,oh,g_oh); GS(__half,combh,g_combh);
  GS(int,tokE,g_tokE); GS(float,tokW,g_tokW); GS(int,lst,g_list); GS(float,wlst,g_wlist);
  GS(int,cnt,g_cnt);
  #undef GS

  f2h_k<<<2048,256>>>(x,xh,NT*1024);
  f2h_k<<<2048,256>>>(W1,W1h,NE*1024*1024);
  f2h_k<<<2048,256>>>(W2,W2h,NE*1024*1024);
  f2h_k<<<1024,256>>>(Ws1,Ws1h,1024*1024);
  f2h_k<<<1024,256>>>(Ws2,Ws2h,1024*1024);
  f2h_k<<<1024,256>>>(Wo,Woh,1024*1024);
  f2h_k<<<256,256>>>(Wao,Waoh,128*1024);
  wqkv_k<<<512,256>>>(Wq,Wkv,Wqkvh);
  wkuv_k<<<64,256>>>(Wku,Wvu,Wkuvh);
  gate_k<<<NT,128>>>(x,Wg,rs,tokE,tokW);
  lists_k<<<NE,256>>>(tokE,tokW,lst,wlst,cnt);

  dim3 gFull(8,128);
  gemm_k<1,false><<<gFull,256>>>(xh,Ws1h,NT,nullptr,1024,1024,bs1,nullptr,hb,nullptr,nullptr,nullptr,nullptr);
  gemm_k<0,false><<<gFull,256>>>(hb,Ws2h,NT,nullptr,1024,1024,bs2,y,nullptr,nullptr,nullptr,nullptr,nullptr);
  for(int e=0;e<NE;e++){
    gemm_k<1,true ><<<gFull,256>>>(xh,W1h+(long)e*1024*1024,0,cnt+e,1024,1024,b1+e*1024,
                                   nullptr,hb,nullptr,lst+e*NT,nullptr,nullptr);
    gemm_k<2,false><<<gFull,256>>>(hb,W2h+(long)e*1024*1024,0,cnt+e,1024,1024,b2+e*1024,
                                   nullptr,nullptr,nullptr,lst+e*NT,wlst+e*NT,y);
  }
  f2h_k<<<2048,256>>>(y,yh,NT*1024);
  gemm_k<0,false><<<dim3(3,128),256>>>(yh,Wqkvh,NT,nullptr,384,1024,nullptr,qlat,nullptr,nullptr,nullptr,nullptr,nullptr);
  lat_k<<<2048,256>>>(qlat,lath);
  gemm_k<0,false><<<dim3(2,128),256>>>(lath,Wkuvh,NT,nullptr,256,256,nullptr,kvb,nullptr,nullptr,nullptr,nullptr,nullptr);
  attn_k<<<2048,128>>>(qlat,kvb,oh);
  gemm_k<3,false><<<gFull,256>>>(oh,Waoh,NT,nullptr,1024,128,nullptr,nullptr,combh,y,nullptr,nullptr,nullptr);
  gemm_k<0,false><<<gFull,256>>>(combh,Woh,NT,nullptr,1024,1024,bo,out,nullptr,nullptr,nullptr,nullptr,nullptr);
  value_k<<<NT,128>>>(combh,Wv,bv,out+(long)NT*1024);
}

// round 4
// speedup vs baseline: 1.2353x; 1.2353x over previous
#include <cuda_runtime.h>
#include <cuda_fp16.h>
#include <math.h>
#include <stdint.h>

#define NT 16384
#define NE 8

// ---------------- scratch ----------------
__device__ __half g_xh   [NT*1024];
__device__ __half g_W1h  [NE*1024*1024];  // [e][F][D] (K-major rows)
__device__ __half g_W2h  [NE*1024*1024];  // [e][D][F]
__device__ __half g_Ws1h [1024*1024];     // [F][D]
__device__ __half g_Ws2h [1024*1024];     // [D][F]
__device__ __half g_Wqkvh[384*1024];      // rows 0-127 Wq^T, 128-383 Wkv^T
__device__ __half g_Wkuvh[256*256];       // rows 0-127 Wku^T, 128-255 Wvu^T
__device__ __half g_Waoh [1024*128];      // [D][128]
__device__ __half g_Woh  [1024*1024];     // [O][D]
__device__ __half g_hb   [NT*1024];
__device__ float  g_y    [NT*1024];
__device__ __half g_yh   [NT*1024];
__device__ float  g_qlat [NT*384];
__device__ __half g_lath [NT*256];
__device__ float  g_kv   [NT*256];
__device__ __half g_oh   [NT*128];
__device__ __half g_combh[NT*1024];
__device__ int    g_tokE [NT*2];
__device__ float  g_tokW [NT*2];
__device__ int    g_list [NE*NT];
__device__ float  g_wlist[NE*NT];
__device__ int    g_cnt  [NE];

// ---------------- PTX helpers ----------------
__device__ __forceinline__ void cp16s(uint32_t s, const void* g, bool p){
  int n = p ? 16 : 0;
  asm volatile("cp.async.cg.shared.global [%0],[%1],16,%2;\n"::"r"(s),"l"(g),"r"(n));
}
#define CP_COMMIT() asm volatile("cp.async.commit_group;\n")
__device__ __forceinline__ void ldsm4(uint32_t& r0,uint32_t& r1,uint32_t& r2,uint32_t& r3,uint32_t a){
  asm volatile("ldmatrix.sync.aligned.m8n8.x4.shared.b16 {%0,%1,%2,%3}, [%4];\n"
    : "=r"(r0),"=r"(r1),"=r"(r2),"=r"(r3) : "r"(a));
}
__device__ __forceinline__ void mma16816(float c[4], const uint32_t a[4], const uint32_t b[2]){
  asm volatile("mma.sync.aligned.m16n8k16.row.col.f32.f16.f16.f32 "
    "{%0,%1,%2,%3},{%4,%5,%6,%7},{%8,%9},{%0,%1,%2,%3};\n"
    :"+f"(c[0]),"+f"(c[1]),"+f"(c[2]),"+f"(c[3])
    :"r"(a[0]),"r"(a[1]),"r"(a[2]),"r"(a[3]),"r"(b[0]),"r"(b[1]));
}

// ---------------- HMMA GEMM, ldmatrix both operands ----------------
// C[M,Ntot] = A[M,K] * BT[Ntot,K]^T. fp16 in, fp32 acc.
// Tile 128x128x32, 4-stage cp.async, 8 warps (64x32 warp tiles).
// Smem: A rows [128][40] (m-major), B rows [128][40] (n-major). 80B row stride:
// ldmatrix 8-row address sets hit all 32 banks exactly once -> conflict-free.
// MODE 0: outF=acc(+bias). 1: outH=gelu(acc+bias). 2: ydst[gidx[r]] += gw[r]*(acc+bias).
// 3: outH=half(acc+addF). GATHER: A row = gidx[r].
#define STAGES 4
#define RSTR 40                       // halves per smem row
#define STAGE_H (128*RSTR)            // halves per stage per operand

template<int MODE,bool GATHER>
__global__ void __launch_bounds__(256,2) hm_gemm(
  const __half* __restrict__ A, const __half* __restrict__ BT,
  int M, const int* __restrict__ Mp, int Ntot, int K,
  const float* __restrict__ bias, float* __restrict__ outF, __half* __restrict__ outH,
  const float* __restrict__ addF, const int* __restrict__ gidx,
  const float* __restrict__ gw, float* __restrict__ ydst)
{
  if (Mp) M = *Mp;
  const int bM = blockIdx.y*128;
  if (bM >= M) return;
  const int bN = blockIdx.x*128;

  extern __shared__ __half sm[];
  __half* Asm = sm;                    // [STAGES][128][RSTR]
  __half* Bsm = sm + STAGES*STAGE_H;   // [STAGES][128][RSTR]
  const uint32_t AsmU = (uint32_t)__cvta_generic_to_shared(Asm);
  const uint32_t BsmU = (uint32_t)__cvta_generic_to_shared(Bsm);

  const int tid=threadIdx.x, lane=tid&31, warp=tid>>5;
  const int m0=(warp>>2)*64, n0=(warp&3)*32;

  // ---- cp.async slots: 2 A-chunks + 2 B-chunks per thread (16B each) ----
  const __half* aptr[2]; uint32_t aoff[2]; bool avld[2];
  #pragma unroll
  for(int s=0;s<2;s++){
    int c=tid+256*s, row=c>>2, col=(c&3)*8;
    int rg=bM+row; bool v=rg<M;
    long rowIdx = v ? (GATHER?(long)gidx[rg]:(long)rg) : 0;
    aptr[s]=A+rowIdx*(long)K+col; aoff[s]=(uint32_t)(row*RSTR+col)*2; avld[s]=v;
  }
  const __half* bptr[2]; uint32_t boff[2];
  #pragma unroll
  for(int s=0;s<2;s++){
    int c=tid+256*s, row=c>>2, col=(c&3)*8;
    bptr[s]=BT+(long)(bN+row)*K+col; boff[s]=(uint32_t)(row*RSTR+col)*2;
  }
  auto load_stage=[&](int st_){
    int buf=st_%STAGES;
    uint32_t ab=AsmU+buf*STAGE_H*2, bb=BsmU+buf*STAGE_H*2;
    #pragma unroll
    for(int s=0;s<2;s++) cp16s(ab+aoff[s], aptr[s]+st_*32, avld[s]);
    #pragma unroll
    for(int s=0;s<2;s++) cp16s(bb+boff[s], bptr[s]+st_*32, true);
    CP_COMMIT();
  };

  float acc[4][4][4];
  #pragma unroll
  for(int i=0;i<4;i++)
    #pragma unroll
    for(int j=0;j<4;j++){ acc[i][j][0]=0.f;acc[i][j][1]=0.f;acc[i][j][2]=0.f;acc[i][j][3]=0.f; }

  const int KT=K>>5;
  #pragma unroll
  for(int s=0;s<3;s++){ if(s<KT) load_stage(s); else CP_COMMIT(); }

  // ldmatrix per-lane address components
  const int a_r = ((lane>>3)&1)*8 + (lane&7);   // row within 16
  const int a_k = (lane>>4)*8;                  // k offset within 16
  const int b_n = (lane>>4)*8 + (lane&7);       // n within 16
  const int b_k = ((lane>>3)&1)*8;              // k offset within 16

  for(int st=0; st<KT; st++){
    asm volatile("cp.async.wait_group 2;\n");
    __syncthreads();
    if (st+3<KT) load_stage(st+3);
    const int buf=st%STAGES;
    const uint32_t ab=AsmU+buf*STAGE_H*2, bb=BsmU+buf*STAGE_H*2;
    #pragma unroll
    for(int kk=0;kk<2;kk++){
      const int k16=kk*16;
      uint32_t af[4][4], bf[4][2];
      #pragma unroll
      for(int mi=0;mi<4;mi++){
        uint32_t addr = ab + (uint32_t)((m0+mi*16+a_r)*RSTR + k16 + a_k)*2;
        ldsm4(af[mi][0],af[mi][1],af[mi][2],af[mi][3],addr);
      }
      #pragma unroll
      for(int nb=0;nb<2;nb++){
        uint32_t addr = bb + (uint32_t)((n0+nb*16+b_n)*RSTR + k16 + b_k)*2;
        ldsm4(bf[nb*2][0],bf[nb*2][1],bf[nb*2+1][0],bf[nb*2+1][1],addr);
      }
      #pragma unroll
      for(int mi=0;mi<4;mi++)
        #pragma unroll
        for(int ni=0;ni<4;ni++) mma16816(acc[mi][ni],af[mi],bf[ni]);
    }
    __syncthreads();
  }

  // ---- epilogue ----
  const int lr=lane>>2, lc=(lane&3)*2;
  #pragma unroll
  for(int mi=0;mi<4;mi++)
    #pragma unroll
    for(int ni=0;ni<4;ni++){
      int r0=bM+m0+mi*16+lr, c0=bN+n0+ni*8+lc;
      #pragma unroll
      for(int q=0;q<4;q++){
        int r=r0+(q>>1)*8, c=c0+(q&1);
        if(r>=M) continue;
        float v=acc[mi][ni][q];
        if(MODE==0){ if(bias) v+=bias[c]; outF[(long)r*Ntot+c]=v; }
        else if(MODE==1){ if(bias) v+=bias[c];
          v=0.5f*v*(1.0f+erff(v*0.70710678118654752f)); outH[(long)r*Ntot+c]=__float2half(v); }
        else if(MODE==2){ if(bias) v+=bias[c];
          ydst[(long)gidx[r]*Ntot+c]+=gw[r]*v; }
        else { v+=addF[(long)r*Ntot+c]; outH[(long)r*Ntot+c]=__float2half(v); }
      }
    }
}
#define HM_SMEM (2*STAGES*STAGE_H*2)

// ---------------- prep kernels ----------------
__global__ void f2h_k(const float* __restrict__ s, __half* __restrict__ d, int n){
  for(int i=blockIdx.x*blockDim.x+threadIdx.x;i<n;i+=gridDim.x*blockDim.x)
    d[i]=__float2half(s[i]);
}
// S:[R][C] fp32 -> D:[C][R] half (batched along z)
__global__ void t_f2h_k(const float* __restrict__ S, __half* __restrict__ D, int R, int C){
  __shared__ float t[32][33];
  long bo = (long)blockIdx.z * R * C;
  int c0 = blockIdx.x*32, r0 = blockIdx.y*32;
  int x = threadIdx.x, y = threadIdx.y;   // 32 x 8
  #pragma unroll
  for (int i=y; i<32; i+=8){
    int r=r0+i, c=c0+x;
    t[i][x] = (r<R && c<C) ? S[bo+(long)r*C+c] : 0.f;
  }
  __syncthreads();
  #pragma unroll
  for (int i=y; i<32; i+=8){
    int c=c0+i, r=r0+x;
    if (c<C && r<R) D[bo+(long)c*R+r] = __float2half(t[x][i]);
  }
}
__global__ void lat_k(const float* __restrict__ qlat,__half* __restrict__ d){
  for(int i=blockIdx.x*blockDim.x+threadIdx.x;i<NT*256;i+=gridDim.x*blockDim.x)
    d[i]=__float2half(qlat[(long)(i>>8)*384+128+(i&255)]);
}
__global__ void gate_k(const float* __restrict__ x,const float* __restrict__ Wg,
                       const float* __restrict__ rs,int* __restrict__ tokE,float* __restrict__ tokW){
  int t=blockIdx.x, tid=threadIdx.x;
  float a[8]={0,0,0,0,0,0,0,0};
  const float* xr=x+(long)t*1024;
  for(int i=tid;i<1024;i+=128){
    float xv=xr[i]; const float* wr=Wg+i*8;
    #pragma unroll
    for(int e=0;e<8;e++) a[e]+=xv*wr[e];
  }
  __shared__ float sm[128][8];
  #pragma unroll
  for(int e=0;e<8;e++) sm[tid][e]=a[e];
  __syncthreads();
  for(int off=64;off;off>>=1){
    if(tid<off){
      #pragma unroll
      for(int e=0;e<8;e++) sm[tid][e]+=sm[tid+off][e];
    }
    __syncthreads();
  }
  if(tid==0){
    float s[8], sc=rs[0];
    #pragma unroll
    for(int e=0;e<8;e++) s[e]=sc/(1.f+expf(-sm[0][e]));
    int i0=0;
    #pragma unroll
    for(int e=1;e<8;e++) if(s[e]>s[i0]) i0=e;
    int i1=-1;
    #pragma unroll
    for(int e=0;e<8;e++){ if(e==i0)continue; if(i1<0||s[e]>s[i1]) i1=e; }
    float sum=s[i0]+s[i1];
    tokE[2*t]=i0; tokE[2*t+1]=i1;
    tokW[2*t]=s[i0]/sum; tokW[2*t+1]=s[i1]/sum;
  }
}
__global__ void lists_k(const int* __restrict__ tokE,const float* __restrict__ tokW,
                        int* __restrict__ list,float* __restrict__ wlist,int* __restrict__ cnt){
  int e=blockIdx.x, tid=threadIdx.x;
  __shared__ int s[256]; __shared__ int base;
  if(tid==0) base=0;
  __syncthreads();
  for(int st=0;st<NT;st+=256){
    int t=st+tid, flag=0; float w=0.f;
    if(tokE[2*t]==e){flag=1;w=tokW[2*t];}
    else if(tokE[2*t+1]==e){flag=1;w=tokW[2*t+1];}
    s[tid]=flag; __syncthreads();
    for(int off=1;off<256;off<<=1){
      int v=(tid>=off)?s[tid-off]:0; __syncthreads();
      s[tid]+=v; __syncthreads();
    }
    int pos=base+s[tid]-flag;
    if(flag){ list[e*NT+pos]=t; wlist[e*NT+pos]=w; }
    __syncthreads();
    if(tid==0) base+=s[255];
    __syncthreads();
  }
  if(tid==0) cnt[e]=base;
}
// s=8 attention. freqs = pos*rope_freq is ELEMENTWISE (both len 8):
// angle[j] = j * 10000^(-j/8), identical for every position.
__global__ void attn_k(const float* __restrict__ qlat,const float* __restrict__ kv,
                       __half* __restrict__ oh){
  int b=blockIdx.x, h=threadIdx.x>>5, lane=threadIdx.x&31;
  __shared__ float q[4][8][32],k[4][8][32],v[4][8][32],p[4][8][8],sc[4][8][8];
  #pragma unroll
  for(int s=0;s<8;s++){
    long t=(long)b*8+s;
    q[h][s][lane]=qlat[t*384+h*32+lane];
    k[h][s][lane]=kv[t*256+h*32+lane];
    v[h][s][lane]=kv[t*256+128+h*32+lane];
  }
  __syncwarp();
  if(lane<8){
    float ang=(float)lane*powf(10000.f,-(float)lane/8.f);
    float c=cosf(ang), sn=sinf(ang);
    #pragma unroll
    for(int s=0;s<8;s++){
      float x1=q[h][s][lane], x2=q[h][s][lane+8];
      q[h][s][lane]=x1*c-x2*sn; q[h][s][lane+8]=x1*sn+x2*c;
    }
  }
  __syncwarp();
  #pragma unroll
  for(int e=0;e<2;e++){
    int id=lane+e*32, qi=id>>3, ki=id&7;
    float s0=0.f;
    #pragma unroll
    for(int d=0;d<32;d++) s0+=q[h][qi][d]*k[h][ki][d];
    sc[h][qi][ki]=s0*0.17677669529663687f;
  }
  __syncwarp();
  if(lane<8){
    float m=-1e30f;
    #pragma unroll
    for(int j=0;j<8;j++) m=fmaxf(m,sc[h][lane][j]);
    float ex[8], su=0.f;
    #pragma unroll
    for(int j=0;j<8;j++){ ex[j]=expf(sc[h][lane][j]-m); su+=ex[j]; }
    float inv=1.f/su;
    #pragma unroll
    for(int j=0;j<8;j++) p[h][lane][j]=ex[j]*inv;
  }
  __syncwarp();
  #pragma unroll
  for(int qi=0;qi<8;qi++){
    float o=0.f;
    #pragma unroll
    for(int j=0;j<8;j++) o+=p[h][qi][j]*v[h][j][lane];
    oh[((long)b*8+qi)*128+h*32+lane]=__float2half(o);
  }
}
__global__ void value_k(const __half* __restrict__ ch,const float* __restrict__ Wv,
                        const float* __restrict__ bv,float* __restrict__ o){
  int t=blockIdx.x, tid=threadIdx.x;
  float s=0.f;
  for(int i=tid;i<1024;i+=128) s+=__half2float(ch[(long)t*1024+i])*Wv[i];
  __shared__ float sm[128];
  sm[tid]=s; __syncthreads();
  for(int off=64;off;off>>=1){ if(tid<off) sm[tid]+=sm[tid+off]; __syncthreads(); }
  if(tid==0) o[t]=sm[0]+bv[0];
}

// ---------------- host launcher ----------------
extern "C" void kernel_launch(void* const* d_in, const int* in_sizes, int n_in,
                              void* d_out, int out_size){
  const float *x=(const float*)d_in[0], *Wg=(const float*)d_in[1], *W1=(const float*)d_in[2],
    *b1=(const float*)d_in[3], *W2=(const float*)d_in[4], *b2=(const float*)d_in[5],
    *Ws1=(const float*)d_in[6], *bs1=(const float*)d_in[7], *Ws2=(const float*)d_in[8],
    *bs2=(const float*)d_in[9], *rs=(const float*)d_in[10], *Wq=(const float*)d_in[11],
    *Wkv=(const float*)d_in[12], *Wku=(const float*)d_in[13], *Wvu=(const float*)d_in[14],
    *Wao=(const float*)d_in[15], *Wo=(const float*)d_in[16], *bo=(const float*)d_in[17],
    *Wv=(const float*)d_in[18], *bv=(const float*)d_in[19];
  float* out=(float*)d_out;
  #define GS(T,p,s) T* p; cudaGetSymbolAddress((void**)&p,s)
  GS(__half,xh,g_xh); GS(__half,W1h,g_W1h); GS(__half,W2h,g_W2h);
  GS(__half,Ws1h,g_Ws1h); GS(__half,Ws2h,g_Ws2h); GS(__half,Wqkvh,g_Wqkvh);
  GS(__half,Wkuvh,g_Wkuvh); GS(__half,Waoh,g_Waoh); GS(__half,Woh,g_Woh);
  GS(__half,hb,g_hb); GS(float,y,g_y); GS(__half,yh,g_yh); GS(float,qlat,g_qlat);
  GS(__half,lath,g_lath); GS(float,kvb,g_kv); GS(__half,oh,g_oh); GS(__half,combh,g_combh);
  GS(int,tokE,g_tokE); GS(float,tokW,g_tokW); GS(int,lst,g_list); GS(float,wlst,g_wlist);
  GS(int,cnt,g_cnt);
  #undef GS

  cudaFuncSetAttribute(hm_gemm<0,false>, cudaFuncAttributeMaxDynamicSharedMemorySize, HM_SMEM);
  cudaFuncSetAttribute(hm_gemm<1,false>, cudaFuncAttributeMaxDynamicSharedMemorySize, HM_SMEM);
  cudaFuncSetAttribute(hm_gemm<1,true >, cudaFuncAttributeMaxDynamicSharedMemorySize, HM_SMEM);
  cudaFuncSetAttribute(hm_gemm<2,false>, cudaFuncAttributeMaxDynamicSharedMemorySize, HM_SMEM);
  cudaFuncSetAttribute(hm_gemm<3,false>, cudaFuncAttributeMaxDynamicSharedMemorySize, HM_SMEM);

  dim3 tb(32,8);
  f2h_k<<<2048,256>>>(x,xh,NT*1024);
  t_f2h_k<<<dim3(32,32,NE),tb>>>(W1,W1h,1024,1024);
  t_f2h_k<<<dim3(32,32,NE),tb>>>(W2,W2h,1024,1024);
  t_f2h_k<<<dim3(32,32),tb>>>(Ws1,Ws1h,1024,1024);
  t_f2h_k<<<dim3(32,32),tb>>>(Ws2,Ws2h,1024,1024);
  t_f2h_k<<<dim3(32,32),tb>>>(Wo,Woh,1024,1024);
  t_f2h_k<<<dim3(32,4),tb>>>(Wao,Waoh,128,1024);
  t_f2h_k<<<dim3(4,32),tb>>>(Wq,Wqkvh,1024,128);
  t_f2h_k<<<dim3(8,32),tb>>>(Wkv,Wqkvh+128*1024,1024,256);
  t_f2h_k<<<dim3(4,8),tb>>>(Wku,Wkuvh,256,128);
  t_f2h_k<<<dim3(4,8),tb>>>(Wvu,Wkuvh+128*256,256,128);
  gate_k<<<NT,128>>>(x,Wg,rs,tokE,tokW);
  lists_k<<<NE,256>>>(tokE,tokW,lst,wlst,cnt);

  dim3 gFull(8,128);   // 128x128 tiles over 16384 x 1024
  // shared FFN
  hm_gemm<1,false><<<gFull,256,HM_SMEM>>>(xh,Ws1h,NT,nullptr,1024,1024,bs1,nullptr,hb,nullptr,nullptr,nullptr,nullptr);
  hm_gemm<0,false><<<gFull,256,HM_SMEM>>>(hb,Ws2h,NT,nullptr,1024,1024,bs2,y,nullptr,nullptr,nullptr,nullptr,nullptr);
  // experts: gather -> gelu -> weighted scatter-add into y
  for(int e=0;e<NE;e++){
    hm_gemm<1,true ><<<gFull,256,HM_SMEM>>>(xh,W1h+(long)e*1024*1024,0,cnt+e,1024,1024,b1+e*1024,
                                            nullptr,hb,nullptr,lst+e*NT,nullptr,nullptr);
    hm_gemm<2,false><<<gFull,256,HM_SMEM>>>(hb,W2h+(long)e*1024*1024,0,cnt+e,1024,1024,b2+e*1024,
                                            nullptr,nullptr,nullptr,lst+e*NT,wlst+e*NT,y);
  }
  f2h_k<<<2048,256>>>(y,yh,NT*1024);
  // MLA projections
  hm_gemm<0,false><<<dim3(3,128),256,HM_SMEM>>>(yh,Wqkvh,NT,nullptr,384,1024,nullptr,qlat,nullptr,nullptr,nullptr,nullptr,nullptr);
  lat_k<<<2048,256>>>(qlat,lath);
  hm_gemm<0,false><<<dim3(2,128),256,HM_SMEM>>>(lath,Wkuvh,NT,nullptr,256,256,nullptr,kvb,nullptr,nullptr,nullptr,nullptr,nullptr);
  attn_k<<<2048,128>>>(qlat,kvb,oh);
  hm_gemm<3,false><<<gFull,256,HM_SMEM>>>(oh,Waoh,NT,nullptr,1024,128,nullptr,nullptr,combh,y,nullptr,nullptr,nullptr);
  // decision + value
  hm_gemm<0,false><<<gFull,256,HM_SMEM>>>(combh,Woh,NT,nullptr,1024,1024,bo,out,nullptr,nullptr,nullptr,nullptr,nullptr);
  value_k<<<NT,128>>>(combh,Wv,bv,out+(long)NT*1024);
}

// round 5
// speedup vs baseline: 1.6146x; 1.3071x over previous
#include <cuda_runtime.h>
#include <cuda_fp16.h>
#include <math.h>
#include <stdint.h>

#define NT 16384
#define NE 8
#define PADROWS 33792    // 2*NT + 8*128 margin

// ---------------- scratch ----------------
__device__ __half g_xh   [NT*1024];
__device__ __half g_W1h  [NE*1024*1024];  // [e][F][D] (n-major rows, K-contig)
__device__ __half g_W2h  [NE*1024*1024];  // [e][D][F]
__device__ __half g_Ws1h [1024*1024];
__device__ __half g_Ws2h [1024*1024];
__device__ __half g_Wqkvh[384*1024];
__device__ __half g_Wkuvh[256*256];
__device__ __half g_Waoh [1024*128];
__device__ __half g_Woh  [1024*1024];
__device__ __half g_hb   [PADROWS*1024];
__device__ __half g_z    [PADROWS*1024];
__device__ float  g_y    [NT*1024];
__device__ __half g_yh   [NT*1024];
__device__ float  g_qlat [NT*384];
__device__ __half g_lath [NT*256];
__device__ float  g_kv   [NT*256];
__device__ __half g_oh   [NT*128];
__device__ __half g_combh[NT*1024];
__device__ int    g_tokE [NT*2];
__device__ float  g_tokW [NT*2];
__device__ int    g_list [NE*NT];
__device__ int    g_rowTok[PADROWS];
__device__ int    g_tokPos[NT*2];
__device__ int    g_cnt  [NE];
__device__ int    g_poff [NE+1];

// ---------------- PTX helpers ----------------
__device__ __forceinline__ void cp16s(uint32_t s, const void* g, bool p){
  int n = p ? 16 : 0;
  asm volatile("cp.async.cg.shared.global [%0],[%1],16,%2;\n"::"r"(s),"l"(g),"r"(n));
}
#define CP_COMMIT() asm volatile("cp.async.commit_group;\n")
__device__ __forceinline__ void ldsm4(uint32_t& r0,uint32_t& r1,uint32_t& r2,uint32_t& r3,uint32_t a){
  asm volatile("ldmatrix.sync.aligned.m8n8.x4.shared.b16 {%0,%1,%2,%3}, [%4];\n"
    : "=r"(r0),"=r"(r1),"=r"(r2),"=r"(r3) : "r"(a));
}
__device__ __forceinline__ void mma16816(float c[4], const uint32_t a[4], const uint32_t b[2]){
  asm volatile("mma.sync.aligned.m16n8k16.row.col.f32.f16.f16.f32 "
    "{%0,%1,%2,%3},{%4,%5,%6,%7},{%8,%9},{%0,%1,%2,%3};\n"
    :"+f"(c[0]),"+f"(c[1]),"+f"(c[2]),"+f"(c[3])
    :"r"(a[0]),"r"(a[1]),"r"(a[2]),"r"(a[3]),"r"(b[0]),"r"(b[1]));
}

// ---------------- HMMA GEMM ----------------
// C[M,Ntot] = A[M,K] * BT[Ntot,K]^T. fp16 in / fp32 acc. Tile 128x128x32, 4-stage.
// MODE 0: outF=acc(+bias). 1: outH=gelu(acc+bias). 3: outH=half(acc+addF). 4: outH=half(acc+bias).
// GATHER: A row = gidx[r] (negative => masked). EXPSEG: expert e from poff; BT+=e<<20, bias+=e*1024.
#define STAGES 4
#define RSTR 40
#define STAGE_H (128*RSTR)

template<int MODE,bool GATHER,bool EXPSEG>
__global__ void __launch_bounds__(256,2) hm_gemm(
  const __half* __restrict__ A, const __half* __restrict__ BT,
  int M, const int* __restrict__ Mp, int Ntot, int K,
  const float* __restrict__ bias, float* __restrict__ outF, __half* __restrict__ outH,
  const float* __restrict__ addF, const int* __restrict__ gidx,
  const int* __restrict__ poff)
{
  if (Mp) M = *Mp;
  const int bM = blockIdx.y*128;
  if (bM >= M) return;
  const int bN = blockIdx.x*128;

  if (EXPSEG){
    int e=0;
    #pragma unroll
    for(int k=0;k<NE-1;k++) if (bM >= poff[k+1]) e = k+1;
    BT += (long)e<<20;
    if (bias) bias += e*1024;
  }

  extern __shared__ __half sm[];
  const uint32_t AsmU = (uint32_t)__cvta_generic_to_shared(sm);
  const uint32_t BsmU = AsmU + STAGES*STAGE_H*2;

  const int tid=threadIdx.x, lane=tid&31, warp=tid>>5;
  const int m0=(warp>>2)*64, n0=(warp&3)*32;

  const __half* aptr[2]; uint32_t aoff[2]; bool avld[2];
  #pragma unroll
  for(int s=0;s<2;s++){
    int c=tid+256*s, row=c>>2, col=(c&3)*8;
    int rg=bM+row; bool v=rg<M;
    long rowIdx;
    if (GATHER){ int gi = v ? gidx[rg] : 0; if (gi<0){ v=false; gi=0; } rowIdx = gi; }
    else rowIdx = v ? (long)rg : 0;
    aptr[s]=A+rowIdx*(long)K+col; aoff[s]=(uint32_t)(row*RSTR+col)*2; avld[s]=v;
  }
  const __half* bptr[2]; uint32_t boff[2];
  #pragma unroll
  for(int s=0;s<2;s++){
    int c=tid+256*s, row=c>>2, col=(c&3)*8;
    bptr[s]=BT+(long)(bN+row)*K+col; boff[s]=(uint32_t)(row*RSTR+col)*2;
  }
  auto load_stage=[&](int st_){
    int buf=st_%STAGES;
    uint32_t ab=AsmU+buf*STAGE_H*2, bb=BsmU+buf*STAGE_H*2;
    #pragma unroll
    for(int s=0;s<2;s++) cp16s(ab+aoff[s], aptr[s]+st_*32, avld[s]);
    #pragma unroll
    for(int s=0;s<2;s++) cp16s(bb+boff[s], bptr[s]+st_*32, true);
    CP_COMMIT();
  };

  float acc[4][4][4];
  #pragma unroll
  for(int i=0;i<4;i++)
    #pragma unroll
    for(int j=0;j<4;j++){ acc[i][j][0]=0.f;acc[i][j][1]=0.f;acc[i][j][2]=0.f;acc[i][j][3]=0.f; }

  const int KT=K>>5;
  #pragma unroll
  for(int s=0;s<3;s++){ if(s<KT) load_stage(s); else CP_COMMIT(); }

  const int a_r = ((lane>>3)&1)*8 + (lane&7);
  const int a_k = (lane>>4)*8;
  const int b_n = (lane>>4)*8 + (lane&7);
  const int b_k = ((lane>>3)&1)*8;

  for(int st=0; st<KT; st++){
    asm volatile("cp.async.wait_group 2;\n");
    __syncthreads();
    if (st+3<KT) load_stage(st+3);
    const int buf=st%STAGES;
    const uint32_t ab=AsmU+buf*STAGE_H*2, bb=BsmU+buf*STAGE_H*2;
    #pragma unroll
    for(int kk=0;kk<2;kk++){
      const int k16=kk*16;
      uint32_t af[4][4], bf[4][2];
      #pragma unroll
      for(int mi=0;mi<4;mi++){
        uint32_t addr = ab + (uint32_t)((m0+mi*16+a_r)*RSTR + k16 + a_k)*2;
        ldsm4(af[mi][0],af[mi][1],af[mi][2],af[mi][3],addr);
      }
      #pragma unroll
      for(int nb=0;nb<2;nb++){
        uint32_t addr = bb + (uint32_t)((n0+nb*16+b_n)*RSTR + k16 + b_k)*2;
        ldsm4(bf[nb*2][0],bf[nb*2][1],bf[nb*2+1][0],bf[nb*2+1][1],addr);
      }
      #pragma unroll
      for(int mi=0;mi<4;mi++)
        #pragma unroll
        for(int ni=0;ni<4;ni++) mma16816(acc[mi][ni],af[mi],bf[ni]);
    }
  }

  // ---- epilogue (pairwise stores) ----
  const int lr=lane>>2, lc=(lane&3)*2;
  #pragma unroll
  for(int mi=0;mi<4;mi++)
    #pragma unroll
    for(int ni=0;ni<4;ni++){
      int rA=bM+m0+mi*16+lr, c=bN+n0+ni*8+lc;
      #pragma unroll
      for(int h=0;h<2;h++){
        int r=rA+h*8;
        if(r>=M) continue;
        float v0=acc[mi][ni][h*2+0], v1=acc[mi][ni][h*2+1];
        if(MODE==0){
          if(bias){ v0+=bias[c]; v1+=bias[c+1]; }
          float2 f; f.x=v0; f.y=v1;
          *(float2*)&outF[(long)r*Ntot+c]=f;
        } else if(MODE==1){
          if(bias){ v0+=bias[c]; v1+=bias[c+1]; }
          v0=0.5f*v0*(1.0f+erff(v0*0.70710678118654752f));
          v1=0.5f*v1*(1.0f+erff(v1*0.70710678118654752f));
          *(__half2*)&outH[(long)r*Ntot+c]=__floats2half2_rn(v0,v1);
        } else if(MODE==3){
          v0+=addF[(long)r*Ntot+c]; v1+=addF[(long)r*Ntot+c+1];
          *(__half2*)&outH[(long)r*Ntot+c]=__floats2half2_rn(v0,v1);
        } else {
          if(bias){ v0+=bias[c]; v1+=bias[c+1]; }
          *(__half2*)&outH[(long)r*Ntot+c]=__floats2half2_rn(v0,v1);
        }
      }
    }
}
#define HM_SMEM (2*STAGES*STAGE_H*2)

// ---------------- prep / small kernels ----------------
__global__ void f2h4_k(const float4* __restrict__ s, uint2* __restrict__ d, int n4){
  int i=blockIdx.x*blockDim.x+threadIdx.x, st=gridDim.x*blockDim.x;
  for(;i<n4;i+=st){
    float4 v=s[i];
    __half2 h0=__floats2half2_rn(v.x,v.y), h1=__floats2half2_rn(v.z,v.w);
    uint2 u; u.x=*(uint32_t*)&h0; u.y=*(uint32_t*)&h1;
    d[i]=u;
  }
}
// S:[R][C] fp32 -> D:[C][R] half, batched along z. R,C multiples of 32.
__global__ void t_f2h_k(const float* __restrict__ S, __half* __restrict__ D, int R, int C){
  __shared__ float t[32][33];
  long bo = (long)blockIdx.z * R * C;
  int c0 = blockIdx.x*32, r0 = blockIdx.y*32;
  int x = threadIdx.x, y = threadIdx.y;   // 32 x 8
  #pragma unroll
  for (int i=y; i<32; i+=8) t[i][x] = S[bo+(long)(r0+i)*C + c0+x];
  __syncthreads();
  int q = y*32+x;
  int cl = q>>3, rl = (q&7)*4;
  __half2 a=__floats2half2_rn(t[rl  ][cl], t[rl+1][cl]);
  __half2 b=__floats2half2_rn(t[rl+2][cl], t[rl+3][cl]);
  uint2 u; u.x=*(uint32_t*)&a; u.y=*(uint32_t*)&b;
  *(uint2*)&D[bo+(long)(c0+cl)*R + r0+rl] = u;
}
__global__ void lat_k(const float* __restrict__ qlat,__half* __restrict__ d){
  int i=blockIdx.x*blockDim.x+threadIdx.x, st=gridDim.x*blockDim.x;
  for(;i<NT*128;i+=st){          // float2 granularity
    int t=i>>7, c=(i&127)*2;
    float2 v=*(const float2*)&qlat[(long)t*384+128+c];
    *(__half2*)&d[(long)t*256+c]=__floats2half2_rn(v.x,v.y);
  }
}
__global__ void gate_k(const float* __restrict__ x,const float* __restrict__ Wg,
                       const float* __restrict__ rs,int* __restrict__ tokE,float* __restrict__ tokW){
  int t=blockIdx.x, tid=threadIdx.x;
  float a[8]={0,0,0,0,0,0,0,0};
  const float* xr=x+(long)t*1024;
  for(int i=tid;i<1024;i+=128){
    float xv=xr[i]; const float* wr=Wg+i*8;
    #pragma unroll
    for(int e=0;e<8;e++) a[e]+=xv*wr[e];
  }
  __shared__ float sm[128][8];
  #pragma unroll
  for(int e=0;e<8;e++) sm[tid][e]=a[e];
  __syncthreads();
  for(int off=64;off;off>>=1){
    if(tid<off){
      #pragma unroll
      for(int e=0;e<8;e++) sm[tid][e]+=sm[tid+off][e];
    }
    __syncthreads();
  }
  if(tid==0){
    float s[8], sc=rs[0];
    #pragma unroll
    for(int e=0;e<8;e++) s[e]=sc/(1.f+expf(-sm[0][e]));
    int i0=0;
    #pragma unroll
    for(int e=1;e<8;e++) if(s[e]>s[i0]) i0=e;
    int i1=-1;
    #pragma unroll
    for(int e=0;e<8;e++){ if(e==i0)continue; if(i1<0||s[e]>s[i1]) i1=e; }
    float sum=s[i0]+s[i1];
    tokE[2*t]=i0; tokE[2*t+1]=i1;
    tokW[2*t]=s[i0]/sum; tokW[2*t+1]=s[i1]/sum;
  }
}
__global__ void lists_k(const int* __restrict__ tokE,
                        int* __restrict__ list,int* __restrict__ cnt){
  int e=blockIdx.x, tid=threadIdx.x;   // 1024 threads
  __shared__ int s[1024]; __shared__ int base;
  if(tid==0) base=0;
  __syncthreads();
  for(int st=0;st<NT;st+=1024){
    int t=st+tid;
    int flag = (tokE[2*t]==e || tokE[2*t+1]==e) ? 1 : 0;
    s[tid]=flag; __syncthreads();
    for(int off=1;off<1024;off<<=1){
      int v=(tid>=off)?s[tid-off]:0; __syncthreads();
      s[tid]+=v; __syncthreads();
    }
    if(flag) list[e*NT+base+s[tid]-1]=t;
    __syncthreads();
    if(tid==0) base+=s[1023];
    __syncthreads();
  }
  if(tid==0) cnt[e]=base;
}
__global__ void poff_k(const int* __restrict__ cnt, int* __restrict__ poff){
  if(threadIdx.x==0){
    int a=0; poff[0]=0;
    for(int e=0;e<NE;e++){ a += (cnt[e]+127)&~127; poff[e+1]=a; }
  }
}
__global__ void fill_k(const int* __restrict__ cnt,const int* __restrict__ poff,
                       const int* __restrict__ list,const int* __restrict__ tokE,
                       int* __restrict__ rowTok,int* __restrict__ tokPos){
  int e=blockIdx.y;
  int i=blockIdx.x*256+threadIdx.x;
  int base=poff[e], n=cnt[e], pad=poff[e+1]-base;
  if(i<pad){
    if(i<n){
      int t=list[e*NT+i];
      rowTok[base+i]=t;
      if(tokE[2*t]==e) tokPos[2*t]=base+i; else tokPos[2*t+1]=base+i;
    } else rowTok[base+i]=-1;
  }
}
__global__ void combine_k(float* __restrict__ y, const __half* __restrict__ Z,
                          const int* __restrict__ tokPos, const float* __restrict__ tokW,
                          __half* __restrict__ yh){
  int t=blockIdx.x, tid=threadIdx.x;  // 128 threads
  int p0=tokPos[2*t], p1=tokPos[2*t+1];
  float w0=tokW[2*t], w1=tokW[2*t+1];
  const __half2* z0=(const __half2*)(Z+(long)p0*1024);
  const __half2* z1=(const __half2*)(Z+(long)p1*1024);
  float2* yp=(float2*)(y+(long)t*1024);
  __half2* yhp=(__half2*)(yh+(long)t*1024);
  for(int i=tid;i<512;i+=128){
    float2 yv=yp[i];
    float2 a=__half22float2(z0[i]), b=__half22float2(z1[i]);
    yv.x += w0*a.x + w1*b.x;
    yv.y += w0*a.y + w1*b.y;
    yp[i]=yv;
    yhp[i]=__floats2half2_rn(yv.x,yv.y);
  }
}
// s=8 attention. freqs = pos*rope_freq is ELEMENTWISE (both len 8):
// angle[j] = j * 10000^(-j/8), identical for every position.
__global__ void attn_k(const float* __restrict__ qlat,const float* __restrict__ kv,
                       __half* __restrict__ oh){
  int b=blockIdx.x, h=threadIdx.x>>5, lane=threadIdx.x&31;
  __shared__ float q[4][8][32],k[4][8][32],v[4][8][32],p[4][8][8],sc[4][8][8];
  #pragma unroll
  for(int s=0;s<8;s++){
    long t=(long)b*8+s;
    q[h][s][lane]=qlat[t*384+h*32+lane];
    k[h][s][lane]=kv[t*256+h*32+lane];
    v[h][s][lane]=kv[t*256+128+h*32+lane];
  }
  __syncwarp();
  if(lane<8){
    float ang=(float)lane*powf(10000.f,-(float)lane/8.f);
    float c=cosf(ang), sn=sinf(ang);
    #pragma unroll
    for(int s=0;s<8;s++){
      float x1=q[h][s][lane], x2=q[h][s][lane+8];
      q[h][s][lane]=x1*c-x2*sn; q[h][s][lane+8]=x1*sn+x2*c;
    }
  }
  __syncwarp();
  #pragma unroll
  for(int e=0;e<2;e++){
    int id=lane+e*32, qi=id>>3, ki=id&7;
    float s0=0.f;
    #pragma unroll
    for(int d=0;d<32;d++) s0+=q[h][qi][d]*k[h][ki][d];
    sc[h][qi][ki]=s0*0.17677669529663687f;
  }
  __syncwarp();
  if(lane<8){
    float m=-1e30f;
    #pragma unroll
    for(int j=0;j<8;j++) m=fmaxf(m,sc[h][lane][j]);
    float ex[8], su=0.f;
    #pragma unroll
    for(int j=0;j<8;j++){ ex[j]=expf(sc[h][lane][j]-m); su+=ex[j]; }
    float inv=1.f/su;
    #pragma unroll
    for(int j=0;j<8;j++) p[h][lane][j]=ex[j]*inv;
  }
  __syncwarp();
  #pragma unroll
  for(int qi=0;qi<8;qi++){
    float o=0.f;
    #pragma unroll
    for(int j=0;j<8;j++) o+=p[h][qi][j]*v[h][j][lane];
    oh[((long)b*8+qi)*128+h*32+lane]=__float2half(o);
  }
}
__global__ void value_k(const __half* __restrict__ ch,const float* __restrict__ Wv,
                        const float* __restrict__ bv,float* __restrict__ o){
  int t=blockIdx.x, tid=threadIdx.x;
  const __half2* cp=(const __half2*)(ch+(long)t*1024);
  const float2* wp=(const float2*)Wv;
  float s=0.f;
  for(int i=tid;i<512;i+=128){
    float2 c=__half22float2(cp[i]); float2 w=wp[i];
    s += c.x*w.x + c.y*w.y;
  }
  __shared__ float sm[128];
  sm[tid]=s; __syncthreads();
  for(int off=64;off;off>>=1){ if(tid<off) sm[tid]+=sm[tid+off]; __syncthreads(); }
  if(tid==0) o[t]=sm[0]+bv[0];
}

// ---------------- host launcher ----------------
extern "C" void kernel_launch(void* const* d_in, const int* in_sizes, int n_in,
                              void* d_out, int out_size){
  const float *x=(const float*)d_in[0], *Wg=(const float*)d_in[1], *W1=(const float*)d_in[2],
    *b1=(const float*)d_in[3], *W2=(const float*)d_in[4], *b2=(const float*)d_in[5],
    *Ws1=(const float*)d_in[6], *bs1=(const float*)d_in[7], *Ws2=(const float*)d_in[8],
    *bs2=(const float*)d_in[9], *rs=(const float*)d_in[10], *Wq=(const float*)d_in[11],
    *Wkv=(const float*)d_in[12], *Wku=(const float*)d_in[13], *Wvu=(const float*)d_in[14],
    *Wao=(const float*)d_in[15], *Wo=(const float*)d_in[16], *bo=(const float*)d_in[17],
    *Wv=(const float*)d_in[18], *bv=(const float*)d_in[19];
  float* out=(float*)d_out;
  #define GS(T,p,s) T* p; cudaGetSymbolAddress((void**)&p,s)
  GS(__half,xh,g_xh); GS(__half,W1h,g_W1h); GS(__half,W2h,g_W2h);
  GS(__half,Ws1h,g_Ws1h); GS(__half,Ws2h,g_Ws2h); GS(__half,Wqkvh,g_Wqkvh);
  GS(__half,Wkuvh,g_Wkuvh); GS(__half,Waoh,g_Waoh); GS(__half,Woh,g_Woh);
  GS(__half,hb,g_hb); GS(__half,zb,g_z); GS(float,y,g_y); GS(__half,yh,g_yh);
  GS(float,qlat,g_qlat); GS(__half,lath,g_lath); GS(float,kvb,g_kv);
  GS(__half,oh,g_oh); GS(__half,combh,g_combh);
  GS(int,tokE,g_tokE); GS(float,tokW,g_tokW); GS(int,lst,g_list);
  GS(int,rowTok,g_rowTok); GS(int,tokPos,g_tokPos); GS(int,cnt,g_cnt); GS(int,poff,g_poff);
  #undef GS

  cudaFuncSetAttribute(hm_gemm<0,false,false>, cudaFuncAttributeMaxDynamicSharedMemorySize, HM_SMEM);
  cudaFuncSetAttribute(hm_gemm<1,false,false>, cudaFuncAttributeMaxDynamicSharedMemorySize, HM_SMEM);
  cudaFuncSetAttribute(hm_gemm<1,true ,true >, cudaFuncAttributeMaxDynamicSharedMemorySize, HM_SMEM);
  cudaFuncSetAttribute(hm_gemm<4,false,true >, cudaFuncAttributeMaxDynamicSharedMemorySize, HM_SMEM);
  cudaFuncSetAttribute(hm_gemm<3,false,false>, cudaFuncAttributeMaxDynamicSharedMemorySize, HM_SMEM);

  dim3 tb(32,8);
  f2h4_k<<<2048,256>>>((const float4*)x,(uint2*)xh,NT*256);
  t_f2h_k<<<dim3(32,32,NE),tb>>>(W1,W1h,1024,1024);
  t_f2h_k<<<dim3(32,32,NE),tb>>>(W2,W2h,1024,1024);
  t_f2h_k<<<dim3(32,32),tb>>>(Ws1,Ws1h,1024,1024);
  t_f2h_k<<<dim3(32,32),tb>>>(Ws2,Ws2h,1024,1024);
  t_f2h_k<<<dim3(32,32),tb>>>(Wo,Woh,1024,1024);
  t_f2h_k<<<dim3(32,4),tb>>>(Wao,Waoh,128,1024);
  t_f2h_k<<<dim3(4,32),tb>>>(Wq,Wqkvh,1024,128);
  t_f2h_k<<<dim3(8,32),tb>>>(Wkv,Wqkvh+128*1024,1024,256);
  t_f2h_k<<<dim3(4,8),tb>>>(Wku,Wkuvh,256,128);
  t_f2h_k<<<dim3(4,8),tb>>>(Wvu,Wkuvh+128*256,256,128);
  gate_k<<<NT,128>>>(x,Wg,rs,tokE,tokW);
  lists_k<<<NE,1024>>>(tokE,lst,cnt);
  poff_k<<<1,32>>>(cnt,poff);
  fill_k<<<dim3(64,NE),256>>>(cnt,poff,lst,tokE,rowTok,tokPos);

  dim3 gFull(8,128);
  // shared FFN
  hm_gemm<1,false,false><<<gFull,256,HM_SMEM>>>(xh,Ws1h,NT,nullptr,1024,1024,bs1,nullptr,hb,nullptr,nullptr,nullptr);
  hm_gemm<0,false,false><<<gFull,256,HM_SMEM>>>(hb,Ws2h,NT,nullptr,1024,1024,bs2,y,nullptr,nullptr,nullptr,nullptr);
  // experts: two fused launches over all 8 experts (padded row segments)
  dim3 gExp(8,PADROWS/128);
  hm_gemm<1,true ,true ><<<gExp,256,HM_SMEM>>>(xh,W1h,0,poff+NE,1024,1024,b1,nullptr,hb,nullptr,rowTok,poff);
  hm_gemm<4,false,true ><<<gExp,256,HM_SMEM>>>(hb,W2h,0,poff+NE,1024,1024,b2,nullptr,zb,nullptr,nullptr,poff);
  combine_k<<<NT,128>>>(y,zb,tokPos,tokW,yh);
  // MLA projections
  hm_gemm<0,false,false><<<dim3(3,128),256,HM_SMEM>>>(yh,Wqkvh,NT,nullptr,384,1024,nullptr,qlat,nullptr,nullptr,nullptr,nullptr);
  lat_k<<<2048,256>>>(qlat,lath);
  hm_gemm<0,false,false><<<dim3(2,128),256,HM_SMEM>>>(lath,Wkuvh,NT,nullptr,256,256,nullptr,kvb,nullptr,nullptr,nullptr,nullptr);
  attn_k<<<2048,128>>>(qlat,kvb,oh);
  hm_gemm<3,false,false><<<gFull,256,HM_SMEM>>>(oh,Waoh,NT,nullptr,1024,128,nullptr,nullptr,combh,y,nullptr,nullptr);
  // decision + value
  hm_gemm<0,false,false><<<gFull,256,HM_SMEM>>>(combh,Woh,NT,nullptr,1024,1024,bo,out,nullptr,nullptr,nullptr,nullptr);
  value_k<<<NT,128>>>(combh,Wv,bv,out+(long)NT*1024);
}

// round 7
// speedup vs baseline: 1.7568x; 1.0881x over previous
#include <cuda_runtime.h>
#include <cuda_fp16.h>
#include <math.h>
#include <stdint.h>

#define NT 16384
#define NE 8
#define PADROWS 50176      // 16384 shared + 2*16384 experts + 8*128 pad margin

// ---------------- scratch ----------------
__device__ __half g_xh   [NT*1024];
__device__ __half g_W1c  [9*1024*1024];   // slot0 = Ws1, slots 1-8 = W1[e]; [K][N] k-major
__device__ __half g_W2c  [9*1024*1024];   // slot0 = Ws2, slots 1-8 = W2[e]
__device__ __half g_Wqkvh[1024*384];      // [K=1024][N=384]: cols 0-127 Wq, 128-383 Wkv
__device__ __half g_Wkuvh[256*256];       // [K=256][N=256]: cols 0-127 Wku, 128-255 Wvu
__device__ __half g_Waoh [128*1024];      // [K=128][N=1024]
__device__ __half g_Woh  [1024*1024];     // [K=1024][N=1024]
__device__ __half g_hb   [PADROWS*1024];
__device__ __half g_z    [PADROWS*1024];
__device__ float  g_y    [NT*1024];
__device__ __half g_yh   [NT*1024];
__device__ float  g_qlat [NT*384];
__device__ __half g_lath [NT*256];
__device__ float  g_kv   [NT*256];
__device__ __half g_oh   [NT*128];
__device__ __half g_combh[NT*1024];
__device__ int    g_tokE [NT*2];
__device__ float  g_tokW [NT*2];
__device__ int    g_list [NE*NT];
__device__ int    g_rowTok[PADROWS];
__device__ int    g_tokPos[NT*2];
__device__ int    g_cnt  [NE];

// ---------------- PTX helpers ----------------
__device__ __forceinline__ void cp16s(uint32_t s, const void* g, bool p){
  int n = p ? 16 : 0;
  asm volatile("cp.async.cg.shared.global [%0],[%1],16,%2;\n"::"r"(s),"l"(g),"r"(n));
}
#define CP_COMMIT() asm volatile("cp.async.commit_group;\n")
__device__ __forceinline__ void ldsm4(uint32_t& r0,uint32_t& r1,uint32_t& r2,uint32_t& r3,uint32_t a){
  asm volatile("ldmatrix.sync.aligned.m8n8.x4.shared.b16 {%0,%1,%2,%3}, [%4];\n"
    : "=r"(r0),"=r"(r1),"=r"(r2),"=r"(r3) : "r"(a));
}
__device__ __forceinline__ void ldsm4t(uint32_t& r0,uint32_t& r1,uint32_t& r2,uint32_t& r3,uint32_t a){
  asm volatile("ldmatrix.sync.aligned.m8n8.x4.trans.shared.b16 {%0,%1,%2,%3}, [%4];\n"
    : "=r"(r0),"=r"(r1),"=r"(r2),"=r"(r3) : "r"(a));
}
__device__ __forceinline__ void mma16816(float c[4], const uint32_t a[4], const uint32_t b[2]){
  asm volatile("mma.sync.aligned.m16n8k16.row.col.f32.f16.f16.f32 "
    "{%0,%1,%2,%3},{%4,%5,%6,%7},{%8,%9},{%0,%1,%2,%3};\n"
    :"+f"(c[0]),"+f"(c[1]),"+f"(c[2]),"+f"(c[3])
    :"r"(a[0]),"r"(a[1]),"r"(a[2]),"r"(a[3]),"r"(b[0]),"r"(b[1]));
}

// ---------------- HMMA GEMM ----------------
// C[M,Ntot] = A[M,K] * B[K,Ntot]  (B k-major, ldmatrix.trans). fp16 in / fp32 acc.
// Tile 128x128x32, 4-stage cp.async.
// MODE 0: outF=acc(+bias). 1: outH=gelu(acc+bias). 3: outH=half(acc+addF). 4: outH=half(acc+bias).
// GATHER: A row = rowTok[r] (negative => zero-filled).
// EXPSEG: 9 segments from cnt[]: seg0 rows [0,16384) -> B slot 0 + biasS;
//         seg e rows (padded expert region) -> slot e + biasE+(e-1)*1024.
#define STAGES 4
#define RSTRA 40
#define RSTRB 136
#define ASTG (128*RSTRA)
#define BSTG (32*RSTRB)
#define HM_SMEM (STAGES*(ASTG+BSTG)*2)

template<int MODE,bool GATHER,bool EXPSEG>
__global__ void __launch_bounds__(256,2) hm_gemm(
  const __half* __restrict__ A, const __half* __restrict__ B,
  int M, int Ntot, int K,
  const float* __restrict__ biasS, const float* __restrict__ biasE,
  float* __restrict__ outF, __half* __restrict__ outH,
  const float* __restrict__ addF, const int* __restrict__ rowTok,
  const int* __restrict__ cnt)
{
  const int bM = blockIdx.y*128;
  const float* bias = biasS;
  if (EXPSEG){
    int Mtot = 16384, seg = 0;
    #pragma unroll
    for (int k=0;k<NE;k++){
      int pad = (cnt[k]+127)&~127;
      if (bM >= Mtot) seg = k+1;
      Mtot += pad;
    }
    if (bM >= Mtot) return;
    M = Mtot;
    B += (long)seg<<20;
    bias = (seg==0) ? biasS : (biasE ? biasE+(seg-1)*1024 : nullptr);
  } else {
    if (bM >= M) return;
  }
  const int bN = blockIdx.x*128;

  extern __shared__ __half sm[];
  const uint32_t AsmU = (uint32_t)__cvta_generic_to_shared(sm);
  const uint32_t BsmU = AsmU + STAGES*ASTG*2;

  const int tid=threadIdx.x, lane=tid&31, warp=tid>>5;
  const int m0=(warp>>2)*64, n0=(warp&3)*32;

  const __half* aptr[2]; uint32_t aoff[2]; bool avld[2];
  #pragma unroll
  for(int s=0;s<2;s++){
    int c=tid+256*s, row=c>>2, col=(c&3)*8;
    int rg=bM+row; bool v=rg<M;
    long rowIdx;
    if (GATHER){ int gi = v ? rowTok[rg] : 0; if (gi<0){ v=false; gi=0; } rowIdx = gi; }
    else rowIdx = v ? (long)rg : 0;
    aptr[s]=A+rowIdx*(long)K+col; aoff[s]=(uint32_t)(row*RSTRA+col)*2; avld[s]=v;
  }
  const __half* bptr[2]; uint32_t boff[2];
  #pragma unroll
  for(int s=0;s<2;s++){
    int c=tid+256*s, row=c>>4, col=(c&15)*8;
    bptr[s]=B+(long)row*Ntot+bN+col; boff[s]=(uint32_t)(row*RSTRB+col)*2;
  }
  auto load_stage=[&](int st_){
    int buf=st_%STAGES;
    uint32_t ab=AsmU+buf*ASTG*2, bb=BsmU+buf*BSTG*2;
    #pragma unroll
    for(int s=0;s<2;s++) cp16s(ab+aoff[s], aptr[s]+st_*32, avld[s]);
    #pragma unroll
    for(int s=0;s<2;s++) cp16s(bb+boff[s], bptr[s]+(long)st_*32*Ntot, true);
    CP_COMMIT();
  };

  float acc[4][4][4];
  #pragma unroll
  for(int i=0;i<4;i++)
    #pragma unroll
    for(int j=0;j<4;j++){ acc[i][j][0]=0.f;acc[i][j][1]=0.f;acc[i][j][2]=0.f;acc[i][j][3]=0.f; }

  const int KT=K>>5;
  #pragma unroll
  for(int s=0;s<3;s++){ if(s<KT) load_stage(s); else CP_COMMIT(); }

  const int a_r = ((lane>>3)&1)*8 + (lane&7);
  const int a_k = (lane>>4)*8;
  const int b_row = lane&15;
  const int b_cg  = (lane>>4)*8;

  for(int st=0; st<KT; st++){
    asm volatile("cp.async.wait_group 2;\n");
    __syncthreads();
    if (st+3<KT) load_stage(st+3);
    const int buf=st%STAGES;
    const uint32_t ab=AsmU+buf*ASTG*2, bb=BsmU+buf*BSTG*2;
    #pragma unroll
    for(int kk=0;kk<2;kk++){
      const int k16=kk*16;
      uint32_t af[4][4], bf[4][2];
      #pragma unroll
      for(int mi=0;mi<4;mi++){
        uint32_t addr = ab + (uint32_t)((m0+mi*16+a_r)*RSTRA + k16 + a_k)*2;
        ldsm4(af[mi][0],af[mi][1],af[mi][2],af[mi][3],addr);
      }
      #pragma unroll
      for(int nb=0;nb<2;nb++){
        uint32_t addr = bb + (uint32_t)((k16+b_row)*RSTRB + n0 + nb*16 + b_cg)*2;
        ldsm4t(bf[nb*2][0],bf[nb*2][1],bf[nb*2+1][0],bf[nb*2+1][1],addr);
      }
      #pragma unroll
      for(int mi=0;mi<4;mi++)
        #pragma unroll
        for(int ni=0;ni<4;ni++) mma16816(acc[mi][ni],af[mi],bf[ni]);
    }
  }

  const int lr=lane>>2, lc=(lane&3)*2;
  #pragma unroll
  for(int mi=0;mi<4;mi++)
    #pragma unroll
    for(int ni=0;ni<4;ni++){
      int rA=bM+m0+mi*16+lr, c=bN+n0+ni*8+lc;
      #pragma unroll
      for(int h=0;h<2;h++){
        int r=rA+h*8;
        if(r>=M) continue;
        float v0=acc[mi][ni][h*2+0], v1=acc[mi][ni][h*2+1];
        if(MODE==0){
          if(bias){ v0+=bias[c]; v1+=bias[c+1]; }
          float2 f; f.x=v0; f.y=v1;
          *(float2*)&outF[(long)r*Ntot+c]=f;
        } else if(MODE==1){
          if(bias){ v0+=bias[c]; v1+=bias[c+1]; }
          v0=0.5f*v0*(1.0f+erff(v0*0.70710678118654752f));
          v1=0.5f*v1*(1.0f+erff(v1*0.70710678118654752f));
          *(__half2*)&outH[(long)r*Ntot+c]=__floats2half2_rn(v0,v1);
        } else if(MODE==3){
          v0+=addF[(long)r*Ntot+c]; v1+=addF[(long)r*Ntot+c+1];
          *(__half2*)&outH[(long)r*Ntot+c]=__floats2half2_rn(v0,v1);
        } else {
          if(bias){ v0+=bias[c]; v1+=bias[c+1]; }
          *(__half2*)&outH[(long)r*Ntot+c]=__floats2half2_rn(v0,v1);
        }
      }
    }
}

// ---------------- prep / small kernels ----------------
__global__ void f2h4_k(const float4* __restrict__ s, uint2* __restrict__ d, int n4){
  int i=blockIdx.x*blockDim.x+threadIdx.x, st=gridDim.x*blockDim.x;
  for(;i<n4;i+=st){
    float4 v=s[i];
    __half2 h0=__floats2half2_rn(v.x,v.y), h1=__floats2half2_rn(v.z,v.w);
    uint2 u; u.x=*(uint32_t*)&h0; u.y=*(uint32_t*)&h1;
    d[i]=u;
  }
}
__global__ void wcat9_k(const float4* __restrict__ S, const float4* __restrict__ E,
                        uint2* __restrict__ d){
  int i=blockIdx.x*blockDim.x+threadIdx.x, st=gridDim.x*blockDim.x;
  const int n4=9*262144;
  for(;i<n4;i+=st){
    float4 v = (i<262144) ? S[i] : E[i-262144];
    __half2 h0=__floats2half2_rn(v.x,v.y), h1=__floats2half2_rn(v.z,v.w);
    uint2 u; u.x=*(uint32_t*)&h0; u.y=*(uint32_t*)&h1;
    d[i]=u;
  }
}
__global__ void ccat_k(const float* __restrict__ A, int C0,
                       const float* __restrict__ Bm, int C1,
                       __half* __restrict__ d, int K){
  int Ct=C0+C1, n2=K*Ct/2;
  for(int i=blockIdx.x*blockDim.x+threadIdx.x;i<n2;i+=gridDim.x*blockDim.x){
    int r=i/(Ct/2), c=(i%(Ct/2))*2;
    float2 v;
    if (c<C0) v=*(const float2*)&A[(long)r*C0+c];
    else      v=*(const float2*)&Bm[(long)r*C1+c-C0];
    *(__half2*)&d[(long)r*Ct+c]=__floats2half2_rn(v.x,v.y);
  }
}
__global__ void lat_k(const float* __restrict__ qlat,__half* __restrict__ d){
  int i=blockIdx.x*blockDim.x+threadIdx.x, st=gridDim.x*blockDim.x;
  for(;i<NT*128;i+=st){
    int t=i>>7, c=(i&127)*2;
    float2 v=*(const float2*)&qlat[(long)t*384+128+c];
    *(__half2*)&d[(long)t*256+c]=__floats2half2_rn(v.x,v.y);
  }
}
__global__ void gate_k(const float* __restrict__ x,const float* __restrict__ Wg,
                       const float* __restrict__ rs,int* __restrict__ tokE,float* __restrict__ tokW){
  int t=blockIdx.x, tid=threadIdx.x;
  float a[8]={0,0,0,0,0,0,0,0};
  const float* xr=x+(long)t*1024;
  for(int i=tid;i<1024;i+=128){
    float xv=xr[i]; const float* wr=Wg+i*8;
    #pragma unroll
    for(int e=0;e<8;e++) a[e]+=xv*wr[e];
  }
  __shared__ float sm[128][8];
  #pragma unroll
  for(int e=0;e<8;e++) sm[tid][e]=a[e];
  __syncthreads();
  for(int off=64;off;off>>=1){
    if(tid<off){
      #pragma unroll
      for(int e=0;e<8;e++) sm[tid][e]+=sm[tid+off][e];
    }
    __syncthreads();
  }
  if(tid==0){
    float s[8], sc=rs[0];
    #pragma unroll
    for(int e=0;e<8;e++) s[e]=sc/(1.f+expf(-sm[0][e]));
    int i0=0;
    #pragma unroll
    for(int e=1;e<8;e++) if(s[e]>s[i0]) i0=e;
    int i1=-1;
    #pragma unroll
    for(int e=0;e<8;e++){ if(e==i0)continue; if(i1<0||s[e]>s[i1]) i1=e; }
    float sum=s[i0]+s[i1];
    tokE[2*t]=i0; tokE[2*t+1]=i1;
    tokW[2*t]=s[i0]/sum; tokW[2*t+1]=s[i1]/sum;
  }
}
__global__ void lists_k(const int* __restrict__ tokE,
                        int* __restrict__ list,int* __restrict__ cnt){
  int e=blockIdx.x, tid=threadIdx.x;
  __shared__ int s[1024]; __shared__ int base;
  if(tid==0) base=0;
  __syncthreads();
  for(int st=0;st<NT;st+=1024){
    int t=st+tid;
    int flag = (tokE[2*t]==e || tokE[2*t+1]==e) ? 1 : 0;
    s[tid]=flag; __syncthreads();
    for(int off=1;off<1024;off<<=1){
      int v=(tid>=off)?s[tid-off]:0; __syncthreads();
      s[tid]+=v; __syncthreads();
    }
    if(flag) list[e*NT+base+s[tid]-1]=t;
    __syncthreads();
    if(tid==0) base+=s[1023];
    __syncthreads();
  }
  if(tid==0) cnt[e]=base;
}
__global__ void fill_k(const int* __restrict__ cnt,const int* __restrict__ list,
                       const int* __restrict__ tokE,
                       int* __restrict__ rowTok,int* __restrict__ tokPos){
  int e=blockIdx.y;
  int i=blockIdx.x*256+threadIdx.x;
  if (e==0){ if(i<16384) rowTok[i]=i; return; }
  int ex=e-1;
  int base=16384;
  for(int k=0;k<ex;k++) base += (cnt[k]+127)&~127;
  int n=cnt[ex], pad=(n+127)&~127;
  if(i<pad){
    if(i<n){
      int t=list[ex*NT+i];
      rowTok[base+i]=t;
      if(tokE[2*t]==ex) tokPos[2*t]=base+i; else tokPos[2*t+1]=base+i;
    } else rowTok[base+i]=-1;
  }
}
__global__ void combine_k(float* __restrict__ y, const __half* __restrict__ Z,
                          const int* __restrict__ tokPos, const float* __restrict__ tokW,
                          __half* __restrict__ yh){
  int t=blockIdx.x, tid=threadIdx.x;
  int p0=tokPos[2*t], p1=tokPos[2*t+1];
  float w0=tokW[2*t], w1=tokW[2*t+1];
  const __half2* zs=(const __half2*)(Z+(long)t*1024);
  const __half2* z0=(const __half2*)(Z+(long)p0*1024);
  const __half2* z1=(const __half2*)(Z+(long)p1*1024);
  float2* yp=(float2*)(y+(long)t*1024);
  __half2* yhp=(__half2*)(yh+(long)t*1024);
  for(int i=tid;i<512;i+=128){
    float2 s=__half22float2(zs[i]);
    float2 a=__half22float2(z0[i]), b=__half22float2(z1[i]);
    float2 yv;
    yv.x = s.x + w0*a.x + w1*b.x;
    yv.y = s.y + w0*a.y + w1*b.y;
    yp[i]=yv;
    yhp[i]=__floats2half2_rn(yv.x,yv.y);
  }
}
// s=8 attention. freqs = pos*rope_freq is ELEMENTWISE (both len 8):
// angle[j] = j * 10000^(-j/8), identical for every position.
__global__ void attn_k(const float* __restrict__ qlat,const float* __restrict__ kv,
                       __half* __restrict__ oh){
  int b=blockIdx.x, h=threadIdx.x>>5, lane=threadIdx.x&31;
  __shared__ float q[4][8][32],k[4][8][32],v[4][8][32],p[4][8][8],sc[4][8][8];
  #pragma unroll
  for(int s=0;s<8;s++){
    long t=(long)b*8+s;
    q[h][s][lane]=qlat[t*384+h*32+lane];
    k[h][s][lane]=kv[t*256+h*32+lane];
    v[h][s][lane]=kv[t*256+128+h*32+lane];
  }
  __syncwarp();
  if(lane<8){
    float ang=(float)lane*powf(10000.f,-(float)lane/8.f);
    float c=cosf(ang), sn=sinf(ang);
    #pragma unroll
    for(int s=0;s<8;s++){
      float x1=q[h][s][lane], x2=q[h][s][lane+8];
      q[h][s][lane]=x1*c-x2*sn; q[h][s][lane+8]=x1*sn+x2*c;
    }
  }
  __syncwarp();
  #pragma unroll
  for(int e=0;e<2;e++){
    int id=lane+e*32, qi=id>>3, ki=id&7;
    float s0=0.f;
    #pragma unroll
    for(int d=0;d<32;d++) s0+=q[h][qi][d]*k[h][ki][d];
    sc[h][qi][ki]=s0*0.17677669529663687f;
  }
  __syncwarp();
  if(lane<8){
    float m=-1e30f;
    #pragma unroll
    for(int j=0;j<8;j++) m=fmaxf(m,sc[h][lane][j]);
    float ex[8], su=0.f;
    #pragma unroll
    for(int j=0;j<8;j++){ ex[j]=expf(sc[h][lane][j]-m); su+=ex[j]; }
    float inv=1.f/su;
    #pragma unroll
    for(int j=0;j<8;j++) p[h][lane][j]=ex[j]*inv;
  }
  __syncwarp();
  #pragma unroll
  for(int qi=0;qi<8;qi++){
    float o=0.f;
    #pragma unroll
    for(int j=0;j<8;j++) o+=p[h][qi][j]*v[h][j][lane];
    oh[((long)b*8+qi)*128+h*32+lane]=__float2half(o);
  }
}
__global__ void value_k(const __half* __restrict__ ch,const float* __restrict__ Wv,
                        const float* __restrict__ bv,float* __restrict__ o){
  int t=blockIdx.x, tid=threadIdx.x;
  const __half2* cp=(const __half2*)(ch+(long)t*1024);
  const float2* wp=(const float2*)Wv;
  float s=0.f;
  for(int i=tid;i<512;i+=128){
    float2 c=__half22float2(cp[i]); float2 w=wp[i];
    s += c.x*w.x + c.y*w.y;
  }
  __shared__ float sm[128];
  sm[tid]=s; __syncthreads();
  for(int off=64;off;off>>=1){ if(tid<off) sm[tid]+=sm[tid+off]; __syncthreads(); }
  if(tid==0) o[t]=sm[0]+bv[0];
}

// ---------------- host launcher ----------------
extern "C" void kernel_launch(void* const* d_in, const int* in_sizes, int n_in,
                              void* d_out, int out_size){
  const float *x=(const float*)d_in[0], *Wg=(const float*)d_in[1], *W1=(const float*)d_in[2],
    *b1=(const float*)d_in[3], *W2=(const float*)d_in[4], *b2=(const float*)d_in[5],
    *Ws1=(const float*)d_in[6], *bs1=(const float*)d_in[7], *Ws2=(const float*)d_in[8],
    *bs2=(const float*)d_in[9], *rs=(const float*)d_in[10], *Wq=(const float*)d_in[11],
    *Wkv=(const float*)d_in[12], *Wku=(const float*)d_in[13], *Wvu=(const float*)d_in[14],
    *Wao=(const float*)d_in[15], *Wo=(const float*)d_in[16], *bo=(const float*)d_in[17],
    *Wv=(const float*)d_in[18], *bv=(const float*)d_in[19];
  float* out=(float*)d_out;
  #define GS(T,p,s) T* p; cudaGetSymbolAddress((void**)&p,s)
  GS(__half,xh,g_xh); GS(__half,W1c,g_W1c); GS(__half,W2c,g_W2c);
  GS(__half,Wqkvh,g_Wqkvh); GS(__half,Wkuvh,g_Wkuvh); GS(__half,Waoh,g_Waoh); GS(__half,Woh,g_Woh);
  GS(__half,hb,g_hb); GS(__half,zb,g_z); GS(float,y,g_y); GS(__half,yh,g_yh);
  GS(float,qlat,g_qlat); GS(__half,lath,g_lath); GS(float,kvb,g_kv);
  GS(__half,oh,g_oh); GS(__half,combh,g_combh);
  GS(int,tokE,g_tokE); GS(float,tokW,g_tokW); GS(int,lst,g_list);
  GS(int,rowTok,g_rowTok); GS(int,tokPos,g_tokPos); GS(int,cnt,g_cnt);
  #undef GS

  cudaFuncSetAttribute(hm_gemm<0,false,false>, cudaFuncAttributeMaxDynamicSharedMemorySize, HM_SMEM);
  cudaFuncSetAttribute(hm_gemm<1,true ,true >, cudaFuncAttributeMaxDynamicSharedMemorySize, HM_SMEM);
  cudaFuncSetAttribute(hm_gemm<4,false,true >, cudaFuncAttributeMaxDynamicSharedMemorySize, HM_SMEM);
  cudaFuncSetAttribute(hm_gemm<3,false,false>, cudaFuncAttributeMaxDynamicSharedMemorySize, HM_SMEM);

  // launch order chosen so launch #5 (0-based) is the fused FFN1 GEMM (ncu -s 5 -c 1)
  f2h4_k<<<2048,256>>>((const float4*)x,(uint2*)xh,NT*256);                 // 0
  wcat9_k<<<4096,256>>>((const float4*)Ws1,(const float4*)W1,(uint2*)W1c);  // 1
  gate_k<<<NT,128>>>(x,Wg,rs,tokE,tokW);                                    // 2
  lists_k<<<NE,1024>>>(tokE,lst,cnt);                                       // 3
  fill_k<<<dim3(68,9),256>>>(cnt,lst,tokE,rowTok,tokPos);                   // 4

  dim3 gFFN(8,PADROWS/128);
  hm_gemm<1,true ,true ><<<gFFN,256,HM_SMEM>>>(xh,W1c,0,1024,1024,bs1,b1,   // 5 <- profiled
      nullptr,hb,nullptr,rowTok,cnt);
  wcat9_k<<<4096,256>>>((const float4*)Ws2,(const float4*)W2,(uint2*)W2c);  // 6
  hm_gemm<4,false,true ><<<gFFN,256,HM_SMEM>>>(hb,W2c,0,1024,1024,bs2,b2,   // 7
      nullptr,zb,nullptr,nullptr,cnt);
  combine_k<<<NT,128>>>(y,zb,tokPos,tokW,yh);                               // 8

  ccat_k<<<768,256>>>(Wq,128,Wkv,256,Wqkvh,1024);                           // 9
  hm_gemm<0,false,false><<<dim3(3,128),256,HM_SMEM>>>(yh,Wqkvh,NT,384,1024, // 10
      nullptr,nullptr,qlat,nullptr,nullptr,nullptr,nullptr);
  lat_k<<<2048,256>>>(qlat,lath);                                           // 11
  ccat_k<<<128,256>>>(Wku,128,Wvu,128,Wkuvh,256);                           // 12
  hm_gemm<0,false,false><<<dim3(2,128),256,HM_SMEM>>>(lath,Wkuvh,NT,256,256,// 13
      nullptr,nullptr,kvb,nullptr,nullptr,nullptr,nullptr);
  attn_k<<<2048,128>>>(qlat,kvb,oh);                                        // 14
  f2h4_k<<<256,256>>>((const float4*)Wao,(uint2*)Waoh,128*256);             // 15
  hm_gemm<3,false,false><<<dim3(8,128),256,HM_SMEM>>>(oh,Waoh,NT,1024,128,  // 16
      nullptr,nullptr,nullptr,combh,y,nullptr,nullptr);
  f2h4_k<<<1024,256>>>((const float4*)Wo,(uint2*)Woh,256*1024);             // 17
  hm_gemm<0,false,false><<<dim3(8,128),256,HM_SMEM>>>(combh,Woh,NT,1024,1024,// 18
      bo,nullptr,out,nullptr,nullptr,nullptr,nullptr);
  value_k<<<NT,128>>>(combh,Wv,bv,out+(long)NT*1024);                       // 19
}

// round 9
// speedup vs baseline: 1.7625x; 1.0033x over previous
#include <cuda_runtime.h>
#include <cuda_fp16.h>
#include <math.h>
#include <stdint.h>

#define NT 16384
#define NE 8
#define CAP 6144                        // fixed per-expert segment capacity (48 tiles)
#define PADROWS (16384 + NE*CAP)        // 65536

// ---------------- scratch ----------------
__device__ __half g_xh   [NT*1024];
__device__ __half g_W1c  [9*1024*1024];   // slot0 = Ws1, slots 1-8 = W1[e]; [K][N] k-major
__device__ __half g_W2c  [9*1024*1024];   // slot0 = Ws2, slots 1-8 = W2[e]
__device__ __half g_Wqkvh[1024*384];      // [K=1024][N=384]: cols 0-127 Wq, 128-383 Wkv
__device__ __half g_Wkuvh[256*256];       // [K=256][N=256]: cols 0-127 Wku, 128-255 Wvu
__device__ __half g_Waoh [128*1024];      // [K=128][N=1024]
__device__ __half g_Woh  [1024*1024];     // [K=1024][N=1024]
__device__ __half g_hb   [PADROWS*1024];
__device__ __half g_z    [PADROWS*1024];
__device__ __half g_yh   [NT*1024];
__device__ float  g_qbuf [NT*128];
__device__ __half g_lath [NT*256];
__device__ float  g_kv   [NT*256];
__device__ __half g_oh   [NT*128];
__device__ __half g_combh[NT*1024];
__device__ int    g_tokE [NT*2];
__device__ float  g_tokW [NT*2];
__device__ int    g_rowTok[PADROWS];
__device__ int    g_tokPos[NT*2];
__device__ int    g_cnt  [NE];

// ---------------- PTX helpers ----------------
__device__ __forceinline__ void cp16s(uint32_t s, const void* g, bool p){
  int n = p ? 16 : 0;
  asm volatile("cp.async.cg.shared.global [%0],[%1],16,%2;\n"::"r"(s),"l"(g),"r"(n));
}
#define CP_COMMIT() asm volatile("cp.async.commit_group;\n")
__device__ __forceinline__ void ldsm4(uint32_t& r0,uint32_t& r1,uint32_t& r2,uint32_t& r3,uint32_t a){
  asm volatile("ldmatrix.sync.aligned.m8n8.x4.shared.b16 {%0,%1,%2,%3}, [%4];\n"
    : "=r"(r0),"=r"(r1),"=r"(r2),"=r"(r3) : "r"(a));
}
__device__ __forceinline__ void ldsm4t(uint32_t& r0,uint32_t& r1,uint32_t& r2,uint32_t& r3,uint32_t a){
  asm volatile("ldmatrix.sync.aligned.m8n8.x4.trans.shared.b16 {%0,%1,%2,%3}, [%4];\n"
    : "=r"(r0),"=r"(r1),"=r"(r2),"=r"(r3) : "r"(a));
}
__device__ __forceinline__ void mma16816(float c[4], const uint32_t a[4], const uint32_t b[2]){
  asm volatile("mma.sync.aligned.m16n8k16.row.col.f32.f16.f16.f32 "
    "{%0,%1,%2,%3},{%4,%5,%6,%7},{%8,%9},{%0,%1,%2,%3};\n"
    :"+f"(c[0]),"+f"(c[1]),"+f"(c[2]),"+f"(c[3])
    :"r"(a[0]),"r"(a[1]),"r"(a[2]),"r"(a[3]),"r"(b[0]),"r"(b[1]));
}

// ---------------- HMMA GEMM ----------------
// C[M,Ntot] = A[M,K] * B[K,Ntot]  (B k-major, ldmatrix.trans). fp16 in / fp32 acc.
// Tile 128x128x32, 4-stage cp.async.
// MODE 0: outF=acc(+bias). 1: outH=gelu(acc+bias). 3: outH=half(acc+addH). 4: outH=half(acc+bias).
// MODE 5 (qkv): bN==0 tile -> outF fp32 stride 128; bN>=128 -> outH half stride 256 at col-128.
// GATHER: A row = rowTok[r] (negative => zero-filled).
// EXPSEG: seg0 rows [0,16384) -> B slot 0 + biasS; expert e at fixed base 16384+e*CAP,
//         valid tiles bounded by pad(cnt[e]); B slot e+1, bias biasE+e*1024.
#define STAGES 4
#define RSTRA 40
#define RSTRB 136
#define ASTG (128*RSTRA)
#define BSTG (32*RSTRB)
#define HM_SMEM (STAGES*(ASTG+BSTG)*2)

template<int MODE,bool GATHER,bool EXPSEG>
__global__ void __launch_bounds__(256,2) hm_gemm(
  const __half* __restrict__ A, const __half* __restrict__ B,
  int M, int Ntot, int K,
  const float* __restrict__ biasS, const float* __restrict__ biasE,
  float* __restrict__ outF, __half* __restrict__ outH,
  const __half* __restrict__ addH, const int* __restrict__ rowTok,
  const int* __restrict__ cnt)
{
  const int bM = blockIdx.y*128;
  const float* bias = biasS;
  if (EXPSEG){
    int seg;
    if (bM < 16384) seg = 0;
    else {
      int s = (bM - 16384) / CAP;
      int local = (bM - 16384) - s*CAP;
      int padc = (cnt[s]+127)&~127;
      if (padc > CAP) padc = CAP;
      if (local >= padc) return;
      seg = s+1;
    }
    B += (long)seg<<20;
    bias = (seg==0) ? biasS : (biasE ? biasE+(seg-1)*1024 : nullptr);
    M = PADROWS;
  } else {
    if (bM >= M) return;
  }
  const int bN = blockIdx.x*128;

  extern __shared__ __half sm[];
  const uint32_t AsmU = (uint32_t)__cvta_generic_to_shared(sm);
  const uint32_t BsmU = AsmU + STAGES*ASTG*2;

  const int tid=threadIdx.x, lane=tid&31, warp=tid>>5;
  const int m0=(warp>>2)*64, n0=(warp&3)*32;

  const __half* aptr[2]; uint32_t aoff[2]; bool avld[2];
  #pragma unroll
  for(int s=0;s<2;s++){
    int c=tid+256*s, row=c>>2, col=(c&3)*8;
    int rg=bM+row; bool v=rg<M;
    long rowIdx;
    if (GATHER){ int gi = v ? rowTok[rg] : 0; if (gi<0){ v=false; gi=0; } rowIdx = gi; }
    else rowIdx = v ? (long)rg : 0;
    aptr[s]=A+rowIdx*(long)K+col; aoff[s]=(uint32_t)(row*RSTRA+col)*2; avld[s]=v;
  }
  const __half* bptr[2]; uint32_t boff[2];
  #pragma unroll
  for(int s=0;s<2;s++){
    int c=tid+256*s, row=c>>4, col=(c&15)*8;
    bptr[s]=B+(long)row*Ntot+bN+col; boff[s]=(uint32_t)(row*RSTRB+col)*2;
  }
  auto load_stage=[&](int st_){
    int buf=st_%STAGES;
    uint32_t ab=AsmU+buf*ASTG*2, bb=BsmU+buf*BSTG*2;
    #pragma unroll
    for(int s=0;s<2;s++) cp16s(ab+aoff[s], aptr[s]+st_*32, avld[s]);
    #pragma unroll
    for(int s=0;s<2;s++) cp16s(bb+boff[s], bptr[s]+(long)st_*32*Ntot, true);
    CP_COMMIT();
  };

  float acc[4][4][4];
  #pragma unroll
  for(int i=0;i<4;i++)
    #pragma unroll
    for(int j=0;j<4;j++){ acc[i][j][0]=0.f;acc[i][j][1]=0.f;acc[i][j][2]=0.f;acc[i][j][3]=0.f; }

  const int KT=K>>5;
  #pragma unroll
  for(int s=0;s<3;s++){ if(s<KT) load_stage(s); else CP_COMMIT(); }

  const int a_r = ((lane>>3)&1)*8 + (lane&7);
  const int a_k = (lane>>4)*8;
  const int b_row = lane&15;
  const int b_cg  = (lane>>4)*8;

  for(int st=0; st<KT; st++){
    asm volatile("cp.async.wait_group 2;\n");
    __syncthreads();
    if (st+3<KT) load_stage(st+3);
    const int buf=st%STAGES;
    const uint32_t ab=AsmU+buf*ASTG*2, bb=BsmU+buf*BSTG*2;
    #pragma unroll
    for(int kk=0;kk<2;kk++){
      const int k16=kk*16;
      uint32_t af[4][4], bf[4][2];
      #pragma unroll
      for(int mi=0;mi<4;mi++){
        uint32_t addr = ab + (uint32_t)((m0+mi*16+a_r)*RSTRA + k16 + a_k)*2;
        ldsm4(af[mi][0],af[mi][1],af[mi][2],af[mi][3],addr);
      }
      #pragma unroll
      for(int nb=0;nb<2;nb++){
        uint32_t addr = bb + (uint32_t)((k16+b_row)*RSTRB + n0 + nb*16 + b_cg)*2;
        ldsm4t(bf[nb*2][0],bf[nb*2][1],bf[nb*2+1][0],bf[nb*2+1][1],addr);
      }
      #pragma unroll
      for(int mi=0;mi<4;mi++)
        #pragma unroll
        for(int ni=0;ni<4;ni++) mma16816(acc[mi][ni],af[mi],bf[ni]);
    }
  }

  const int lr=lane>>2, lc=(lane&3)*2;
  #pragma unroll
  for(int mi=0;mi<4;mi++)
    #pragma unroll
    for(int ni=0;ni<4;ni++){
      int rA=bM+m0+mi*16+lr, c=bN+n0+ni*8+lc;
      #pragma unroll
      for(int h=0;h<2;h++){
        int r=rA+h*8;
        if(r>=M) continue;
        float v0=acc[mi][ni][h*2+0], v1=acc[mi][ni][h*2+1];
        if(MODE==0){
          if(bias){ v0+=bias[c]; v1+=bias[c+1]; }
          float2 f; f.x=v0; f.y=v1;
          *(float2*)&outF[(long)r*Ntot+c]=f;
        } else if(MODE==1){
          if(bias){ v0+=bias[c]; v1+=bias[c+1]; }
          v0=0.5f*v0*(1.0f+erff(v0*0.70710678118654752f));
          v1=0.5f*v1*(1.0f+erff(v1*0.70710678118654752f));
          *(__half2*)&outH[(long)r*Ntot+c]=__floats2half2_rn(v0,v1);
        } else if(MODE==3){
          __half2 ah=*(const __half2*)&addH[(long)r*Ntot+c];
          float2 af2=__half22float2(ah);
          v0+=af2.x; v1+=af2.y;
          *(__half2*)&outH[(long)r*Ntot+c]=__floats2half2_rn(v0,v1);
        } else if(MODE==4){
          if(bias){ v0+=bias[c]; v1+=bias[c+1]; }
          *(__half2*)&outH[(long)r*Ntot+c]=__floats2half2_rn(v0,v1);
        } else { // MODE 5
          if(bN==0){
            float2 f; f.x=v0; f.y=v1;
            *(float2*)&outF[(long)r*128+c]=f;
          } else {
            *(__half2*)&outH[(long)r*256+(c-128)]=__floats2half2_rn(v0,v1);
          }
        }
      }
    }
}

// ---------------- prep / small kernels ----------------
__global__ void f2h4_k(const float4* __restrict__ s, uint2* __restrict__ d, int n4){
  int i=blockIdx.x*blockDim.x+threadIdx.x, st=gridDim.x*blockDim.x;
  for(;i<n4;i+=st){
    float4 v=s[i];
    __half2 h0=__floats2half2_rn(v.x,v.y), h1=__floats2half2_rn(v.z,v.w);
    uint2 u; u.x=*(uint32_t*)&h0; u.y=*(uint32_t*)&h1;
    d[i]=u;
  }
}
__global__ void wcat9_k(const float4* __restrict__ S, const float4* __restrict__ E,
                        uint2* __restrict__ d){
  int i=blockIdx.x*blockDim.x+threadIdx.x, st=gridDim.x*blockDim.x;
  const int n4=9*262144;
  for(;i<n4;i+=st){
    float4 v = (i<262144) ? S[i] : E[i-262144];
    __half2 h0=__floats2half2_rn(v.x,v.y), h1=__floats2half2_rn(v.z,v.w);
    uint2 u; u.x=*(uint32_t*)&h0; u.y=*(uint32_t*)&h1;
    d[i]=u;
  }
}
__global__ void ccat_k(const float* __restrict__ A, int C0,
                       const float* __restrict__ Bm, int C1,
                       __half* __restrict__ d, int K){
  int Ct=C0+C1, n2=K*Ct/2;
  for(int i=blockIdx.x*blockDim.x+threadIdx.x;i<n2;i+=gridDim.x*blockDim.x){
    int r=i/(Ct/2), c=(i%(Ct/2))*2;
    float2 v;
    if (c<C0) v=*(const float2*)&A[(long)r*C0+c];
    else      v=*(const float2*)&Bm[(long)r*C1+c-C0];
    *(__half2*)&d[(long)r*Ct+c]=__floats2half2_rn(v.x,v.y);
  }
}
__global__ void init_k(int* __restrict__ rowTok, int* __restrict__ cnt){
  int i=blockIdx.x*256+threadIdx.x;
  if (i<PADROWS) rowTok[i] = (i<16384) ? i : -1;
  if (i<NE) cnt[i]=0;
}
__global__ void gate_k(const float* __restrict__ x,const float* __restrict__ Wg,
                       const float* __restrict__ rs,int* __restrict__ tokE,float* __restrict__ tokW){
  int t=blockIdx.x, tid=threadIdx.x;
  float a[8]={0,0,0,0,0,0,0,0};
  const float* xr=x+(long)t*1024;
  for(int i=tid;i<1024;i+=128){
    float xv=xr[i]; const float* wr=Wg+i*8;
    #pragma unroll
    for(int e=0;e<8;e++) a[e]+=xv*wr[e];
  }
  __shared__ float sm[128][8];
  #pragma unroll
  for(int e=0;e<8;e++) sm[tid][e]=a[e];
  __syncthreads();
  for(int off=64;off;off>>=1){
    if(tid<off){
      #pragma unroll
      for(int e=0;e<8;e++) sm[tid][e]+=sm[tid+off][e];
    }
    __syncthreads();
  }
  if(tid==0){
    float s[8], sc=rs[0];
    #pragma unroll
    for(int e=0;e<8;e++) s[e]=sc/(1.f+expf(-sm[0][e]));
    int i0=0;
    #pragma unroll
    for(int e=1;e<8;e++) if(s[e]>s[i0]) i0=e;
    int i1=-1;
    #pragma unroll
    for(int e=0;e<8;e++){ if(e==i0)continue; if(i1<0||s[e]>s[i1]) i1=e; }
    float sum=s[i0]+s[i1];
    tokE[2*t]=i0; tokE[2*t+1]=i1;
    tokW[2*t]=s[i0]/sum; tokW[2*t+1]=s[i1]/sum;
  }
}
// atomic slot assignment; output is order-independent (each row's values depend
// only on its token; combine gathers via tokPos), so replay-deterministic.
__global__ void scatter_k(const int* __restrict__ tokE, int* __restrict__ cnt,
                          int* __restrict__ rowTok, int* __restrict__ tokPos){
  int t=blockIdx.x*256+threadIdx.x;
  if (t>=NT) return;
  #pragma unroll
  for(int j=0;j<2;j++){
    int e=tokE[2*t+j];
    int slot=atomicAdd(&cnt[e],1);
    if (slot<CAP){
      int p=16384+e*CAP+slot;
      rowTok[p]=t;
      tokPos[2*t+j]=p;
    }
  }
}
__global__ void combine_k(const __half* __restrict__ Z,
                          const int* __restrict__ tokPos, const float* __restrict__ tokW,
                          __half* __restrict__ yh){
  int t=blockIdx.x, tid=threadIdx.x;
  int p0=tokPos[2*t], p1=tokPos[2*t+1];
  float w0=tokW[2*t], w1=tokW[2*t+1];
  const __half2* zs=(const __half2*)(Z+(long)t*1024);
  const __half2* z0=(const __half2*)(Z+(long)p0*1024);
  const __half2* z1=(const __half2*)(Z+(long)p1*1024);
  __half2* yhp=(__half2*)(yh+(long)t*1024);
  for(int i=tid;i<512;i+=128){
    float2 s=__half22float2(zs[i]);
    float2 a=__half22float2(z0[i]), b=__half22float2(z1[i]);
    yhp[i]=__floats2half2_rn(s.x + w0*a.x + w1*b.x, s.y + w0*a.y + w1*b.y);
  }
}
// s=8 attention. freqs = pos*rope_freq is ELEMENTWISE (both len 8):
// angle[j] = j * 10000^(-j/8), identical for every position.
__global__ void attn_k(const float* __restrict__ qbuf,const float* __restrict__ kv,
                       __half* __restrict__ oh){
  int b=blockIdx.x, h=threadIdx.x>>5, lane=threadIdx.x&31;
  __shared__ float q[4][8][32],k[4][8][32],v[4][8][32],p[4][8][8],sc[4][8][8];
  #pragma unroll
  for(int s=0;s<8;s++){
    long t=(long)b*8+s;
    q[h][s][lane]=qbuf[t*128+h*32+lane];
    k[h][s][lane]=kv[t*256+h*32+lane];
    v[h][s][lane]=kv[t*256+128+h*32+lane];
  }
  __syncwarp();
  if(lane<8){
    float ang=(float)lane*powf(10000.f,-(float)lane/8.f);
    float c=cosf(ang), sn=sinf(ang);
    #pragma unroll
    for(int s=0;s<8;s++){
      float x1=q[h][s][lane], x2=q[h][s][lane+8];
      q[h][s][lane]=x1*c-x2*sn; q[h][s][lane+8]=x1*sn+x2*c;
    }
  }
  __syncwarp();
  #pragma unroll
  for(int e=0;e<2;e++){
    int id=lane+e*32, qi=id>>3, ki=id&7;
    float s0=0.f;
    #pragma unroll
    for(int d=0;d<32;d++) s0+=q[h][qi][d]*k[h][ki][d];
    sc[h][qi][ki]=s0*0.17677669529663687f;
  }
  __syncwarp();
  if(lane<8){
    float m=-1e30f;
    #pragma unroll
    for(int j=0;j<8;j++) m=fmaxf(m,sc[h][lane][j]);
    float ex[8], su=0.f;
    #pragma unroll
    for(int j=0;j<8;j++){ ex[j]=expf(sc[h][lane][j]-m); su+=ex[j]; }
    float inv=1.f/su;
    #pragma unroll
    for(int j=0;j<8;j++) p[h][lane][j]=ex[j]*inv;
  }
  __syncwarp();
  #pragma unroll
  for(int qi=0;qi<8;qi++){
    float o=0.f;
    #pragma unroll
    for(int j=0;j<8;j++) o+=p[h][qi][j]*v[h][j][lane];
    oh[((long)b*8+qi)*128+h*32+lane]=__float2half(o);
  }
}
__global__ void value_k(const __half* __restrict__ ch,const float* __restrict__ Wv,
                        const float* __restrict__ bv,float* __restrict__ o){
  int t=blockIdx.x, tid=threadIdx.x;
  const __half2* cp=(const __half2*)(ch+(long)t*1024);
  const float2* wp=(const float2*)Wv;
  float s=0.f;
  for(int i=tid;i<512;i+=128){
    float2 c=__half22float2(cp[i]); float2 w=wp[i];
    s += c.x*w.x + c.y*w.y;
  }
  __shared__ float sm[128];
  sm[tid]=s; __syncthreads();
  for(int off=64;off;off>>=1){ if(tid<off) sm[tid]+=sm[tid+off]; __syncthreads(); }
  if(tid==0) o[t]=sm[0]+bv[0];
}

// ---------------- host launcher ----------------
extern "C" void kernel_launch(void* const* d_in, const int* in_sizes, int n_in,
                              void* d_out, int out_size){
  const float *x=(const float*)d_in[0], *Wg=(const float*)d_in[1], *W1=(const float*)d_in[2],
    *b1=(const float*)d_in[3], *W2=(const float*)d_in[4], *b2=(const float*)d_in[5],
    *Ws1=(const float*)d_in[6], *bs1=(const float*)d_in[7], *Ws2=(const float*)d_in[8],
    *bs2=(const float*)d_in[9], *rs=(const float*)d_in[10], *Wq=(const float*)d_in[11],
    *Wkv=(const float*)d_in[12], *Wku=(const float*)d_in[13], *Wvu=(const float*)d_in[14],
    *Wao=(const float*)d_in[15], *Wo=(const float*)d_in[16], *bo=(const float*)d_in[17],
    *Wv=(const float*)d_in[18], *bv=(const float*)d_in[19];
  float* out=(float*)d_out;
  #define GS(T,p,s) T* p; cudaGetSymbolAddress((void**)&p,s)
  GS(__half,xh,g_xh); GS(__half,W1c,g_W1c); GS(__half,W2c,g_W2c);
  GS(__half,Wqkvh,g_Wqkvh); GS(__half,Wkuvh,g_Wkuvh); GS(__half,Waoh,g_Waoh); GS(__half,Woh,g_Woh);
  GS(__half,hb,g_hb); GS(__half,zb,g_z); GS(__half,yh,g_yh);
  GS(float,qbuf,g_qbuf); GS(__half,lath,g_lath); GS(float,kvb,g_kv);
  GS(__half,oh,g_oh); GS(__half,combh,g_combh);
  GS(int,tokE,g_tokE); GS(float,tokW,g_tokW);
  GS(int,rowTok,g_rowTok); GS(int,tokPos,g_tokPos); GS(int,cnt,g_cnt);
  #undef GS

  cudaFuncSetAttribute(hm_gemm<0,false,false>, cudaFuncAttributeMaxDynamicSharedMemorySize, HM_SMEM);
  cudaFuncSetAttribute(hm_gemm<1,true ,true >, cudaFuncAttributeMaxDynamicSharedMemorySize, HM_SMEM);
  cudaFuncSetAttribute(hm_gemm<4,false,true >, cudaFuncAttributeMaxDynamicSharedMemorySize, HM_SMEM);
  cudaFuncSetAttribute(hm_gemm<3,false,false>, cudaFuncAttributeMaxDynamicSharedMemorySize, HM_SMEM);
  cudaFuncSetAttribute(hm_gemm<5,false,false>, cudaFuncAttributeMaxDynamicSharedMemorySize, HM_SMEM);

  // launch order: #5 (0-based) = fused FFN1 GEMM (ncu -s 5 -c 1)
  f2h4_k<<<2048,256>>>((const float4*)x,(uint2*)xh,NT*256);                 // 0
  wcat9_k<<<4096,256>>>((const float4*)Ws1,(const float4*)W1,(uint2*)W1c);  // 1
  init_k<<<PADROWS/256,256>>>(rowTok,cnt);                                  // 2
  gate_k<<<NT,128>>>(x,Wg,rs,tokE,tokW);                                    // 3
  scatter_k<<<NT/256,256>>>(tokE,cnt,rowTok,tokPos);                        // 4

  dim3 gFFN(8,PADROWS/128);
  hm_gemm<1,true ,true ><<<gFFN,256,HM_SMEM>>>(xh,W1c,0,1024,1024,bs1,b1,   // 5 <- profiled
      nullptr,hb,nullptr,rowTok,cnt);
  wcat9_k<<<4096,256>>>((const float4*)Ws2,(const float4*)W2,(uint2*)W2c);  // 6
  hm_gemm<4,false,true ><<<gFFN,256,HM_SMEM>>>(hb,W2c,0,1024,1024,bs2,b2,   // 7
      nullptr,zb,nullptr,nullptr,cnt);
  combine_k<<<NT,128>>>(zb,tokPos,tokW,yh);                                 // 8

  ccat_k<<<768,256>>>(Wq,128,Wkv,256,Wqkvh,1024);                           // 9
  hm_gemm<5,false,false><<<dim3(3,128),256,HM_SMEM>>>(yh,Wqkvh,NT,384,1024, // 10
      nullptr,nullptr,qbuf,lath,nullptr,nullptr,nullptr);
  ccat_k<<<128,256>>>(Wku,128,Wvu,128,Wkuvh,256);                           // 11
  hm_gemm<0,false,false><<<dim3(2,128),256,HM_SMEM>>>(lath,Wkuvh,NT,256,256,// 12
      nullptr,nullptr,kvb,nullptr,nullptr,nullptr,nullptr);
  attn_k<<<2048,128>>>(qbuf,kvb,oh);                                        // 13
  f2h4_k<<<256,256>>>((const float4*)Wao,(uint2*)Waoh,128*256);             // 14
  hm_gemm<3,false,false><<<dim3(8,128),256,HM_SMEM>>>(oh,Waoh,NT,1024,128,  // 15
      nullptr,nullptr,nullptr,combh,yh,nullptr,nullptr);
  f2h4_k<<<1024,256>>>((const float4*)Wo,(uint2*)Woh,256*1024);             // 16
  hm_gemm<0,false,false><<<dim3(8,128),256,HM_SMEM>>>(combh,Woh,NT,1024,1024,// 17
      bo,nullptr,out,nullptr,nullptr,nullptr,nullptr);
  value_k<<<NT,128>>>(combh,Wv,bv,out+(long)NT*1024);                       // 18
}

// round 10
// speedup vs baseline: 1.9975x; 1.1333x over previous
#include <cuda_runtime.h>
#include <cuda_fp16.h>
#include <math.h>
#include <stdint.h>

#define NT 16384
#define NE 8
#define CAP 6144                        // fixed per-expert segment capacity (48 tiles)
#define PADROWS (16384 + NE*CAP)        // 65536

// ---------------- scratch ----------------
__device__ __half g_xh   [NT*1024];
__device__ __half g_W1c  [9*1024*1024];   // slot0 = Ws1, slots 1-8 = W1[e]; [K][N] k-major
__device__ __half g_W2c  [9*1024*1024];   // slot0 = Ws2, slots 1-8 = W2[e]
__device__ __half g_Wqkvh[1024*384];      // [K=1024][N=384]: cols 0-127 Wq, 128-383 Wkv
__device__ __half g_Wkuvh[256*256];       // [K=256][N=256]: cols 0-127 Wku, 128-255 Wvu
__device__ __half g_Waoh [128*1024];      // [K=128][N=1024]
__device__ __half g_Woh  [1024*1024];     // [K=1024][N=1024]
__device__ __half g_hb   [PADROWS*1024];
__device__ __half g_z    [PADROWS*1024];
__device__ __half g_yh   [NT*1024];
__device__ float  g_qbuf [NT*128];
__device__ __half g_lath [NT*256];
__device__ float  g_kv   [NT*256];
__device__ __half g_oh   [NT*128];
__device__ __half g_combh[NT*1024];
__device__ int    g_tokE [NT*2];
__device__ float  g_tokW [NT*2];
__device__ int    g_rowTok[PADROWS];
__device__ int    g_tokPos[NT*2];
__device__ int    g_cnt  [NE];

// ---------------- PTX helpers ----------------
__device__ __forceinline__ void cp16s(uint32_t s, const void* g, bool p){
  int n = p ? 16 : 0;
  asm volatile("cp.async.cg.shared.global [%0],[%1],16,%2;\n"::"r"(s),"l"(g),"r"(n));
}
#define CP_COMMIT() asm volatile("cp.async.commit_group;\n")
__device__ __forceinline__ void ldsm4(uint32_t& r0,uint32_t& r1,uint32_t& r2,uint32_t& r3,uint32_t a){
  asm volatile("ldmatrix.sync.aligned.m8n8.x4.shared.b16 {%0,%1,%2,%3}, [%4];\n"
    : "=r"(r0),"=r"(r1),"=r"(r2),"=r"(r3) : "r"(a));
}
__device__ __forceinline__ void ldsm4t(uint32_t& r0,uint32_t& r1,uint32_t& r2,uint32_t& r3,uint32_t a){
  asm volatile("ldmatrix.sync.aligned.m8n8.x4.trans.shared.b16 {%0,%1,%2,%3}, [%4];\n"
    : "=r"(r0),"=r"(r1),"=r"(r2),"=r"(r3) : "r"(a));
}
__device__ __forceinline__ void mma16816(float c[4], const uint32_t a[4], const uint32_t b[2]){
  asm volatile("mma.sync.aligned.m16n8k16.row.col.f32.f16.f16.f32 "
    "{%0,%1,%2,%3},{%4,%5,%6,%7},{%8,%9},{%0,%1,%2,%3};\n"
    :"+f"(c[0]),"+f"(c[1]),"+f"(c[2]),"+f"(c[3])
    :"r"(a[0]),"r"(a[1]),"r"(a[2]),"r"(a[3]),"r"(b[0]),"r"(b[1]));
}

// ---------------- HMMA GEMM ----------------
// C[M,Ntot] = A[M,K] * B[K,Ntot]  (B k-major, ldmatrix.trans). fp16 in / fp32 acc.
// Tile 128x128x32, 4-stage cp.async.
// MODE 0: outF=acc(+bias). 1: outH=gelu(acc+bias). 3: outH=half(acc+addH). 4: outH=half(acc+bias).
// MODE 5 (qkv): bN==0 tile -> outF fp32 stride 128; bN>=128 -> outH half stride 256 at col-128.
// GATHER: A row = rowTok[r] (negative => zero-filled).
// EXPSEG: seg0 rows [0,16384) -> B slot 0 + biasS; expert e at fixed base 16384+e*CAP,
//         valid tiles bounded by pad(cnt[e]); B slot e+1, bias biasE+e*1024.
#define STAGES 4
#define RSTRA 40
#define RSTRB 136
#define ASTG (128*RSTRA)
#define BSTG (32*RSTRB)
#define HM_SMEM (STAGES*(ASTG+BSTG)*2)

template<int MODE,bool GATHER,bool EXPSEG>
__global__ void __launch_bounds__(256,2) hm_gemm(
  const __half* __restrict__ A, const __half* __restrict__ B,
  int M, int Ntot, int K,
  const float* __restrict__ biasS, const float* __restrict__ biasE,
  float* __restrict__ outF, __half* __restrict__ outH,
  const __half* __restrict__ addH, const int* __restrict__ rowTok,
  const int* __restrict__ cnt)
{
  const int bM = blockIdx.y*128;
  const float* bias = biasS;
  if (EXPSEG){
    int seg;
    if (bM < 16384) seg = 0;
    else {
      int s = (bM - 16384) / CAP;
      int local = (bM - 16384) - s*CAP;
      int padc = (cnt[s]+127)&~127;
      if (padc > CAP) padc = CAP;
      if (local >= padc) return;
      seg = s+1;
    }
    B += (long)seg<<20;
    bias = (seg==0) ? biasS : (biasE ? biasE+(seg-1)*1024 : nullptr);
    M = PADROWS;
  } else {
    if (bM >= M) return;
  }
  const int bN = blockIdx.x*128;

  extern __shared__ __half sm[];
  const uint32_t AsmU = (uint32_t)__cvta_generic_to_shared(sm);
  const uint32_t BsmU = AsmU + STAGES*ASTG*2;

  const int tid=threadIdx.x, lane=tid&31, warp=tid>>5;
  const int m0=(warp>>2)*64, n0=(warp&3)*32;

  const __half* aptr[2]; uint32_t aoff[2]; bool avld[2];
  #pragma unroll
  for(int s=0;s<2;s++){
    int c=tid+256*s, row=c>>2, col=(c&3)*8;
    int rg=bM+row; bool v=rg<M;
    long rowIdx;
    if (GATHER){ int gi = v ? rowTok[rg] : 0; if (gi<0){ v=false; gi=0; } rowIdx = gi; }
    else rowIdx = v ? (long)rg : 0;
    aptr[s]=A+rowIdx*(long)K+col; aoff[s]=(uint32_t)(row*RSTRA+col)*2; avld[s]=v;
  }
  const __half* bptr[2]; uint32_t boff[2];
  #pragma unroll
  for(int s=0;s<2;s++){
    int c=tid+256*s, row=c>>4, col=(c&15)*8;
    bptr[s]=B+(long)row*Ntot+bN+col; boff[s]=(uint32_t)(row*RSTRB+col)*2;
  }
  auto load_stage=[&](int st_){
    int buf=st_%STAGES;
    uint32_t ab=AsmU+buf*ASTG*2, bb=BsmU+buf*BSTG*2;
    #pragma unroll
    for(int s=0;s<2;s++) cp16s(ab+aoff[s], aptr[s]+st_*32, avld[s]);
    #pragma unroll
    for(int s=0;s<2;s++) cp16s(bb+boff[s], bptr[s]+(long)st_*32*Ntot, true);
    CP_COMMIT();
  };

  float acc[4][4][4];
  #pragma unroll
  for(int i=0;i<4;i++)
    #pragma unroll
    for(int j=0;j<4;j++){ acc[i][j][0]=0.f;acc[i][j][1]=0.f;acc[i][j][2]=0.f;acc[i][j][3]=0.f; }

  const int KT=K>>5;
  #pragma unroll
  for(int s=0;s<3;s++){ if(s<KT) load_stage(s); else CP_COMMIT(); }

  const int a_r = ((lane>>3)&1)*8 + (lane&7);
  const int a_k = (lane>>4)*8;
  const int b_row = lane&15;
  const int b_cg  = (lane>>4)*8;

  for(int st=0; st<KT; st++){
    asm volatile("cp.async.wait_group 2;\n");
    __syncthreads();
    if (st+3<KT) load_stage(st+3);
    const int buf=st%STAGES;
    const uint32_t ab=AsmU+buf*ASTG*2, bb=BsmU+buf*BSTG*2;
    #pragma unroll
    for(int kk=0;kk<2;kk++){
      const int k16=kk*16;
      uint32_t af[4][4], bf[4][2];
      #pragma unroll
      for(int mi=0;mi<4;mi++){
        uint32_t addr = ab + (uint32_t)((m0+mi*16+a_r)*RSTRA + k16 + a_k)*2;
        ldsm4(af[mi][0],af[mi][1],af[mi][2],af[mi][3],addr);
      }
      #pragma unroll
      for(int nb=0;nb<2;nb++){
        uint32_t addr = bb + (uint32_t)((k16+b_row)*RSTRB + n0 + nb*16 + b_cg)*2;
        ldsm4t(bf[nb*2][0],bf[nb*2][1],bf[nb*2+1][0],bf[nb*2+1][1],addr);
      }
      #pragma unroll
      for(int mi=0;mi<4;mi++)
        #pragma unroll
        for(int ni=0;ni<4;ni++) mma16816(acc[mi][ni],af[mi],bf[ni]);
    }
  }

  const int lr=lane>>2, lc=(lane&3)*2;
  #pragma unroll
  for(int mi=0;mi<4;mi++)
    #pragma unroll
    for(int ni=0;ni<4;ni++){
      int rA=bM+m0+mi*16+lr, c=bN+n0+ni*8+lc;
      #pragma unroll
      for(int h=0;h<2;h++){
        int r=rA+h*8;
        if(r>=M) continue;
        float v0=acc[mi][ni][h*2+0], v1=acc[mi][ni][h*2+1];
        if(MODE==0){
          if(bias){ v0+=bias[c]; v1+=bias[c+1]; }
          float2 f; f.x=v0; f.y=v1;
          *(float2*)&outF[(long)r*Ntot+c]=f;
        } else if(MODE==1){
          if(bias){ v0+=bias[c]; v1+=bias[c+1]; }
          v0=0.5f*v0*(1.0f+erff(v0*0.70710678118654752f));
          v1=0.5f*v1*(1.0f+erff(v1*0.70710678118654752f));
          *(__half2*)&outH[(long)r*Ntot+c]=__floats2half2_rn(v0,v1);
        } else if(MODE==3){
          __half2 ah=*(const __half2*)&addH[(long)r*Ntot+c];
          float2 af2=__half22float2(ah);
          v0+=af2.x; v1+=af2.y;
          *(__half2*)&outH[(long)r*Ntot+c]=__floats2half2_rn(v0,v1);
        } else if(MODE==4){
          if(bias){ v0+=bias[c]; v1+=bias[c+1]; }
          *(__half2*)&outH[(long)r*Ntot+c]=__floats2half2_rn(v0,v1);
        } else { // MODE 5
          if(bN==0){
            float2 f; f.x=v0; f.y=v1;
            *(float2*)&outF[(long)r*128+c]=f;
          } else {
            *(__half2*)&outH[(long)r*256+(c-128)]=__floats2half2_rn(v0,v1);
          }
        }
      }
    }
}

// ---------------- prep / small kernels ----------------
__global__ void f2h4_k(const float4* __restrict__ s, uint2* __restrict__ d, int n4){
  int i=blockIdx.x*blockDim.x+threadIdx.x, st=gridDim.x*blockDim.x;
  for(;i<n4;i+=st){
    float4 v=s[i];
    __half2 h0=__floats2half2_rn(v.x,v.y), h1=__floats2half2_rn(v.z,v.w);
    uint2 u; u.x=*(uint32_t*)&h0; u.y=*(uint32_t*)&h1;
    d[i]=u;
  }
}
__global__ void wcat9_k(const float4* __restrict__ S, const float4* __restrict__ E,
                        uint2* __restrict__ d){
  int i=blockIdx.x*blockDim.x+threadIdx.x, st=gridDim.x*blockDim.x;
  const int n4=9*262144;
  for(;i<n4;i+=st){
    float4 v = (i<262144) ? S[i] : E[i-262144];
    __half2 h0=__floats2half2_rn(v.x,v.y), h1=__floats2half2_rn(v.z,v.w);
    uint2 u; u.x=*(uint32_t*)&h0; u.y=*(uint32_t*)&h1;
    d[i]=u;
  }
}
__global__ void ccat_k(const float* __restrict__ A, int C0,
                       const float* __restrict__ Bm, int C1,
                       __half* __restrict__ d, int K){
  int Ct=C0+C1, n2=K*Ct/2;
  for(int i=blockIdx.x*blockDim.x+threadIdx.x;i<n2;i+=gridDim.x*blockDim.x){
    int r=i/(Ct/2), c=(i%(Ct/2))*2;
    float2 v;
    if (c<C0) v=*(const float2*)&A[(long)r*C0+c];
    else      v=*(const float2*)&Bm[(long)r*C1+c-C0];
    *(__half2*)&d[(long)r*Ct+c]=__floats2half2_rn(v.x,v.y);
  }
}
__global__ void init_k(int* __restrict__ rowTok, int* __restrict__ cnt){
  int i=blockIdx.x*256+threadIdx.x;
  if (i<PADROWS) rowTok[i] = (i<16384) ? i : -1;
  if (i<NE) cnt[i]=0;
}
// gate: warp-per-token GEMV. WgT staged transposed in smem (bank-conflict-free:
// for fixed e, lane l reads i=l+32j -> bank=lane). x reads fully coalesced.
__global__ void __launch_bounds__(256) gate_k(
    const float* __restrict__ x,const float* __restrict__ Wg,
    const float* __restrict__ rs,int* __restrict__ tokE,float* __restrict__ tokW){
  __shared__ float WgT[8*1024];
  int tid=threadIdx.x;
  for(int j=tid;j<8192;j+=256){
    int i=j>>3, e=j&7;
    WgT[e*1024+i]=Wg[j];
  }
  __syncthreads();
  int warp=tid>>5, lane=tid&31;
  float sc=rs[0];
  #pragma unroll 1
  for(int tt=0; tt<4; tt++){
    int t = blockIdx.x*32 + warp*4 + tt;
    const float* xr = x + (long)t*1024;
    float a[8]={0,0,0,0,0,0,0,0};
    #pragma unroll 4
    for(int j=0;j<32;j++){
      float xv = xr[lane+32*j];
      const float* wt = &WgT[lane+32*j];
      #pragma unroll
      for(int e=0;e<8;e++) a[e] += xv*wt[e*1024];
    }
    #pragma unroll
    for(int off=16;off;off>>=1){
      #pragma unroll
      for(int e=0;e<8;e++) a[e]+=__shfl_down_sync(0xffffffffu,a[e],off);
    }
    if(lane==0){
      float s[8];
      #pragma unroll
      for(int e=0;e<8;e++) s[e]=sc/(1.f+expf(-a[e]));
      int i0=0;
      #pragma unroll
      for(int e=1;e<8;e++) if(s[e]>s[i0]) i0=e;
      int i1=-1;
      #pragma unroll
      for(int e=0;e<8;e++){ if(e==i0)continue; if(i1<0||s[e]>s[i1]) i1=e; }
      float sum=s[i0]+s[i1];
      tokE[2*t]=i0; tokE[2*t+1]=i1;
      tokW[2*t]=s[i0]/sum; tokW[2*t+1]=s[i1]/sum;
    }
  }
}
// atomic slot assignment; output is order-independent (each row's values depend
// only on its token; combine gathers via tokPos), so replay-deterministic.
__global__ void scatter_k(const int* __restrict__ tokE, int* __restrict__ cnt,
                          int* __restrict__ rowTok, int* __restrict__ tokPos){
  int t=blockIdx.x*256+threadIdx.x;
  if (t>=NT) return;
  #pragma unroll
  for(int j=0;j<2;j++){
    int e=tokE[2*t+j];
    int slot=atomicAdd(&cnt[e],1);
    if (slot<CAP){
      int p=16384+e*CAP+slot;
      rowTok[p]=t;
      tokPos[2*t+j]=p;
    }
  }
}
__global__ void combine_k(const __half* __restrict__ Z,
                          const int* __restrict__ tokPos, const float* __restrict__ tokW,
                          __half* __restrict__ yh){
  int t=blockIdx.x, tid=threadIdx.x;
  int p0=tokPos[2*t], p1=tokPos[2*t+1];
  float w0=tokW[2*t], w1=tokW[2*t+1];
  const __half2* zs=(const __half2*)(Z+(long)t*1024);
  const __half2* z0=(const __half2*)(Z+(long)p0*1024);
  const __half2* z1=(const __half2*)(Z+(long)p1*1024);
  __half2* yhp=(__half2*)(yh+(long)t*1024);
  for(int i=tid;i<512;i+=128){
    float2 s=__half22float2(zs[i]);
    float2 a=__half22float2(z0[i]), b=__half22float2(z1[i]);
    yhp[i]=__floats2half2_rn(s.x + w0*a.x + w1*b.x, s.y + w0*a.y + w1*b.y);
  }
}
// s=8 attention. freqs = pos*rope_freq is ELEMENTWISE (both len 8):
// angle[j] = j * 10000^(-j/8), identical for every position.
__global__ void attn_k(const float* __restrict__ qbuf,const float* __restrict__ kv,
                       __half* __restrict__ oh){
  int b=blockIdx.x, h=threadIdx.x>>5, lane=threadIdx.x&31;
  __shared__ float q[4][8][32],k[4][8][32],v[4][8][32],p[4][8][8],sc[4][8][8];
  #pragma unroll
  for(int s=0;s<8;s++){
    long t=(long)b*8+s;
    q[h][s][lane]=qbuf[t*128+h*32+lane];
    k[h][s][lane]=kv[t*256+h*32+lane];
    v[h][s][lane]=kv[t*256+128+h*32+lane];
  }
  __syncwarp();
  if(lane<8){
    float ang=(float)lane*powf(10000.f,-(float)lane/8.f);
    float c=cosf(ang), sn=sinf(ang);
    #pragma unroll
    for(int s=0;s<8;s++){
      float x1=q[h][s][lane], x2=q[h][s][lane+8];
      q[h][s][lane]=x1*c-x2*sn; q[h][s][lane+8]=x1*sn+x2*c;
    }
  }
  __syncwarp();
  #pragma unroll
  for(int e=0;e<2;e++){
    int id=lane+e*32, qi=id>>3, ki=id&7;
    float s0=0.f;
    #pragma unroll
    for(int d=0;d<32;d++) s0+=q[h][qi][d]*k[h][ki][d];
    sc[h][qi][ki]=s0*0.17677669529663687f;
  }
  __syncwarp();
  if(lane<8){
    float m=-1e30f;
    #pragma unroll
    for(int j=0;j<8;j++) m=fmaxf(m,sc[h][lane][j]);
    float ex[8], su=0.f;
    #pragma unroll
    for(int j=0;j<8;j++){ ex[j]=expf(sc[h][lane][j]-m); su+=ex[j]; }
    float inv=1.f/su;
    #pragma unroll
    for(int j=0;j<8;j++) p[h][lane][j]=ex[j]*inv;
  }
  __syncwarp();
  #pragma unroll
  for(int qi=0;qi<8;qi++){
    float o=0.f;
    #pragma unroll
    for(int j=0;j<8;j++) o+=p[h][qi][j]*v[h][j][lane];
    oh[((long)b*8+qi)*128+h*32+lane]=__float2half(o);
  }
}
__global__ void value_k(const __half* __restrict__ ch,const float* __restrict__ Wv,
                        const float* __restrict__ bv,float* __restrict__ o){
  int t=blockIdx.x, tid=threadIdx.x;
  const __half2* cp=(const __half2*)(ch+(long)t*1024);
  const float2* wp=(const float2*)Wv;
  float s=0.f;
  for(int i=tid;i<512;i+=128){
    float2 c=__half22float2(cp[i]); float2 w=wp[i];
    s += c.x*w.x + c.y*w.y;
  }
  __shared__ float sm[128];
  sm[tid]=s; __syncthreads();
  for(int off=64;off;off>>=1){ if(tid<off) sm[tid]+=sm[tid+off]; __syncthreads(); }
  if(tid==0) o[t]=sm[0]+bv[0];
}

// ---------------- host launcher ----------------
extern "C" void kernel_launch(void* const* d_in, const int* in_sizes, int n_in,
                              void* d_out, int out_size){
  const float *x=(const float*)d_in[0], *Wg=(const float*)d_in[1], *W1=(const float*)d_in[2],
    *b1=(const float*)d_in[3], *W2=(const float*)d_in[4], *b2=(const float*)d_in[5],
    *Ws1=(const float*)d_in[6], *bs1=(const float*)d_in[7], *Ws2=(const float*)d_in[8],
    *bs2=(const float*)d_in[9], *rs=(const float*)d_in[10], *Wq=(const float*)d_in[11],
    *Wkv=(const float*)d_in[12], *Wku=(const float*)d_in[13], *Wvu=(const float*)d_in[14],
    *Wao=(const float*)d_in[15], *Wo=(const float*)d_in[16], *bo=(const float*)d_in[17],
    *Wv=(const float*)d_in[18], *bv=(const float*)d_in[19];
  float* out=(float*)d_out;
  #define GS(T,p,s) T* p; cudaGetSymbolAddress((void**)&p,s)
  GS(__half,xh,g_xh); GS(__half,W1c,g_W1c); GS(__half,W2c,g_W2c);
  GS(__half,Wqkvh,g_Wqkvh); GS(__half,Wkuvh,g_Wkuvh); GS(__half,Waoh,g_Waoh); GS(__half,Woh,g_Woh);
  GS(__half,hb,g_hb); GS(__half,zb,g_z); GS(__half,yh,g_yh);
  GS(float,qbuf,g_qbuf); GS(__half,lath,g_lath); GS(float,kvb,g_kv);
  GS(__half,oh,g_oh); GS(__half,combh,g_combh);
  GS(int,tokE,g_tokE); GS(float,tokW,g_tokW);
  GS(int,rowTok,g_rowTok); GS(int,tokPos,g_tokPos); GS(int,cnt,g_cnt);
  #undef GS

  cudaFuncSetAttribute(hm_gemm<0,false,false>, cudaFuncAttributeMaxDynamicSharedMemorySize, HM_SMEM);
  cudaFuncSetAttribute(hm_gemm<1,true ,true >, cudaFuncAttributeMaxDynamicSharedMemorySize, HM_SMEM);
  cudaFuncSetAttribute(hm_gemm<4,false,true >, cudaFuncAttributeMaxDynamicSharedMemorySize, HM_SMEM);
  cudaFuncSetAttribute(hm_gemm<3,false,false>, cudaFuncAttributeMaxDynamicSharedMemorySize, HM_SMEM);
  cudaFuncSetAttribute(hm_gemm<5,false,false>, cudaFuncAttributeMaxDynamicSharedMemorySize, HM_SMEM);

  // launch order: #5 (0-based) = fused FFN1 GEMM (ncu -s 5 -c 1)
  f2h4_k<<<2048,256>>>((const float4*)x,(uint2*)xh,NT*256);                 // 0
  wcat9_k<<<4096,256>>>((const float4*)Ws1,(const float4*)W1,(uint2*)W1c);  // 1
  init_k<<<PADROWS/256,256>>>(rowTok,cnt);                                  // 2
  gate_k<<<512,256>>>(x,Wg,rs,tokE,tokW);                                   // 3
  scatter_k<<<NT/256,256>>>(tokE,cnt,rowTok,tokPos);                        // 4

  dim3 gFFN(8,PADROWS/128);
  hm_gemm<1,true ,true ><<<gFFN,256,HM_SMEM>>>(xh,W1c,0,1024,1024,bs1,b1,   // 5 <- profiled
      nullptr,hb,nullptr,rowTok,cnt);
  wcat9_k<<<4096,256>>>((const float4*)Ws2,(const float4*)W2,(uint2*)W2c);  // 6
  hm_gemm<4,false,true ><<<gFFN,256,HM_SMEM>>>(hb,W2c,0,1024,1024,bs2,b2,   // 7
      nullptr,zb,nullptr,nullptr,cnt);
  combine_k<<<NT,128>>>(zb,tokPos,tokW,yh);                                 // 8

  ccat_k<<<768,256>>>(Wq,128,Wkv,256,Wqkvh,1024);                           // 9
  hm_gemm<5,false,false><<<dim3(3,128),256,HM_SMEM>>>(yh,Wqkvh,NT,384,1024, // 10
      nullptr,nullptr,qbuf,lath,nullptr,nullptr,nullptr);
  ccat_k<<<128,256>>>(Wku,128,Wvu,128,Wkuvh,256);                           // 11
  hm_gemm<0,false,false><<<dim3(2,128),256,HM_SMEM>>>(lath,Wkuvh,NT,256,256,// 12
      nullptr,nullptr,kvb,nullptr,nullptr,nullptr,nullptr);
  attn_k<<<2048,128>>>(qbuf,kvb,oh);                                        // 13
  f2h4_k<<<256,256>>>((const float4*)Wao,(uint2*)Waoh,128*256);             // 14
  hm_gemm<3,false,false><<<dim3(8,128),256,HM_SMEM>>>(oh,Waoh,NT,1024,128,  // 15
      nullptr,nullptr,nullptr,combh,yh,nullptr,nullptr);
  f2h4_k<<<1024,256>>>((const float4*)Wo,(uint2*)Woh,256*1024);             // 16
  hm_gemm<0,false,false><<<dim3(8,128),256,HM_SMEM>>>(combh,Woh,NT,1024,1024,// 17
      bo,nullptr,out,nullptr,nullptr,nullptr,nullptr);
  value_k<<<NT,128>>>(combh,Wv,bv,out+(long)NT*1024);                       // 18
}

// round 11
// speedup vs baseline: 2.0234x; 1.0129x over previous
#include <cuda_runtime.h>
#include <cuda_fp16.h>
#include <math.h>
#include <stdint.h>

#define NT 16384
#define NE 8
#define CAP 6144                        // fixed per-expert segment capacity (48 tiles)
#define PADROWS (16384 + NE*CAP)        // 65536

// ---------------- scratch ----------------
__device__ __half g_xh   [NT*1024];
__device__ __half g_W1c  [9*1024*1024];   // slot0 = Ws1, slots 1-8 = W1[e]; [K][N] k-major
__device__ __half g_W2c  [9*1024*1024];   // slot0 = Ws2, slots 1-8 = W2[e]
__device__ __half g_Wqkvh[1024*384];      // [K=1024][N=384]: cols 0-127 Wq, 128-383 Wkv
__device__ __half g_Wkuvh[256*256];       // [K=256][N=256]: cols 0-127 Wku, 128-255 Wvu
__device__ __half g_Waoh [128*1024];      // [K=128][N=1024]
__device__ __half g_Woh  [1024*1024];     // [K=1024][N=1024]
__device__ __half g_hb   [PADROWS*1024];
__device__ __half g_z    [PADROWS*1024];
__device__ __half g_yh   [NT*1024];
__device__ float  g_qbuf [NT*128];
__device__ __half g_lath [NT*256];
__device__ float  g_kv   [NT*256];
__device__ __half g_oh   [NT*128];
__device__ __half g_combh[NT*1024];
__device__ int    g_tokE [NT*2];
__device__ float  g_tokW [NT*2];
__device__ int    g_rowTok[PADROWS];
__device__ int    g_tokPos[NT*2];
__device__ int    g_cnt  [NE];

// ---------------- PTX helpers ----------------
__device__ __forceinline__ void cp16s(uint32_t s, const void* g, bool p){
  int n = p ? 16 : 0;
  asm volatile("cp.async.cg.shared.global [%0],[%1],16,%2;\n"::"r"(s),"l"(g),"r"(n));
}
#define CP_COMMIT() asm volatile("cp.async.commit_group;\n")
__device__ __forceinline__ void ldsm4(uint32_t& r0,uint32_t& r1,uint32_t& r2,uint32_t& r3,uint32_t a){
  asm volatile("ldmatrix.sync.aligned.m8n8.x4.shared.b16 {%0,%1,%2,%3}, [%4];\n"
    : "=r"(r0),"=r"(r1),"=r"(r2),"=r"(r3) : "r"(a));
}
__device__ __forceinline__ void ldsm4t(uint32_t& r0,uint32_t& r1,uint32_t& r2,uint32_t& r3,uint32_t a){
  asm volatile("ldmatrix.sync.aligned.m8n8.x4.trans.shared.b16 {%0,%1,%2,%3}, [%4];\n"
    : "=r"(r0),"=r"(r1),"=r"(r2),"=r"(r3) : "r"(a));
}
__device__ __forceinline__ void mma16816(float c[4], const uint32_t a[4], const uint32_t b[2]){
  asm volatile("mma.sync.aligned.m16n8k16.row.col.f32.f16.f16.f32 "
    "{%0,%1,%2,%3},{%4,%5,%6,%7},{%8,%9},{%0,%1,%2,%3};\n"
    :"+f"(c[0]),"+f"(c[1]),"+f"(c[2]),"+f"(c[3])
    :"r"(a[0]),"r"(a[1]),"r"(a[2]),"r"(a[3]),"r"(b[0]),"r"(b[1]));
}

// ---------------- HMMA GEMM ----------------
// C[M,Ntot] = A[M,K] * B[K,Ntot]  (B k-major, ldmatrix.trans). fp16 in / fp32 acc.
// Tile 128x128x32, 4-stage cp.async.
// MODE 0: outF=acc(+bias). 1: outH=gelu(acc+bias). 3: outH=half(acc+addH). 4: outH=half(acc+bias).
// MODE 5 (qkv): bN==0 tile -> outF fp32 stride 128; bN>=128 -> outH half stride 256 at col-128.
// GATHER: A row = rowTok[r] (negative => zero-filled).
// EXPSEG: seg0 rows [0,16384) -> B slot 0 + biasS; expert e at fixed base 16384+e*CAP,
//         valid tiles bounded by pad(cnt[e]); B slot e+1, bias biasE+e*1024.
#define STAGES 4
#define RSTRA 40
#define RSTRB 136
#define ASTG (128*RSTRA)
#define BSTG (32*RSTRB)
#define HM_SMEM (STAGES*(ASTG+BSTG)*2)

template<int MODE,bool GATHER,bool EXPSEG>
__global__ void __launch_bounds__(256,2) hm_gemm(
  const __half* __restrict__ A, const __half* __restrict__ B,
  int M, int Ntot, int K,
  const float* __restrict__ biasS, const float* __restrict__ biasE,
  float* __restrict__ outF, __half* __restrict__ outH,
  const __half* __restrict__ addH, const int* __restrict__ rowTok,
  const int* __restrict__ cnt)
{
  const int bM = blockIdx.y*128;
  const float* bias = biasS;
  if (EXPSEG){
    int seg;
    if (bM < 16384) seg = 0;
    else {
      int s = (bM - 16384) / CAP;
      int local = (bM - 16384) - s*CAP;
      int padc = (cnt[s]+127)&~127;
      if (padc > CAP) padc = CAP;
      if (local >= padc) return;
      seg = s+1;
    }
    B += (long)seg<<20;
    bias = (seg==0) ? biasS : (biasE ? biasE+(seg-1)*1024 : nullptr);
    M = PADROWS;
  } else {
    if (bM >= M) return;
  }
  const int bN = blockIdx.x*128;

  extern __shared__ __half sm[];
  const uint32_t AsmU = (uint32_t)__cvta_generic_to_shared(sm);
  const uint32_t BsmU = AsmU + STAGES*ASTG*2;

  const int tid=threadIdx.x, lane=tid&31, warp=tid>>5;
  const int m0=(warp>>2)*64, n0=(warp&3)*32;

  const __half* aptr[2]; uint32_t aoff[2]; bool avld[2];
  #pragma unroll
  for(int s=0;s<2;s++){
    int c=tid+256*s, row=c>>2, col=(c&3)*8;
    int rg=bM+row; bool v=rg<M;
    long rowIdx;
    if (GATHER){ int gi = v ? rowTok[rg] : 0; if (gi<0){ v=false; gi=0; } rowIdx = gi; }
    else rowIdx = v ? (long)rg : 0;
    aptr[s]=A+rowIdx*(long)K+col; aoff[s]=(uint32_t)(row*RSTRA+col)*2; avld[s]=v;
  }
  const __half* bptr[2]; uint32_t boff[2];
  #pragma unroll
  for(int s=0;s<2;s++){
    int c=tid+256*s, row=c>>4, col=(c&15)*8;
    bptr[s]=B+(long)row*Ntot+bN+col; boff[s]=(uint32_t)(row*RSTRB+col)*2;
  }
  auto load_stage=[&](int st_){
    int buf=st_%STAGES;
    uint32_t ab=AsmU+buf*ASTG*2, bb=BsmU+buf*BSTG*2;
    #pragma unroll
    for(int s=0;s<2;s++) cp16s(ab+aoff[s], aptr[s]+st_*32, avld[s]);
    #pragma unroll
    for(int s=0;s<2;s++) cp16s(bb+boff[s], bptr[s]+(long)st_*32*Ntot, true);
    CP_COMMIT();
  };

  float acc[4][4][4];
  #pragma unroll
  for(int i=0;i<4;i++)
    #pragma unroll
    for(int j=0;j<4;j++){ acc[i][j][0]=0.f;acc[i][j][1]=0.f;acc[i][j][2]=0.f;acc[i][j][3]=0.f; }

  const int KT=K>>5;
  #pragma unroll
  for(int s=0;s<3;s++){ if(s<KT) load_stage(s); else CP_COMMIT(); }

  const int a_r = ((lane>>3)&1)*8 + (lane&7);
  const int a_k = (lane>>4)*8;
  const int b_row = lane&15;
  const int b_cg  = (lane>>4)*8;

  for(int st=0; st<KT; st++){
    asm volatile("cp.async.wait_group 2;\n");
    __syncthreads();
    if (st+3<KT) load_stage(st+3);
    const int buf=st%STAGES;
    const uint32_t ab=AsmU+buf*ASTG*2, bb=BsmU+buf*BSTG*2;
    #pragma unroll
    for(int kk=0;kk<2;kk++){
      const int k16=kk*16;
      uint32_t af[4][4], bf[4][2];
      #pragma unroll
      for(int mi=0;mi<4;mi++){
        uint32_t addr = ab + (uint32_t)((m0+mi*16+a_r)*RSTRA + k16 + a_k)*2;
        ldsm4(af[mi][0],af[mi][1],af[mi][2],af[mi][3],addr);
      }
      #pragma unroll
      for(int nb=0;nb<2;nb++){
        uint32_t addr = bb + (uint32_t)((k16+b_row)*RSTRB + n0 + nb*16 + b_cg)*2;
        ldsm4t(bf[nb*2][0],bf[nb*2][1],bf[nb*2+1][0],bf[nb*2+1][1],addr);
      }
      #pragma unroll
      for(int mi=0;mi<4;mi++)
        #pragma unroll
        for(int ni=0;ni<4;ni++) mma16816(acc[mi][ni],af[mi],bf[ni]);
    }
  }

  const int lr=lane>>2, lc=(lane&3)*2;
  #pragma unroll
  for(int mi=0;mi<4;mi++)
    #pragma unroll
    for(int ni=0;ni<4;ni++){
      int rA=bM+m0+mi*16+lr, c=bN+n0+ni*8+lc;
      #pragma unroll
      for(int h=0;h<2;h++){
        int r=rA+h*8;
        if(r>=M) continue;
        float v0=acc[mi][ni][h*2+0], v1=acc[mi][ni][h*2+1];
        if(MODE==0){
          if(bias){ v0+=bias[c]; v1+=bias[c+1]; }
          float2 f; f.x=v0; f.y=v1;
          *(float2*)&outF[(long)r*Ntot+c]=f;
        } else if(MODE==1){
          if(bias){ v0+=bias[c]; v1+=bias[c+1]; }
          v0=0.5f*v0*(1.0f+erff(v0*0.70710678118654752f));
          v1=0.5f*v1*(1.0f+erff(v1*0.70710678118654752f));
          *(__half2*)&outH[(long)r*Ntot+c]=__floats2half2_rn(v0,v1);
        } else if(MODE==3){
          __half2 ah=*(const __half2*)&addH[(long)r*Ntot+c];
          float2 af2=__half22float2(ah);
          v0+=af2.x; v1+=af2.y;
          *(__half2*)&outH[(long)r*Ntot+c]=__floats2half2_rn(v0,v1);
        } else if(MODE==4){
          if(bias){ v0+=bias[c]; v1+=bias[c+1]; }
          *(__half2*)&outH[(long)r*Ntot+c]=__floats2half2_rn(v0,v1);
        } else { // MODE 5
          if(bN==0){
            float2 f; f.x=v0; f.y=v1;
            *(float2*)&outF[(long)r*128+c]=f;
          } else {
            *(__half2*)&outH[(long)r*256+(c-128)]=__floats2half2_rn(v0,v1);
          }
        }
      }
    }
}

// ---------------- prep / small kernels ----------------
__global__ void f2h4_k(const float4* __restrict__ s, uint2* __restrict__ d, int n4){
  int i=blockIdx.x*blockDim.x+threadIdx.x, st=gridDim.x*blockDim.x;
  for(;i<n4;i+=st){
    float4 v=s[i];
    __half2 h0=__floats2half2_rn(v.x,v.y), h1=__floats2half2_rn(v.z,v.w);
    uint2 u; u.x=*(uint32_t*)&h0; u.y=*(uint32_t*)&h1;
    d[i]=u;
  }
}
// both FFN weight banks in one launch: z=0 -> (Ws1,W1)->W1c ; z=1 -> (Ws2,W2)->W2c
__global__ void wcat2_k(const float4* __restrict__ S1, const float4* __restrict__ E1, uint2* __restrict__ d1,
                        const float4* __restrict__ S2, const float4* __restrict__ E2, uint2* __restrict__ d2){
  const float4* S = blockIdx.z ? S2 : S1;
  const float4* E = blockIdx.z ? E2 : E1;
  uint2* d = blockIdx.z ? d2 : d1;
  int i=blockIdx.x*blockDim.x+threadIdx.x, st=gridDim.x*blockDim.x;
  const int n4=9*262144;
  for(;i<n4;i+=st){
    float4 v = (i<262144) ? S[i] : E[i-262144];
    __half2 h0=__floats2half2_rn(v.x,v.y), h1=__floats2half2_rn(v.z,v.w);
    uint2 u; u.x=*(uint32_t*)&h0; u.y=*(uint32_t*)&h1;
    d[i]=u;
  }
}
__global__ void ccat_k(const float* __restrict__ A, int C0,
                       const float* __restrict__ Bm, int C1,
                       __half* __restrict__ d, int K){
  int Ct=C0+C1, n2=K*Ct/2;
  for(int i=blockIdx.x*blockDim.x+threadIdx.x;i<n2;i+=gridDim.x*blockDim.x){
    int r=i/(Ct/2), c=(i%(Ct/2))*2;
    float2 v;
    if (c<C0) v=*(const float2*)&A[(long)r*C0+c];
    else      v=*(const float2*)&Bm[(long)r*C1+c-C0];
    *(__half2*)&d[(long)r*Ct+c]=__floats2half2_rn(v.x,v.y);
  }
}
__global__ void init_k(int* __restrict__ rowTok, int* __restrict__ cnt){
  int i=blockIdx.x*256+threadIdx.x;
  if (i<PADROWS) rowTok[i] = (i<16384) ? i : -1;
  if (i<NE) cnt[i]=0;
}
// gate: one warp per token. WgT staged transposed in smem (conflict-free). Also
// emits xh = half(x) (bit-identical to the old separate f2h pass).
__global__ void __launch_bounds__(256) gate_k(
    const float* __restrict__ x,const float* __restrict__ Wg,
    const float* __restrict__ rs,int* __restrict__ tokE,float* __restrict__ tokW,
    __half* __restrict__ xh){
  __shared__ float WgT[8*1024];
  int tid=threadIdx.x;
  for(int j=tid;j<8192;j+=256){
    int i=j>>3, e=j&7;
    WgT[e*1024+i]=Wg[j];
  }
  __syncthreads();
  int warp=tid>>5, lane=tid&31;
  float sc=rs[0];
  int t = blockIdx.x*8 + warp;
  const float* xr = x + (long)t*1024;
  __half* xo = xh + (long)t*1024;
  float a[8]={0,0,0,0,0,0,0,0};
  #pragma unroll 4
  for(int j=0;j<32;j++){
    float xv = xr[lane+32*j];
    xo[lane+32*j] = __float2half(xv);
    const float* wt = &WgT[lane+32*j];
    #pragma unroll
    for(int e=0;e<8;e++) a[e] += xv*wt[e*1024];
  }
  #pragma unroll
  for(int off=16;off;off>>=1){
    #pragma unroll
    for(int e=0;e<8;e++) a[e]+=__shfl_down_sync(0xffffffffu,a[e],off);
  }
  if(lane==0){
    float s[8];
    #pragma unroll
    for(int e=0;e<8;e++) s[e]=sc/(1.f+expf(-a[e]));
    int i0=0;
    #pragma unroll
    for(int e=1;e<8;e++) if(s[e]>s[i0]) i0=e;
    int i1=-1;
    #pragma unroll
    for(int e=0;e<8;e++){ if(e==i0)continue; if(i1<0||s[e]>s[i1]) i1=e; }
    float sum=s[i0]+s[i1];
    tokE[2*t]=i0; tokE[2*t+1]=i1;
    tokW[2*t]=s[i0]/sum; tokW[2*t+1]=s[i1]/sum;
  }
}
// atomic slot assignment; output is order-independent (each row's values depend
// only on its token; combine gathers via tokPos), so replay-deterministic.
__global__ void scatter_k(const int* __restrict__ tokE, int* __restrict__ cnt,
                          int* __restrict__ rowTok, int* __restrict__ tokPos){
  int t=blockIdx.x*256+threadIdx.x;
  if (t>=NT) return;
  #pragma unroll
  for(int j=0;j<2;j++){
    int e=tokE[2*t+j];
    int slot=atomicAdd(&cnt[e],1);
    if (slot<CAP){
      int p=16384+e*CAP+slot;
      rowTok[p]=t;
      tokPos[2*t+j]=p;
    }
  }
}
__global__ void combine_k(const __half* __restrict__ Z,
                          const int* __restrict__ tokPos, const float* __restrict__ tokW,
                          __half* __restrict__ yh){
  int t=blockIdx.x, tid=threadIdx.x;
  int p0=tokPos[2*t], p1=tokPos[2*t+1];
  float w0=tokW[2*t], w1=tokW[2*t+1];
  const uint2* zs=(const uint2*)(Z+(long)t*1024);
  const uint2* z0=(const uint2*)(Z+(long)p0*1024);
  const uint2* z1=(const uint2*)(Z+(long)p1*1024);
  uint2* yhp=(uint2*)(yh+(long)t*1024);
  for(int i=tid;i<256;i+=128){
    uint2 us=zs[i], u0=z0[i], u1=z1[i];
    float2 sa=__half22float2(*(__half2*)&us.x), sb=__half22float2(*(__half2*)&us.y);
    float2 aa=__half22float2(*(__half2*)&u0.x), ab=__half22float2(*(__half2*)&u0.y);
    float2 ba=__half22float2(*(__half2*)&u1.x), bb=__half22float2(*(__half2*)&u1.y);
    __half2 r0=__floats2half2_rn(sa.x + w0*aa.x + w1*ba.x, sa.y + w0*aa.y + w1*ba.y);
    __half2 r1=__floats2half2_rn(sb.x + w0*ab.x + w1*bb.x, sb.y + w0*ab.y + w1*bb.y);
    uint2 o; o.x=*(uint32_t*)&r0; o.y=*(uint32_t*)&r1;
    yhp[i]=o;
  }
}
// s=8 attention. freqs = pos*rope_freq is ELEMENTWISE (both len 8):
// angle[j] = j * 10000^(-j/8), identical for every position.
__global__ void attn_k(const float* __restrict__ qbuf,const float* __restrict__ kv,
                       __half* __restrict__ oh){
  int b=blockIdx.x, h=threadIdx.x>>5, lane=threadIdx.x&31;
  __shared__ float q[4][8][32],k[4][8][32],v[4][8][32],p[4][8][8],sc[4][8][8];
  #pragma unroll
  for(int s=0;s<8;s++){
    long t=(long)b*8+s;
    q[h][s][lane]=qbuf[t*128+h*32+lane];
    k[h][s][lane]=kv[t*256+h*32+lane];
    v[h][s][lane]=kv[t*256+128+h*32+lane];
  }
  __syncwarp();
  if(lane<8){
    float ang=(float)lane*powf(10000.f,-(float)lane/8.f);
    float c=cosf(ang), sn=sinf(ang);
    #pragma unroll
    for(int s=0;s<8;s++){
      float x1=q[h][s][lane], x2=q[h][s][lane+8];
      q[h][s][lane]=x1*c-x2*sn; q[h][s][lane+8]=x1*sn+x2*c;
    }
  }
  __syncwarp();
  #pragma unroll
  for(int e=0;e<2;e++){
    int id=lane+e*32, qi=id>>3, ki=id&7;
    float s0=0.f;
    #pragma unroll
    for(int d=0;d<32;d++) s0+=q[h][qi][d]*k[h][ki][d];
    sc[h][qi][ki]=s0*0.17677669529663687f;
  }
  __syncwarp();
  if(lane<8){
    float m=-1e30f;
    #pragma unroll
    for(int j=0;j<8;j++) m=fmaxf(m,sc[h][lane][j]);
    float ex[8], su=0.f;
    #pragma unroll
    for(int j=0;j<8;j++){ ex[j]=expf(sc[h][lane][j]-m); su+=ex[j]; }
    float inv=1.f/su;
    #pragma unroll
    for(int j=0;j<8;j++) p[h][lane][j]=ex[j]*inv;
  }
  __syncwarp();
  #pragma unroll
  for(int qi=0;qi<8;qi++){
    float o=0.f;
    #pragma unroll
    for(int j=0;j<8;j++) o+=p[h][qi][j]*v[h][j][lane];
    oh[((long)b*8+qi)*128+h*32+lane]=__float2half(o);
  }
}
__global__ void value_k(const __half* __restrict__ ch,const float* __restrict__ Wv,
                        const float* __restrict__ bv,float* __restrict__ o){
  int t=blockIdx.x, tid=threadIdx.x;
  const __half2* cp=(const __half2*)(ch+(long)t*1024);
  const float2* wp=(const float2*)Wv;
  float s=0.f;
  for(int i=tid;i<512;i+=128){
    float2 c=__half22float2(cp[i]); float2 w=wp[i];
    s += c.x*w.x + c.y*w.y;
  }
  __shared__ float sm[128];
  sm[tid]=s; __syncthreads();
  for(int off=64;off;off>>=1){ if(tid<off) sm[tid]+=sm[tid+off]; __syncthreads(); }
  if(tid==0) o[t]=sm[0]+bv[0];
}

// ---------------- host launcher ----------------
extern "C" void kernel_launch(void* const* d_in, const int* in_sizes, int n_in,
                              void* d_out, int out_size){
  const float *x=(const float*)d_in[0], *Wg=(const float*)d_in[1], *W1=(const float*)d_in[2],
    *b1=(const float*)d_in[3], *W2=(const float*)d_in[4], *b2=(const float*)d_in[5],
    *Ws1=(const float*)d_in[6], *bs1=(const float*)d_in[7], *Ws2=(const float*)d_in[8],
    *bs2=(const float*)d_in[9], *rs=(const float*)d_in[10], *Wq=(const float*)d_in[11],
    *Wkv=(const float*)d_in[12], *Wku=(const float*)d_in[13], *Wvu=(const float*)d_in[14],
    *Wao=(const float*)d_in[15], *Wo=(const float*)d_in[16], *bo=(const float*)d_in[17],
    *Wv=(const float*)d_in[18], *bv=(const float*)d_in[19];
  float* out=(float*)d_out;
  #define GS(T,p,s) T* p; cudaGetSymbolAddress((void**)&p,s)
  GS(__half,xh,g_xh); GS(__half,W1c,g_W1c); GS(__half,W2c,g_W2c);
  GS(__half,Wqkvh,g_Wqkvh); GS(__half,Wkuvh,g_Wkuvh); GS(__half,Waoh,g_Waoh); GS(__half,Woh,g_Woh);
  GS(__half,hb,g_hb); GS(__half,zb,g_z); GS(__half,yh,g_yh);
  GS(float,qbuf,g_qbuf); GS(__half,lath,g_lath); GS(float,kvb,g_kv);
  GS(__half,oh,g_oh); GS(__half,combh,g_combh);
  GS(int,tokE,g_tokE); GS(float,tokW,g_tokW);
  GS(int,rowTok,g_rowTok); GS(int,tokPos,g_tokPos); GS(int,cnt,g_cnt);
  #undef GS

  cudaFuncSetAttribute(hm_gemm<0,false,false>, cudaFuncAttributeMaxDynamicSharedMemorySize, HM_SMEM);
  cudaFuncSetAttribute(hm_gemm<1,true ,true >, cudaFuncAttributeMaxDynamicSharedMemorySize, HM_SMEM);
  cudaFuncSetAttribute(hm_gemm<4,false,true >, cudaFuncAttributeMaxDynamicSharedMemorySize, HM_SMEM);
  cudaFuncSetAttribute(hm_gemm<3,false,false>, cudaFuncAttributeMaxDynamicSharedMemorySize, HM_SMEM);
  cudaFuncSetAttribute(hm_gemm<5,false,false>, cudaFuncAttributeMaxDynamicSharedMemorySize, HM_SMEM);

  // launch order: #5 (0-based) = fused FFN1 GEMM (ncu -s 5 -c 1)
  wcat2_k<<<dim3(2048,1,2),256>>>((const float4*)Ws1,(const float4*)W1,(uint2*)W1c,
                                  (const float4*)Ws2,(const float4*)W2,(uint2*)W2c);  // 0
  init_k<<<PADROWS/256,256>>>(rowTok,cnt);                                  // 1
  gate_k<<<2048,256>>>(x,Wg,rs,tokE,tokW,xh);                               // 2
  scatter_k<<<NT/256,256>>>(tokE,cnt,rowTok,tokPos);                        // 3
  ccat_k<<<768,256>>>(Wq,128,Wkv,256,Wqkvh,1024);                           // 4

  dim3 gFFN(8,PADROWS/128);
  hm_gemm<1,true ,true ><<<gFFN,256,HM_SMEM>>>(xh,W1c,0,1024,1024,bs1,b1,   // 5 <- profiled
      nullptr,hb,nullptr,rowTok,cnt);
  hm_gemm<4,false,true ><<<gFFN,256,HM_SMEM>>>(hb,W2c,0,1024,1024,bs2,b2,   // 6
      nullptr,zb,nullptr,nullptr,cnt);
  combine_k<<<NT,128>>>(zb,tokPos,tokW,yh);                                 // 7

  hm_gemm<5,false,false><<<dim3(3,128),256,HM_SMEM>>>(yh,Wqkvh,NT,384,1024, // 8
      nullptr,nullptr,qbuf,lath,nullptr,nullptr,nullptr);
  ccat_k<<<128,256>>>(Wku,128,Wvu,128,Wkuvh,256);                           // 9
  hm_gemm<0,false,false><<<dim3(2,128),256,HM_SMEM>>>(lath,Wkuvh,NT,256,256,// 10
      nullptr,nullptr,kvb,nullptr,nullptr,nullptr,nullptr);
  attn_k<<<2048,128>>>(qbuf,kvb,oh);                                        // 11
  f2h4_k<<<256,256>>>((const float4*)Wao,(uint2*)Waoh,128*256);             // 12
  hm_gemm<3,false,false><<<dim3(8,128),256,HM_SMEM>>>(oh,Waoh,NT,1024,128,  // 13
      nullptr,nullptr,nullptr,combh,yh,nullptr,nullptr);
  f2h4_k<<<1024,256>>>((const float4*)Wo,(uint2*)Woh,256*1024);             // 14
  hm_gemm<0,false,false><<<dim3(8,128),256,HM_SMEM>>>(combh,Woh,NT,1024,1024,// 15
      bo,nullptr,out,nullptr,nullptr,nullptr,nullptr);
  value_k<<<NT,128>>>(combh,Wv,bv,out+(long)NT*1024);                       // 16
}

// round 12
// speedup vs baseline: 2.0519x; 1.0141x over previous
#include <cuda_runtime.h>
#include <cuda_fp16.h>
#include <math.h>
#include <stdint.h>

#define NT 16384
#define NE 8
#define CAP 6144                        // fixed per-expert segment capacity (48 tiles)
#define PADROWS (16384 + NE*CAP)        // 65536

// ---------------- scratch ----------------
__device__ __half g_xh   [NT*1024];
__device__ __half g_W1c  [9*1024*1024];   // slot0 = Ws1, slots 1-8 = W1[e]; [K][N] k-major
__device__ __half g_W2c  [9*1024*1024];   // slot0 = Ws2, slots 1-8 = W2[e]
__device__ __half g_Wqkvh[1024*384];      // [K=1024][N=384]: cols 0-127 Wq, 128-383 Wkv
__device__ __half g_Wkuvh[256*256];       // [K=256][N=256]: cols 0-127 Wku, 128-255 Wvu
__device__ __half g_Waoh [128*1024];      // [K=128][N=1024]
__device__ __half g_Woh  [1024*1024];     // [K=1024][N=1024]
__device__ __half g_hb   [PADROWS*1024];
__device__ __half g_z    [PADROWS*1024];
__device__ __half g_yh   [NT*1024];
__device__ float  g_qbuf [NT*128];
__device__ __half g_lath [NT*256];
__device__ float  g_kv   [NT*256];
__device__ __half g_oh   [NT*128];
__device__ __half g_combh[NT*1024];
__device__ int    g_tokE [NT*2];
__device__ float  g_tokW [NT*2];
__device__ int    g_rowTok[PADROWS];
__device__ int    g_tokPos[NT*2];
__device__ int    g_cnt  [NE];

// ---------------- PTX helpers ----------------
__device__ __forceinline__ void cp16s(uint32_t s, const void* g, bool p){
  int n = p ? 16 : 0;
  asm volatile("cp.async.cg.shared.global [%0],[%1],16,%2;\n"::"r"(s),"l"(g),"r"(n));
}
#define CP_COMMIT() asm volatile("cp.async.commit_group;\n")
__device__ __forceinline__ void ldsm4(uint32_t& r0,uint32_t& r1,uint32_t& r2,uint32_t& r3,uint32_t a){
  asm volatile("ldmatrix.sync.aligned.m8n8.x4.shared.b16 {%0,%1,%2,%3}, [%4];\n"
    : "=r"(r0),"=r"(r1),"=r"(r2),"=r"(r3) : "r"(a));
}
__device__ __forceinline__ void ldsm4t(uint32_t& r0,uint32_t& r1,uint32_t& r2,uint32_t& r3,uint32_t a){
  asm volatile("ldmatrix.sync.aligned.m8n8.x4.trans.shared.b16 {%0,%1,%2,%3}, [%4];\n"
    : "=r"(r0),"=r"(r1),"=r"(r2),"=r"(r3) : "r"(a));
}
__device__ __forceinline__ void mma16816(float c[4], const uint32_t a[4], const uint32_t b[2]){
  asm volatile("mma.sync.aligned.m16n8k16.row.col.f32.f16.f16.f32 "
    "{%0,%1,%2,%3},{%4,%5,%6,%7},{%8,%9},{%0,%1,%2,%3};\n"
    :"+f"(c[0]),"+f"(c[1]),"+f"(c[2]),"+f"(c[3])
    :"r"(a[0]),"r"(a[1]),"r"(a[2]),"r"(a[3]),"r"(b[0]),"r"(b[1]));
}

// ---------------- HMMA GEMM ----------------
// C[M,Ntot] = A[M,K] * B[K,Ntot]  (B k-major, ldmatrix.trans). fp16 in / fp32 acc.
// Tile 128x128x32, 4-stage cp.async.
// MODE 0: outF=acc(+bias). 1: outH=gelu(acc+bias). 3: outH=half(acc+addH). 4: outH=half(acc+bias).
// MODE 5 (qkv): bN==0 tile -> outF fp32 stride 128; bN>=128 -> outH half stride 256 at col-128.
// GATHER: A row = (r<16384 ? r : rowTok[r])  — identity for shared segment.
// EXPSEG: seg0 rows [0,16384) -> B slot 0 + biasS; expert e at fixed base 16384+e*CAP,
//         valid tiles bounded by pad(cnt[e]); B slot e+1, bias biasE+e*1024.
#define STAGES 4
#define RSTRA 40
#define RSTRB 136
#define ASTG (128*RSTRA)
#define BSTG (32*RSTRB)
#define HM_SMEM (STAGES*(ASTG+BSTG)*2)

template<int MODE,bool GATHER,bool EXPSEG>
__global__ void __launch_bounds__(256,2) hm_gemm(
  const __half* __restrict__ A, const __half* __restrict__ B,
  int M, int Ntot, int K,
  const float* __restrict__ biasS, const float* __restrict__ biasE,
  float* __restrict__ outF, __half* __restrict__ outH,
  const __half* __restrict__ addH, const int* __restrict__ rowTok,
  const int* __restrict__ cnt)
{
  const int bM = blockIdx.y*128;
  const float* bias = biasS;
  if (EXPSEG){
    int seg;
    if (bM < 16384) seg = 0;
    else {
      int s = (bM - 16384) / CAP;
      int local = (bM - 16384) - s*CAP;
      int padc = (cnt[s]+127)&~127;
      if (padc > CAP) padc = CAP;
      if (local >= padc) return;
      seg = s+1;
    }
    B += (long)seg<<20;
    bias = (seg==0) ? biasS : (biasE ? biasE+(seg-1)*1024 : nullptr);
    M = PADROWS;
  } else {
    if (bM >= M) return;
  }
  const int bN = blockIdx.x*128;

  extern __shared__ __half sm[];
  const uint32_t AsmU = (uint32_t)__cvta_generic_to_shared(sm);
  const uint32_t BsmU = AsmU + STAGES*ASTG*2;

  const int tid=threadIdx.x, lane=tid&31, warp=tid>>5;
  const int m0=(warp>>2)*64, n0=(warp&3)*32;

  const __half* aptr[2]; uint32_t aoff[2]; bool avld[2];
  #pragma unroll
  for(int s=0;s<2;s++){
    int c=tid+256*s, row=c>>2, col=(c&3)*8;
    int rg=bM+row; bool v=rg<M;
    long rowIdx;
    if (GATHER){
      int gi = 0;
      if (v) gi = (rg<16384) ? rg : rowTok[rg];
      if (gi<0){ v=false; gi=0; }
      rowIdx = gi;
    } else rowIdx = v ? (long)rg : 0;
    aptr[s]=A+rowIdx*(long)K+col; aoff[s]=(uint32_t)(row*RSTRA+col)*2; avld[s]=v;
  }
  const __half* bptr[2]; uint32_t boff[2];
  #pragma unroll
  for(int s=0;s<2;s++){
    int c=tid+256*s, row=c>>4, col=(c&15)*8;
    bptr[s]=B+(long)row*Ntot+bN+col; boff[s]=(uint32_t)(row*RSTRB+col)*2;
  }
  auto load_stage=[&](int st_){
    int buf=st_%STAGES;
    uint32_t ab=AsmU+buf*ASTG*2, bb=BsmU+buf*BSTG*2;
    #pragma unroll
    for(int s=0;s<2;s++) cp16s(ab+aoff[s], aptr[s]+st_*32, avld[s]);
    #pragma unroll
    for(int s=0;s<2;s++) cp16s(bb+boff[s], bptr[s]+(long)st_*32*Ntot, true);
    CP_COMMIT();
  };

  float acc[4][4][4];
  #pragma unroll
  for(int i=0;i<4;i++)
    #pragma unroll
    for(int j=0;j<4;j++){ acc[i][j][0]=0.f;acc[i][j][1]=0.f;acc[i][j][2]=0.f;acc[i][j][3]=0.f; }

  const int KT=K>>5;
  #pragma unroll
  for(int s=0;s<3;s++){ if(s<KT) load_stage(s); else CP_COMMIT(); }

  const int a_r = ((lane>>3)&1)*8 + (lane&7);
  const int a_k = (lane>>4)*8;
  const int b_row = lane&15;
  const int b_cg  = (lane>>4)*8;

  for(int st=0; st<KT; st++){
    asm volatile("cp.async.wait_group 2;\n");
    __syncthreads();
    if (st+3<KT) load_stage(st+3);
    const int buf=st%STAGES;
    const uint32_t ab=AsmU+buf*ASTG*2, bb=BsmU+buf*BSTG*2;
    #pragma unroll
    for(int kk=0;kk<2;kk++){
      const int k16=kk*16;
      uint32_t af[4][4], bf[4][2];
      #pragma unroll
      for(int mi=0;mi<4;mi++){
        uint32_t addr = ab + (uint32_t)((m0+mi*16+a_r)*RSTRA + k16 + a_k)*2;
        ldsm4(af[mi][0],af[mi][1],af[mi][2],af[mi][3],addr);
      }
      #pragma unroll
      for(int nb=0;nb<2;nb++){
        uint32_t addr = bb + (uint32_t)((k16+b_row)*RSTRB + n0 + nb*16 + b_cg)*2;
        ldsm4t(bf[nb*2][0],bf[nb*2][1],bf[nb*2+1][0],bf[nb*2+1][1],addr);
      }
      #pragma unroll
      for(int mi=0;mi<4;mi++)
        #pragma unroll
        for(int ni=0;ni<4;ni++) mma16816(acc[mi][ni],af[mi],bf[ni]);
    }
  }

  const int lr=lane>>2, lc=(lane&3)*2;
  #pragma unroll
  for(int mi=0;mi<4;mi++)
    #pragma unroll
    for(int ni=0;ni<4;ni++){
      int rA=bM+m0+mi*16+lr, c=bN+n0+ni*8+lc;
      #pragma unroll
      for(int h=0;h<2;h++){
        int r=rA+h*8;
        if(r>=M) continue;
        float v0=acc[mi][ni][h*2+0], v1=acc[mi][ni][h*2+1];
        if(MODE==0){
          if(bias){ v0+=bias[c]; v1+=bias[c+1]; }
          float2 f; f.x=v0; f.y=v1;
          *(float2*)&outF[(long)r*Ntot+c]=f;
        } else if(MODE==1){
          if(bias){ v0+=bias[c]; v1+=bias[c+1]; }
          v0=0.5f*v0*(1.0f+erff(v0*0.70710678118654752f));
          v1=0.5f*v1*(1.0f+erff(v1*0.70710678118654752f));
          *(__half2*)&outH[(long)r*Ntot+c]=__floats2half2_rn(v0,v1);
        } else if(MODE==3){
          __half2 ah=*(const __half2*)&addH[(long)r*Ntot+c];
          float2 af2=__half22float2(ah);
          v0+=af2.x; v1+=af2.y;
          *(__half2*)&outH[(long)r*Ntot+c]=__floats2half2_rn(v0,v1);
        } else if(MODE==4){
          if(bias){ v0+=bias[c]; v1+=bias[c+1]; }
          *(__half2*)&outH[(long)r*Ntot+c]=__floats2half2_rn(v0,v1);
        } else { // MODE 5
          if(bN==0){
            float2 f; f.x=v0; f.y=v1;
            *(float2*)&outF[(long)r*128+c]=f;
          } else {
            *(__half2*)&outH[(long)r*256+(c-128)]=__floats2half2_rn(v0,v1);
          }
        }
      }
    }
}

// ---------------- fused prep: all weight conversions + gate(+scatter) ----------------
// grid (2048, 1, 5), 256 threads.
// z=0: (Ws1,W1)->W1c   z=1: (Ws2,W2)->W2c
// z=2: gate GEMV + xh convert + atomic scatter (needs cnt pre-zeroed)
// z=3: ccat Wq|Wkv -> Wqkvh
// z=4: blocks [0,128): ccat Wku|Wvu -> Wkuvh ; [128,256): Wao f2h ; [256,1280): Wo f2h
__global__ void __launch_bounds__(256) prep_all_k(
    const float4* __restrict__ Ws1, const float4* __restrict__ W1, uint2* __restrict__ W1c,
    const float4* __restrict__ Ws2, const float4* __restrict__ W2, uint2* __restrict__ W2c,
    const float* __restrict__ x, const float* __restrict__ Wg, const float* __restrict__ rs,
    int* __restrict__ tokE, float* __restrict__ tokW, __half* __restrict__ xh,
    int* __restrict__ cnt, int* __restrict__ rowTok, int* __restrict__ tokPos,
    const float* __restrict__ Wq, const float* __restrict__ Wkv, __half* __restrict__ Wqkvh,
    const float* __restrict__ Wku, const float* __restrict__ Wvu, __half* __restrict__ Wkuvh,
    const float4* __restrict__ Wao, uint2* __restrict__ Waoh,
    const float4* __restrict__ Wo, uint2* __restrict__ Woh)
{
  const int z=blockIdx.z, tid=threadIdx.x;
  if (z==0 || z==1){
    const float4* S = z ? Ws2 : Ws1;
    const float4* E = z ? W2  : W1;
    uint2* d = z ? W2c : W1c;
    const int n4=9*262144;
    for(int i=blockIdx.x*256+tid; i<n4; i+=2048*256){
      float4 v = (i<262144) ? S[i] : E[i-262144];
      __half2 h0=__floats2half2_rn(v.x,v.y), h1=__floats2half2_rn(v.z,v.w);
      uint2 u; u.x=*(uint32_t*)&h0; u.y=*(uint32_t*)&h1;
      d[i]=u;
    }
    return;
  }
  if (z==2){
    __shared__ float WgT[8*1024];
    for(int j=tid;j<8192;j+=256){
      int i=j>>3, e=j&7;
      WgT[e*1024+i]=Wg[j];
    }
    __syncthreads();
    int warp=tid>>5, lane=tid&31;
    float sc=rs[0];
    int t = blockIdx.x*8 + warp;
    const float* xr = x + (long)t*1024;
    __half* xo = xh + (long)t*1024;
    float a[8]={0,0,0,0,0,0,0,0};
    #pragma unroll 4
    for(int j=0;j<32;j++){
      float xv = xr[lane+32*j];
      xo[lane+32*j] = __float2half(xv);
      const float* wt = &WgT[lane+32*j];
      #pragma unroll
      for(int e=0;e<8;e++) a[e] += xv*wt[e*1024];
    }
    #pragma unroll
    for(int off=16;off;off>>=1){
      #pragma unroll
      for(int e=0;e<8;e++) a[e]+=__shfl_down_sync(0xffffffffu,a[e],off);
    }
    if(lane==0){
      float s[8];
      #pragma unroll
      for(int e=0;e<8;e++) s[e]=sc/(1.f+expf(-a[e]));
      int i0=0;
      #pragma unroll
      for(int e=1;e<8;e++) if(s[e]>s[i0]) i0=e;
      int i1=-1;
      #pragma unroll
      for(int e=0;e<8;e++){ if(e==i0)continue; if(i1<0||s[e]>s[i1]) i1=e; }
      float sum=s[i0]+s[i1];
      tokE[2*t]=i0; tokE[2*t+1]=i1;
      tokW[2*t]=s[i0]/sum; tokW[2*t+1]=s[i1]/sum;
      // fused scatter (order-independent: combine gathers via tokPos)
      int ee[2]={i0,i1};
      #pragma unroll
      for(int j=0;j<2;j++){
        int slot=atomicAdd(&cnt[ee[j]],1);
        if (slot<CAP){
          int p=16384+ee[j]*CAP+slot;
          rowTok[p]=t;
          tokPos[2*t+j]=p;
        }
      }
    }
    return;
  }
  if (z==3){
    const int n2=1024*192;            // half2 elements of [1024][384]
    for(int i=blockIdx.x*256+tid; i<n2; i+=2048*256){
      int r=i/192, c=(i%192)*2;
      float2 v;
      if (c<128) v=*(const float2*)&Wq[(long)r*128+c];
      else       v=*(const float2*)&Wkv[(long)r*256+c-128];
      *(__half2*)&Wqkvh[(long)r*384+c]=__floats2half2_rn(v.x,v.y);
    }
    return;
  }
  // z==4
  int b=blockIdx.x;
  if (b<128){
    int i=b*256+tid;                  // 32768 half2 of [256][256]
    int r=i/128, c=(i%128)*2;
    float2 v;
    if (c<128) v=*(const float2*)&Wku[(long)r*128+c];
    else       v=*(const float2*)&Wvu[(long)r*128+c-128];
    *(__half2*)&Wkuvh[(long)r*256+c]=__floats2half2_rn(v.x,v.y);
  } else if (b<256){
    int i=(b-128)*256+tid;            // 32768 float4 of Wao
    float4 v=Wao[i];
    __half2 h0=__floats2half2_rn(v.x,v.y), h1=__floats2half2_rn(v.z,v.w);
    uint2 u; u.x=*(uint32_t*)&h0; u.y=*(uint32_t*)&h1;
    Waoh[i]=u;
  } else if (b<1280){
    int i=(b-256)*256+tid;            // 262144 float4 of Wo
    float4 v=Wo[i];
    __half2 h0=__floats2half2_rn(v.x,v.y), h1=__floats2half2_rn(v.z,v.w);
    uint2 u; u.x=*(uint32_t*)&h0; u.y=*(uint32_t*)&h1;
    Woh[i]=u;
  }
}

// ---------------- remaining small kernels ----------------
__global__ void combine_k(const __half* __restrict__ Z,
                          const int* __restrict__ tokPos, const float* __restrict__ tokW,
                          __half* __restrict__ yh){
  int t=blockIdx.x, tid=threadIdx.x;
  int p0=tokPos[2*t], p1=tokPos[2*t+1];
  float w0=tokW[2*t], w1=tokW[2*t+1];
  const uint2* zs=(const uint2*)(Z+(long)t*1024);
  const uint2* z0=(const uint2*)(Z+(long)p0*1024);
  const uint2* z1=(const uint2*)(Z+(long)p1*1024);
  uint2* yhp=(uint2*)(yh+(long)t*1024);
  for(int i=tid;i<256;i+=128){
    uint2 us=zs[i], u0=z0[i], u1=z1[i];
    float2 sa=__half22float2(*(__half2*)&us.x), sb=__half22float2(*(__half2*)&us.y);
    float2 aa=__half22float2(*(__half2*)&u0.x), ab=__half22float2(*(__half2*)&u0.y);
    float2 ba=__half22float2(*(__half2*)&u1.x), bb=__half22float2(*(__half2*)&u1.y);
    __half2 r0=__floats2half2_rn(sa.x + w0*aa.x + w1*ba.x, sa.y + w0*aa.y + w1*ba.y);
    __half2 r1=__floats2half2_rn(sb.x + w0*ab.x + w1*bb.x, sb.y + w0*ab.y + w1*bb.y);
    uint2 o; o.x=*(uint32_t*)&r0; o.y=*(uint32_t*)&r1;
    yhp[i]=o;
  }
}
// s=8 attention. freqs = pos*rope_freq is ELEMENTWISE (both len 8):
// angle[j] = j * 10000^(-j/8), identical for every position.
__global__ void attn_k(const float* __restrict__ qbuf,const float* __restrict__ kv,
                       __half* __restrict__ oh){
  int b=blockIdx.x, h=threadIdx.x>>5, lane=threadIdx.x&31;
  __shared__ float q[4][8][32],k[4][8][32],v[4][8][32],p[4][8][8],sc[4][8][8];
  #pragma unroll
  for(int s=0;s<8;s++){
    long t=(long)b*8+s;
    q[h][s][lane]=qbuf[t*128+h*32+lane];
    k[h][s][lane]=kv[t*256+h*32+lane];
    v[h][s][lane]=kv[t*256+128+h*32+lane];
  }
  __syncwarp();
  if(lane<8){
    float ang=(float)lane*powf(10000.f,-(float)lane/8.f);
    float c=cosf(ang), sn=sinf(ang);
    #pragma unroll
    for(int s=0;s<8;s++){
      float x1=q[h][s][lane], x2=q[h][s][lane+8];
      q[h][s][lane]=x1*c-x2*sn; q[h][s][lane+8]=x1*sn+x2*c;
    }
  }
  __syncwarp();
  #pragma unroll
  for(int e=0;e<2;e++){
    int id=lane+e*32, qi=id>>3, ki=id&7;
    float s0=0.f;
    #pragma unroll
    for(int d=0;d<32;d++) s0+=q[h][qi][d]*k[h][ki][d];
    sc[h][qi][ki]=s0*0.17677669529663687f;
  }
  __syncwarp();
  if(lane<8){
    float m=-1e30f;
    #pragma unroll
    for(int j=0;j<8;j++) m=fmaxf(m,sc[h][lane][j]);
    float ex[8], su=0.f;
    #pragma unroll
    for(int j=0;j<8;j++){ ex[j]=expf(sc[h][lane][j]-m); su+=ex[j]; }
    float inv=1.f/su;
    #pragma unroll
    for(int j=0;j<8;j++) p[h][lane][j]=ex[j]*inv;
  }
  __syncwarp();
  #pragma unroll
  for(int qi=0;qi<8;qi++){
    float o=0.f;
    #pragma unroll
    for(int j=0;j<8;j++) o+=p[h][qi][j]*v[h][j][lane];
    oh[((long)b*8+qi)*128+h*32+lane]=__float2half(o);
  }
}
__global__ void value_k(const __half* __restrict__ ch,const float* __restrict__ Wv,
                        const float* __restrict__ bv,float* __restrict__ o){
  int t=blockIdx.x, tid=threadIdx.x;
  const __half2* cp=(const __half2*)(ch+(long)t*1024);
  const float2* wp=(const float2*)Wv;
  float s=0.f;
  for(int i=tid;i<512;i+=128){
    float2 c=__half22float2(cp[i]); float2 w=wp[i];
    s += c.x*w.x + c.y*w.y;
  }
  __shared__ float sm[128];
  sm[tid]=s; __syncthreads();
  for(int off=64;off;off>>=1){ if(tid<off) sm[tid]+=sm[tid+off]; __syncthreads(); }
  if(tid==0) o[t]=sm[0]+bv[0];
}

// ---------------- host launcher ----------------
extern "C" void kernel_launch(void* const* d_in, const int* in_sizes, int n_in,
                              void* d_out, int out_size){
  const float *x=(const float*)d_in[0], *Wg=(const float*)d_in[1], *W1=(const float*)d_in[2],
    *b1=(const float*)d_in[3], *W2=(const float*)d_in[4], *b2=(const float*)d_in[5],
    *Ws1=(const float*)d_in[6], *bs1=(const float*)d_in[7], *Ws2=(const float*)d_in[8],
    *bs2=(const float*)d_in[9], *rs=(const float*)d_in[10], *Wq=(const float*)d_in[11],
    *Wkv=(const float*)d_in[12], *Wku=(const float*)d_in[13], *Wvu=(const float*)d_in[14],
    *Wao=(const float*)d_in[15], *Wo=(const float*)d_in[16], *bo=(const float*)d_in[17],
    *Wv=(const float*)d_in[18], *bv=(const float*)d_in[19];
  float* out=(float*)d_out;
  #define GS(T,p,s) T* p; cudaGetSymbolAddress((void**)&p,s)
  GS(__half,xh,g_xh); GS(__half,W1c,g_W1c); GS(__half,W2c,g_W2c);
  GS(__half,Wqkvh,g_Wqkvh); GS(__half,Wkuvh,g_Wkuvh); GS(__half,Waoh,g_Waoh); GS(__half,Woh,g_Woh);
  GS(__half,hb,g_hb); GS(__half,zb,g_z); GS(__half,yh,g_yh);
  GS(float,qbuf,g_qbuf); GS(__half,lath,g_lath); GS(float,kvb,g_kv);
  GS(__half,oh,g_oh); GS(__half,combh,g_combh);
  GS(int,tokE,g_tokE); GS(float,tokW,g_tokW);
  GS(int,rowTok,g_rowTok); GS(int,tokPos,g_tokPos); GS(int,cnt,g_cnt);
  #undef GS

  cudaFuncSetAttribute(hm_gemm<0,false,false>, cudaFuncAttributeMaxDynamicSharedMemorySize, HM_SMEM);
  cudaFuncSetAttribute(hm_gemm<1,true ,true >, cudaFuncAttributeMaxDynamicSharedMemorySize, HM_SMEM);
  cudaFuncSetAttribute(hm_gemm<4,false,true >, cudaFuncAttributeMaxDynamicSharedMemorySize, HM_SMEM);
  cudaFuncSetAttribute(hm_gemm<3,false,false>, cudaFuncAttributeMaxDynamicSharedMemorySize, HM_SMEM);
  cudaFuncSetAttribute(hm_gemm<5,false,false>, cudaFuncAttributeMaxDynamicSharedMemorySize, HM_SMEM);

  cudaMemsetAsync(cnt, 0, NE*sizeof(int));                                  // 0
  prep_all_k<<<dim3(2048,1,5),256>>>(                                       // 1
      (const float4*)Ws1,(const float4*)W1,(uint2*)W1c,
      (const float4*)Ws2,(const float4*)W2,(uint2*)W2c,
      x,Wg,rs,tokE,tokW,xh,cnt,rowTok,tokPos,
      Wq,Wkv,Wqkvh,Wku,Wvu,Wkuvh,
      (const float4*)Wao,(uint2*)Waoh,(const float4*)Wo,(uint2*)Woh);

  dim3 gFFN(8,PADROWS/128);
  hm_gemm<1,true ,true ><<<gFFN,256,HM_SMEM>>>(xh,W1c,0,1024,1024,bs1,b1,   // 2
      nullptr,hb,nullptr,rowTok,cnt);
  hm_gemm<4,false,true ><<<gFFN,256,HM_SMEM>>>(hb,W2c,0,1024,1024,bs2,b2,   // 3
      nullptr,zb,nullptr,nullptr,cnt);
  combine_k<<<NT,128>>>(zb,tokPos,tokW,yh);                                 // 4

  hm_gemm<5,false,false><<<dim3(3,128),256,HM_SMEM>>>(yh,Wqkvh,NT,384,1024, // 5
      nullptr,nullptr,qbuf,lath,nullptr,nullptr,nullptr);
  hm_gemm<0,false,false><<<dim3(2,128),256,HM_SMEM>>>(lath,Wkuvh,NT,256,256,// 6
      nullptr,nullptr,kvb,nullptr,nullptr,nullptr,nullptr);
  attn_k<<<2048,128>>>(qbuf,kvb,oh);                                        // 7
  hm_gemm<3,false,false><<<dim3(8,128),256,HM_SMEM>>>(oh,Waoh,NT,1024,128,  // 8
      nullptr,nullptr,nullptr,combh,yh,nullptr,nullptr);
  hm_gemm<0,false,false><<<dim3(8,128),256,HM_SMEM>>>(combh,Woh,NT,1024,1024,// 9
      bo,nullptr,out,nullptr,nullptr,nullptr,nullptr);
  value_k<<<NT,128>>>(combh,Wv,bv,out+(long)NT*1024);                       // 10
}

// round 15
// speedup vs baseline: 2.0544x; 1.0012x over previous
#include <cuda_runtime.h>
#include <cuda_fp16.h>
#include <math.h>
#include <stdint.h>

#define NT 16384
#define NE 8
#define CAP 6144                        // fixed per-expert segment capacity (48 tiles)
#define PADROWS (16384 + NE*CAP)        // 65536

// ---------------- scratch ----------------
__device__ __half g_xh   [NT*1024];
__device__ __half g_W1c  [9*1024*1024];   // slot0 = Ws1, slots 1-8 = W1[e]; [K][N] k-major
__device__ __half g_W2c  [9*1024*1024];   // slot0 = Ws2, slots 1-8 = W2[e]
__device__ __half g_Wqkvh[1024*384];      // [K=1024][N=384]: cols 0-127 Wq, 128-383 Wkv
__device__ __half g_Wkuvh[256*256];       // [K=256][N=256]: cols 0-127 Wku, 128-255 Wvu
__device__ __half g_Waoh [128*1024];      // [K=128][N=1024]
__device__ __half g_Woh  [1024*1024];     // [K=1024][N=1024]
__device__ __half g_hb   [PADROWS*1024];
__device__ __half g_z    [PADROWS*1024];
__device__ __half g_yh   [NT*1024];
__device__ float  g_qbuf [NT*128];
__device__ __half g_lath [NT*256];
__device__ float  g_kv   [NT*256];
__device__ __half g_oh   [NT*128];
__device__ __half g_combh[NT*1024];
__device__ int    g_tokE [NT*2];
__device__ float  g_tokW [NT*2];
__device__ int    g_rowTok[PADROWS];
__device__ int    g_tokPos[NT*2];
__device__ int    g_cnt  [NE];

// ---------------- PTX helpers ----------------
__device__ __forceinline__ void cp16s(uint32_t s, const void* g, bool p){
  int n = p ? 16 : 0;
  asm volatile("cp.async.cg.shared.global [%0],[%1],16,%2;\n"::"r"(s),"l"(g),"r"(n));
}
#define CP_COMMIT() asm volatile("cp.async.commit_group;\n")
__device__ __forceinline__ void ldsm4(uint32_t& r0,uint32_t& r1,uint32_t& r2,uint32_t& r3,uint32_t a){
  asm volatile("ldmatrix.sync.aligned.m8n8.x4.shared.b16 {%0,%1,%2,%3}, [%4];\n"
    : "=r"(r0),"=r"(r1),"=r"(r2),"=r"(r3) : "r"(a));
}
__device__ __forceinline__ void ldsm4t(uint32_t& r0,uint32_t& r1,uint32_t& r2,uint32_t& r3,uint32_t a){
  asm volatile("ldmatrix.sync.aligned.m8n8.x4.trans.shared.b16 {%0,%1,%2,%3}, [%4];\n"
    : "=r"(r0),"=r"(r1),"=r"(r2),"=r"(r3) : "r"(a));
}
__device__ __forceinline__ void mma16816(float c[4], const uint32_t a[4], const uint32_t b[2]){
  asm volatile("mma.sync.aligned.m16n8k16.row.col.f32.f16.f16.f32 "
    "{%0,%1,%2,%3},{%4,%5,%6,%7},{%8,%9},{%0,%1,%2,%3};\n"
    :"+f"(c[0]),"+f"(c[1]),"+f"(c[2]),"+f"(c[3])
    :"r"(a[0]),"r"(a[1]),"r"(a[2]),"r"(a[3]),"r"(b[0]),"r"(b[1]));
}

// ---------------- HMMA GEMM ----------------
// C[M,Ntot] = A[M,K] * B[K,Ntot]  (B k-major, ldmatrix.trans). fp16 in / fp32 acc.
// Tile 128x128x32, 4-stage cp.async.
// MODE 0: outF=acc(+bias). 1: outH=gelu(acc+bias). 3: outH=half(acc+addH). 4: outH=half(acc+bias).
// MODE 5 (qkv): bN==0 tile -> outF fp32 stride 128; bN>=128 -> outH half stride 256 at col-128.
// GATHER: A row = (r<16384 ? r : rowTok[r])  — identity for shared segment.
// EXPSEG: seg0 rows [0,16384) -> B slot 0 + biasS; expert e at fixed base 16384+e*CAP,
//         valid tiles bounded by pad(cnt[e]); B slot e+1, bias biasE+e*1024.
#define STAGES 4
#define RSTRA 40
#define RSTRB 136
#define ASTG (128*RSTRA)
#define BSTG (32*RSTRB)
#define HM_SMEM (STAGES*(ASTG+BSTG)*2)

template<int MODE,bool GATHER,bool EXPSEG>
__global__ void __launch_bounds__(256,2) hm_gemm(
  const __half* __restrict__ A, const __half* __restrict__ B,
  int M, int Ntot, int K,
  const float* __restrict__ biasS, const float* __restrict__ biasE,
  float* __restrict__ outF, __half* __restrict__ outH,
  const __half* __restrict__ addH, const int* __restrict__ rowTok,
  const int* __restrict__ cnt)
{
  const int bM = blockIdx.y*128;
  const float* bias = biasS;
  if (EXPSEG){
    int seg;
    if (bM < 16384) seg = 0;
    else {
      int s = (bM - 16384) / CAP;
      int local = (bM - 16384) - s*CAP;
      int padc = (cnt[s]+127)&~127;
      if (padc > CAP) padc = CAP;
      if (local >= padc) return;
      seg = s+1;
    }
    B += (long)seg<<20;
    bias = (seg==0) ? biasS : (biasE ? biasE+(seg-1)*1024 : nullptr);
    M = PADROWS;
  } else {
    if (bM >= M) return;
  }
  const int bN = blockIdx.x*128;

  extern __shared__ __half sm[];
  const uint32_t AsmU = (uint32_t)__cvta_generic_to_shared(sm);
  const uint32_t BsmU = AsmU + STAGES*ASTG*2;

  const int tid=threadIdx.x, lane=tid&31, warp=tid>>5;
  const int m0=(warp>>2)*64, n0=(warp&3)*32;

  const __half* aptr[2]; uint32_t aoff[2]; bool avld[2];
  #pragma unroll
  for(int s=0;s<2;s++){
    int c=tid+256*s, row=c>>2, col=(c&3)*8;
    int rg=bM+row; bool v=rg<M;
    long rowIdx;
    if (GATHER){
      int gi = 0;
      if (v) gi = (rg<16384) ? rg : rowTok[rg];
      if (gi<0){ v=false; gi=0; }
      rowIdx = gi;
    } else rowIdx = v ? (long)rg : 0;
    aptr[s]=A+rowIdx*(long)K+col; aoff[s]=(uint32_t)(row*RSTRA+col)*2; avld[s]=v;
  }
  const __half* bptr[2]; uint32_t boff[2];
  #pragma unroll
  for(int s=0;s<2;s++){
    int c=tid+256*s, row=c>>4, col=(c&15)*8;
    bptr[s]=B+(long)row*Ntot+bN+col; boff[s]=(uint32_t)(row*RSTRB+col)*2;
  }
  auto load_stage=[&](int st_){
    int buf=st_%STAGES;
    uint32_t ab=AsmU+buf*ASTG*2, bb=BsmU+buf*BSTG*2;
    #pragma unroll
    for(int s=0;s<2;s++) cp16s(ab+aoff[s], aptr[s]+st_*32, avld[s]);
    #pragma unroll
    for(int s=0;s<2;s++) cp16s(bb+boff[s], bptr[s]+(long)st_*32*Ntot, true);
    CP_COMMIT();
  };

  float acc[4][4][4];
  #pragma unroll
  for(int i=0;i<4;i++)
    #pragma unroll
    for(int j=0;j<4;j++){ acc[i][j][0]=0.f;acc[i][j][1]=0.f;acc[i][j][2]=0.f;acc[i][j][3]=0.f; }

  const int KT=K>>5;
  #pragma unroll
  for(int s=0;s<3;s++){ if(s<KT) load_stage(s); else CP_COMMIT(); }

  const int a_r = ((lane>>3)&1)*8 + (lane&7);
  const int a_k = (lane>>4)*8;
  const int b_row = lane&15;
  const int b_cg  = (lane>>4)*8;

  for(int st=0; st<KT; st++){
    asm volatile("cp.async.wait_group 2;\n");
    __syncthreads();
    if (st+3<KT) load_stage(st+3);
    const int buf=st%STAGES;
    const uint32_t ab=AsmU+buf*ASTG*2, bb=BsmU+buf*BSTG*2;
    #pragma unroll
    for(int kk=0;kk<2;kk++){
      const int k16=kk*16;
      uint32_t af[4][4], bf[4][2];
      #pragma unroll
      for(int mi=0;mi<4;mi++){
        uint32_t addr = ab + (uint32_t)((m0+mi*16+a_r)*RSTRA + k16 + a_k)*2;
        ldsm4(af[mi][0],af[mi][1],af[mi][2],af[mi][3],addr);
      }
      #pragma unroll
      for(int nb=0;nb<2;nb++){
        uint32_t addr = bb + (uint32_t)((k16+b_row)*RSTRB + n0 + nb*16 + b_cg)*2;
        ldsm4t(bf[nb*2][0],bf[nb*2][1],bf[nb*2+1][0],bf[nb*2+1][1],addr);
      }
      #pragma unroll
      for(int mi=0;mi<4;mi++)
        #pragma unroll
        for(int ni=0;ni<4;ni++) mma16816(acc[mi][ni],af[mi],bf[ni]);
    }
  }

  const int lr=lane>>2, lc=(lane&3)*2;
  #pragma unroll
  for(int mi=0;mi<4;mi++)
    #pragma unroll
    for(int ni=0;ni<4;ni++){
      int rA=bM+m0+mi*16+lr, c=bN+n0+ni*8+lc;
      #pragma unroll
      for(int h=0;h<2;h++){
        int r=rA+h*8;
        if(r>=M) continue;
        float v0=acc[mi][ni][h*2+0], v1=acc[mi][ni][h*2+1];
        if(MODE==0){
          if(bias){ v0+=bias[c]; v1+=bias[c+1]; }
          float2 f; f.x=v0; f.y=v1;
          *(float2*)&outF[(long)r*Ntot+c]=f;
        } else if(MODE==1){
          if(bias){ v0+=bias[c]; v1+=bias[c+1]; }
          v0=0.5f*v0*(1.0f+erff(v0*0.70710678118654752f));
          v1=0.5f*v1*(1.0f+erff(v1*0.70710678118654752f));
          *(__half2*)&outH[(long)r*Ntot+c]=__floats2half2_rn(v0,v1);
        } else if(MODE==3){
          __half2 ah=*(const __half2*)&addH[(long)r*Ntot+c];
          float2 af2=__half22float2(ah);
          v0+=af2.x; v1+=af2.y;
          *(__half2*)&outH[(long)r*Ntot+c]=__floats2half2_rn(v0,v1);
        } else if(MODE==4){
          if(bias){ v0+=bias[c]; v1+=bias[c+1]; }
          *(__half2*)&outH[(long)r*Ntot+c]=__floats2half2_rn(v0,v1);
        } else { // MODE 5
          if(bN==0){
            float2 f; f.x=v0; f.y=v1;
            *(float2*)&outF[(long)r*128+c]=f;
          } else {
            *(__half2*)&outH[(long)r*256+(c-128)]=__floats2half2_rn(v0,v1);
          }
        }
      }
    }
}

// ---------------- fused prep: all weight conversions + gate(+scatter) ----------------
// grid (2048, 1, 5), 256 threads.
// z=0: (Ws1,W1)->W1c   z=1: (Ws2,W2)->W2c
// z=2: gate GEMV + xh convert + atomic scatter (needs cnt pre-zeroed)
// z=3: ccat Wq|Wkv -> Wqkvh
// z=4: blocks [0,128): ccat Wku|Wvu -> Wkuvh ; [128,256): Wao f2h ; [256,1280): Wo f2h
__global__ void __launch_bounds__(256) prep_all_k(
    const float4* __restrict__ Ws1, const float4* __restrict__ W1, uint2* __restrict__ W1c,
    const float4* __restrict__ Ws2, const float4* __restrict__ W2, uint2* __restrict__ W2c,
    const float* __restrict__ x, const float* __restrict__ Wg, const float* __restrict__ rs,
    int* __restrict__ tokE, float* __restrict__ tokW, __half* __restrict__ xh,
    int* __restrict__ cnt, int* __restrict__ rowTok, int* __restrict__ tokPos,
    const float* __restrict__ Wq, const float* __restrict__ Wkv, __half* __restrict__ Wqkvh,
    const float* __restrict__ Wku, const float* __restrict__ Wvu, __half* __restrict__ Wkuvh,
    const float4* __restrict__ Wao, uint2* __restrict__ Waoh,
    const float4* __restrict__ Wo, uint2* __restrict__ Woh)
{
  const int z=blockIdx.z, tid=threadIdx.x;
  if (z==0 || z==1){
    const float4* S = z ? Ws2 : Ws1;
    const float4* E = z ? W2  : W1;
    uint2* d = z ? W2c : W1c;
    const int n4=9*262144;
    for(int i=blockIdx.x*256+tid; i<n4; i+=2048*256){
      float4 v = (i<262144) ? S[i] : E[i-262144];
      __half2 h0=__floats2half2_rn(v.x,v.y), h1=__floats2half2_rn(v.z,v.w);
      uint2 u; u.x=*(uint32_t*)&h0; u.y=*(uint32_t*)&h1;
      d[i]=u;
    }
    return;
  }
  if (z==2){
    __shared__ float WgT[8*1024];
    for(int j=tid;j<8192;j+=256){
      int i=j>>3, e=j&7;
      WgT[e*1024+i]=Wg[j];
    }
    __syncthreads();
    int warp=tid>>5, lane=tid&31;
    float sc=rs[0];
    int t = blockIdx.x*8 + warp;
    const float* xr = x + (long)t*1024;
    __half* xo = xh + (long)t*1024;
    float a[8]={0,0,0,0,0,0,0,0};
    #pragma unroll 4
    for(int j=0;j<32;j++){
      float xv = xr[lane+32*j];
      xo[lane+32*j] = __float2half(xv);
      const float* wt = &WgT[lane+32*j];
      #pragma unroll
      for(int e=0;e<8;e++) a[e] += xv*wt[e*1024];
    }
    #pragma unroll
    for(int off=16;off;off>>=1){
      #pragma unroll
      for(int e=0;e<8;e++) a[e]+=__shfl_down_sync(0xffffffffu,a[e],off);
    }
    if(lane==0){
      float s[8];
      #pragma unroll
      for(int e=0;e<8;e++) s[e]=sc/(1.f+expf(-a[e]));
      int i0=0;
      #pragma unroll
      for(int e=1;e<8;e++) if(s[e]>s[i0]) i0=e;
      int i1=-1;
      #pragma unroll
      for(int e=0;e<8;e++){ if(e==i0)continue; if(i1<0||s[e]>s[i1]) i1=e; }
      float sum=s[i0]+s[i1];
      tokE[2*t]=i0; tokE[2*t+1]=i1;
      tokW[2*t]=s[i0]/sum; tokW[2*t+1]=s[i1]/sum;
      int ee[2]={i0,i1};
      #pragma unroll
      for(int j=0;j<2;j++){
        int slot=atomicAdd(&cnt[ee[j]],1);
        if (slot<CAP){
          int p=16384+ee[j]*CAP+slot;
          rowTok[p]=t;
          tokPos[2*t+j]=p;
        }
      }
    }
    return;
  }
  if (z==3){
    const int n2=1024*192;
    for(int i=blockIdx.x*256+tid; i<n2; i+=2048*256){
      int r=i/192, c=(i%192)*2;
      float2 v;
      if (c<128) v=*(const float2*)&Wq[(long)r*128+c];
      else       v=*(const float2*)&Wkv[(long)r*256+c-128];
      *(__half2*)&Wqkvh[(long)r*384+c]=__floats2half2_rn(v.x,v.y);
    }
    return;
  }
  int b=blockIdx.x;
  if (b<128){
    int i=b*256+tid;
    int r=i/128, c=(i%128)*2;
    float2 v;
    if (c<128) v=*(const float2*)&Wku[(long)r*128+c];
    else       v=*(const float2*)&Wvu[(long)r*128+c-128];
    *(__half2*)&Wkuvh[(long)r*256+c]=__floats2half2_rn(v.x,v.y);
  } else if (b<256){
    int i=(b-128)*256+tid;
    float4 v=Wao[i];
    __half2 h0=__floats2half2_rn(v.x,v.y), h1=__floats2half2_rn(v.z,v.w);
    uint2 u; u.x=*(uint32_t*)&h0; u.y=*(uint32_t*)&h1;
    Waoh[i]=u;
  } else if (b<1280){
    int i=(b-256)*256+tid;
    float4 v=Wo[i];
    __half2 h0=__floats2half2_rn(v.x,v.y), h1=__floats2half2_rn(v.z,v.w);
    uint2 u; u.x=*(uint32_t*)&h0; u.y=*(uint32_t*)&h1;
    Woh[i]=u;
  }
}

// ---------------- remaining small kernels ----------------
// combine: one uint4 (8 halves) per thread; 128 threads cover a 1024-half row.
__global__ void combine_k(const __half* __restrict__ Z,
                          const int* __restrict__ tokPos, const float* __restrict__ tokW,
                          __half* __restrict__ yh){
  int t=blockIdx.x, i=threadIdx.x;
  int p0=tokPos[2*t], p1=tokPos[2*t+1];
  float w0=tokW[2*t], w1=tokW[2*t+1];
  uint4 us=((const uint4*)(Z+(long)t *1024))[i];
  uint4 u0=((const uint4*)(Z+(long)p0*1024))[i];
  uint4 u1=((const uint4*)(Z+(long)p1*1024))[i];
  uint4 o;
  #pragma unroll
  for(int q=0;q<4;q++){
    uint32_t su=((uint32_t*)&us)[q], a0=((uint32_t*)&u0)[q], a1=((uint32_t*)&u1)[q];
    float2 s=__half22float2(*(__half2*)&su);
    float2 a=__half22float2(*(__half2*)&a0);
    float2 b=__half22float2(*(__half2*)&a1);
    __half2 r=__floats2half2_rn(s.x + w0*a.x + w1*b.x, s.y + w0*a.y + w1*b.y);
    ((uint32_t*)&o)[q]=*(uint32_t*)&r;
  }
  ((uint4*)(yh+(long)t*1024))[i]=o;
}
// s=8 attention. freqs = pos*rope_freq is ELEMENTWISE (both len 8):
// angle[j] = j * 10000^(-j/8), identical for every position.
__global__ void attn_k(const float* __restrict__ qbuf,const float* __restrict__ kv,
                       __half* __restrict__ oh){
  int b=blockIdx.x, h=threadIdx.x>>5, lane=threadIdx.x&31;
  __shared__ float q[4][8][32],k[4][8][32],v[4][8][32],p[4][8][8],sc[4][8][8];
  #pragma unroll
  for(int s=0;s<8;s++){
    long t=(long)b*8+s;
    q[h][s][lane]=qbuf[t*128+h*32+lane];
    k[h][s][lane]=kv[t*256+h*32+lane];
    v[h][s][lane]=kv[t*256+128+h*32+lane];
  }
  __syncwarp();
  if(lane<8){
    float ang=(float)lane*powf(10000.f,-(float)lane/8.f);
    float c=cosf(ang), sn=sinf(ang);
    #pragma unroll
    for(int s=0;s<8;s++){
      float x1=q[h][s][lane], x2=q[h][s][lane+8];
      q[h][s][lane]=x1*c-x2*sn; q[h][s][lane+8]=x1*sn+x2*c;
    }
  }
  __syncwarp();
  #pragma unroll
  for(int e=0;e<2;e++){
    int id=lane+e*32, qi=id>>3, ki=id&7;
    float s0=0.f;
    #pragma unroll
    for(int d=0;d<32;d++) s0+=q[h][qi][d]*k[h][ki][d];
    sc[h][qi][ki]=s0*0.17677669529663687f;
  }
  __syncwarp();
  if(lane<8){
    float m=-1e30f;
    #pragma unroll
    for(int j=0;j<8;j++) m=fmaxf(m,sc[h][lane][j]);
    float ex[8], su=0.f;
    #pragma unroll
    for(int j=0;j<8;j++){ ex[j]=expf(sc[h][lane][j]-m); su+=ex[j]; }
    float inv=1.f/su;
    #pragma unroll
    for(int j=0;j<8;j++) p[h][lane][j]=ex[j]*inv;
  }
  __syncwarp();
  #pragma unroll
  for(int qi=0;qi<8;qi++){
    float o=0.f;
    #pragma unroll
    for(int j=0;j<8;j++) o+=p[h][qi][j]*v[h][j][lane];
    oh[((long)b*8+qi)*128+h*32+lane]=__float2half(o);
  }
}
// value: R11 version (known passing): half2 loop + smem tree.
__global__ void value_k(const __half* __restrict__ ch,const float* __restrict__ Wv,
                        const float* __restrict__ bv,float* __restrict__ o){
  int t=blockIdx.x, tid=threadIdx.x;
  const __half2* cp=(const __half2*)(ch+(long)t*1024);
  const float2* wp=(const float2*)Wv;
  float s=0.f;
  for(int i=tid;i<512;i+=128){
    float2 c=__half22float2(cp[i]); float2 w=wp[i];
    s += c.x*w.x + c.y*w.y;
  }
  __shared__ float sm[128];
  sm[tid]=s; __syncthreads();
  for(int off=64;off;off>>=1){ if(tid<off) sm[tid]+=sm[tid+off]; __syncthreads(); }
  if(tid==0) o[t]=sm[0]+bv[0];
}

// ---------------- host launcher ----------------
extern "C" void kernel_launch(void* const* d_in, const int* in_sizes, int n_in,
                              void* d_out, int out_size){
  const float *x=(const float*)d_in[0], *Wg=(const float*)d_in[1], *W1=(const float*)d_in[2],
    *b1=(const float*)d_in[3], *W2=(const float*)d_in[4], *b2=(const float*)d_in[5],
    *Ws1=(const float*)d_in[6], *bs1=(const float*)d_in[7], *Ws2=(const float*)d_in[8],
    *bs2=(const float*)d_in[9], *rs=(const float*)d_in[10], *Wq=(const float*)d_in[11],
    *Wkv=(const float*)d_in[12], *Wku=(const float*)d_in[13], *Wvu=(const float*)d_in[14],
    *Wao=(const float*)d_in[15], *Wo=(const float*)d_in[16], *bo=(const float*)d_in[17],
    *Wv=(const float*)d_in[18], *bv=(const float*)d_in[19];
  float* out=(float*)d_out;
  #define GS(T,p,s) T* p; cudaGetSymbolAddress((void**)&p,s)
  GS(__half,xh,g_xh); GS(__half,W1c,g_W1c); GS(__half,W2c,g_W2c);
  GS(__half,Wqkvh,g_Wqkvh); GS(__half,Wkuvh,g_Wkuvh); GS(__half,Waoh,g_Waoh); GS(__half,Woh,g_Woh);
  GS(__half,hb,g_hb); GS(__half,zb,g_z); GS(__half,yh,g_yh);
  GS(float,qbuf,g_qbuf); GS(__half,lath,g_lath); GS(float,kvb,g_kv);
  GS(__half,oh,g_oh); GS(__half,combh,g_combh);
  GS(int,tokE,g_tokE); GS(float,tokW,g_tokW);
  GS(int,rowTok,g_rowTok); GS(int,tokPos,g_tokPos); GS(int,cnt,g_cnt);
  #undef GS

  cudaFuncSetAttribute(hm_gemm<0,false,false>, cudaFuncAttributeMaxDynamicSharedMemorySize, HM_SMEM);
  cudaFuncSetAttribute(hm_gemm<1,true ,true >, cudaFuncAttributeMaxDynamicSharedMemorySize, HM_SMEM);
  cudaFuncSetAttribute(hm_gemm<4,false,true >, cudaFuncAttributeMaxDynamicSharedMemorySize, HM_SMEM);
  cudaFuncSetAttribute(hm_gemm<3,false,false>, cudaFuncAttributeMaxDynamicSharedMemorySize, HM_SMEM);
  cudaFuncSetAttribute(hm_gemm<5,false,false>, cudaFuncAttributeMaxDynamicSharedMemorySize, HM_SMEM);

  cudaMemsetAsync(cnt, 0, NE*sizeof(int));                                  // 0
  prep_all_k<<<dim3(2048,1,5),256>>>(                                       // 1
      (const float4*)Ws1,(const float4*)W1,(uint2*)W1c,
      (const float4*)Ws2,(const float4*)W2,(uint2*)W2c,
      x,Wg,rs,tokE,tokW,xh,cnt,rowTok,tokPos,
      Wq,Wkv,Wqkvh,Wku,Wvu,Wkuvh,
      (const float4*)Wao,(uint2*)Waoh,(const float4*)Wo,(uint2*)Woh);

  dim3 gFFN(8,PADROWS/128);
  hm_gemm<1,true ,true ><<<gFFN,256,HM_SMEM>>>(xh,W1c,0,1024,1024,bs1,b1,   // 2
      nullptr,hb,nullptr,rowTok,cnt);
  hm_gemm<4,false,true ><<<gFFN,256,HM_SMEM>>>(hb,W2c,0,1024,1024,bs2,b2,   // 3
      nullptr,zb,nullptr,nullptr,cnt);
  combine_k<<<NT,128>>>(zb,tokPos,tokW,yh);                                 // 4

  hm_gemm<5,false,false><<<dim3(3,128),256,HM_SMEM>>>(yh,Wqkvh,NT,384,1024, // 5
      nullptr,nullptr,qbuf,lath,nullptr,nullptr,nullptr);
  hm_gemm<0,false,false><<<dim3(2,128),256,HM_SMEM>>>(lath,Wkuvh,NT,256,256,// 6
      nullptr,nullptr,kvb,nullptr,nullptr,nullptr,nullptr);
  attn_k<<<2048,128>>>(qbuf,kvb,oh);                                        // 7
  hm_gemm<3,false,false><<<dim3(8,128),256,HM_SMEM>>>(oh,Waoh,NT,1024,128,  // 8
      nullptr,nullptr,nullptr,combh,yh,nullptr,nullptr);
  hm_gemm<0,false,false><<<dim3(8,128),256,HM_SMEM>>>(combh,Woh,NT,1024,1024,// 9
      bo,nullptr,out,nullptr,nullptr,nullptr,nullptr);
  value_k<<<NT,128>>>(combh,Wv,bv,out+(long)NT*1024);                       // 10
}